// round 1
// baseline (speedup 1.0000x reference)
#include <cuda_runtime.h>
#include <math.h>
#include <math_constants.h>

// ---------------- problem constants ----------------
#define H_     16
#define NOPE_  128
#define ROPE_  64
#define VD_    128
#define KVR_   512
#define QKD_   192        // NOPE+ROPE
#define B_     2
#define T_     2048
#define D_     2048
#define BT_    (B_*T_)    // 4096

// ---------------- scratch (device globals; no cudaMalloc allowed) ----------------
__device__ float g_q[(size_t)BT_ * H_ * QKD_];          // [B,T,H,192]
__device__ float g_kvc[(size_t)BT_ * (KVR_ + ROPE_)];   // [B,T,576]
__device__ float g_lat[(size_t)BT_ * KVR_];             // [B,T,512]
__device__ float g_kvfull[(size_t)BT_ * H_ * (NOPE_+VD_)]; // [B,T,H,256]
__device__ float g_krope[(size_t)BT_ * ROPE_];          // [B,T,64] (roped)
__device__ float g_y[(size_t)BT_ * H_ * VD_];           // [B,T,H,128]

// ---------------- generic fp32 GEMM: C[M,N] = A[M,K] @ B[K,N] ----------------
// M % 128 == 0, K % 16 == 0 guaranteed by call sites; N predicated (N % 4 == 0).
__global__ __launch_bounds__(256) void gemm_kernel(
    const float* __restrict__ A, const float* __restrict__ B,
    float* __restrict__ C, int M, int N, int K)
{
    __shared__ float As[16][132];
    __shared__ float Bs[16][132];

    const int tid = threadIdx.x;
    const int bn0 = blockIdx.x * 128;
    const int bm0 = blockIdx.y * 128;
    const int tx = tid & 15;        // 0..15 -> col group
    const int ty = tid >> 4;        // 0..15 -> row group

    float acc[8][8];
#pragma unroll
    for (int r = 0; r < 8; r++)
#pragma unroll
        for (int c = 0; c < 8; c++) acc[r][c] = 0.f;

    for (int k0 = 0; k0 < K; k0 += 16) {
        // load A tile 128x16 (512 float4, 2 per thread), store transposed
#pragma unroll
        for (int l = 0; l < 2; l++) {
            int idx = tid * 2 + l;          // 0..511
            int row = idx >> 2;             // 0..127
            int kq  = (idx & 3) * 4;        // 0,4,8,12
            const float4 a4 = *(const float4*)(A + (size_t)(bm0 + row) * K + k0 + kq);
            As[kq + 0][row] = a4.x;
            As[kq + 1][row] = a4.y;
            As[kq + 2][row] = a4.z;
            As[kq + 3][row] = a4.w;
        }
        // load B tile 16x128 (512 float4, 2 per thread), N-predicated
#pragma unroll
        for (int l = 0; l < 2; l++) {
            int idx = tid * 2 + l;          // 0..511
            int row = idx >> 5;             // 0..15
            int cq  = (idx & 31) * 4;       // 0..124
            int gcol = bn0 + cq;
            float4 b4 = make_float4(0.f, 0.f, 0.f, 0.f);
            if (gcol < N)
                b4 = *(const float4*)(B + (size_t)(k0 + row) * N + gcol);
            *(float4*)&Bs[row][cq] = b4;
        }
        __syncthreads();

#pragma unroll
        for (int kk = 0; kk < 16; kk++) {
            float a[8], b[8];
            float4 a0 = *(float4*)&As[kk][ty * 8];
            float4 a1 = *(float4*)&As[kk][ty * 8 + 4];
            float4 b0 = *(float4*)&Bs[kk][tx * 8];
            float4 b1 = *(float4*)&Bs[kk][tx * 8 + 4];
            a[0]=a0.x; a[1]=a0.y; a[2]=a0.z; a[3]=a0.w;
            a[4]=a1.x; a[5]=a1.y; a[6]=a1.z; a[7]=a1.w;
            b[0]=b0.x; b[1]=b0.y; b[2]=b0.z; b[3]=b0.w;
            b[4]=b1.x; b[5]=b1.y; b[6]=b1.z; b[7]=b1.w;
#pragma unroll
            for (int r = 0; r < 8; r++)
#pragma unroll
                for (int c = 0; c < 8; c++)
                    acc[r][c] = fmaf(a[r], b[c], acc[r][c]);
        }
        __syncthreads();
    }

    // store (N-predicated; M always in-range)
#pragma unroll
    for (int r = 0; r < 8; r++) {
        size_t gr = (size_t)(bm0 + ty * 8 + r) * N;
#pragma unroll
        for (int c = 0; c < 8; c++) {
            int gc = bn0 + tx * 8 + c;
            if (gc < N) C[gr + gc] = acc[r][c];
        }
    }
}

// ---------------- RMSNorm on kvc[:, :512] -> lat ----------------
__global__ __launch_bounds__(256) void rmsnorm_kernel(
    const float* __restrict__ kvc, const float* __restrict__ w,
    float* __restrict__ lat)
{
    const int row = blockIdx.x;   // 0..BT-1
    const float* x = kvc + (size_t)row * (KVR_ + ROPE_);
    const int tid = threadIdx.x;

    float v0 = x[tid];
    float v1 = x[tid + 256];
    float ss = v0 * v0 + v1 * v1;
#pragma unroll
    for (int off = 16; off; off >>= 1)
        ss += __shfl_xor_sync(0xffffffffu, ss, off);

    __shared__ float red[8];
    if ((tid & 31) == 0) red[tid >> 5] = ss;
    __syncthreads();
    float tot = 0.f;
#pragma unroll
    for (int i = 0; i < 8; i++) tot += red[i];

    float nrm = rsqrtf(tot * (1.f / 512.f) + 1e-6f);
    float* o = lat + (size_t)row * KVR_;
    o[tid]       = v0 * nrm * w[tid];
    o[tid + 256] = v1 * nrm * w[tid + 256];
}

// ---------------- RoPE on q[..., 128:192] in place ----------------
__global__ __launch_bounds__(256) void rope_q_kernel(float* __restrict__ q)
{
    int idx = blockIdx.x * 256 + threadIdx.x;   // over BT*H*32
    if (idx >= BT_ * H_ * 32) return;
    int i  = idx & 31;
    int h  = (idx >> 5) & (H_ - 1);
    int bt = idx >> 9;
    int t  = bt & (T_ - 1);

    float inv = powf(10000.f, -(float)(2 * i) / 64.f);
    float f = (float)t * inv;
    float c = cosf(f), s = sinf(f);

    float* p = q + ((size_t)bt * H_ + h) * QKD_ + NOPE_;
    float x1 = p[i], x2 = p[i + 32];
    p[i]      = x1 * c - x2 * s;
    p[i + 32] = x2 * c + x1 * s;
}

// ---------------- RoPE on kvc[..., 512:576] -> krope ----------------
__global__ __launch_bounds__(256) void rope_k_kernel(
    const float* __restrict__ kvc, float* __restrict__ krope)
{
    int idx = blockIdx.x * 256 + threadIdx.x;   // over BT*32
    if (idx >= BT_ * 32) return;
    int i  = idx & 31;
    int bt = idx >> 5;
    int t  = bt & (T_ - 1);

    float inv = powf(10000.f, -(float)(2 * i) / 64.f);
    float f = (float)t * inv;
    float c = cosf(f), s = sinf(f);

    const float* p = kvc + (size_t)bt * (KVR_ + ROPE_) + KVR_;
    float x1 = p[i], x2 = p[i + 32];
    float* o = krope + (size_t)bt * ROPE_;
    o[i]      = x1 * c - x2 * s;
    o[i + 32] = x2 * c + x1 * s;
}

// ---------------- causal flash attention (fp32) ----------------
// grid: (T/64, H, B); block: 256 threads (tx=tid%16 col-group, ty=tid/16 row-group)
// smem: Qs[64][193] + Ks[64][33] + Ps[64][65] + Vs[64][132] = 27072 floats
#define QS_LD 193
#define KS_LD 33
#define PS_LD 65
#define VS_LD 132
#define ATTN_SMEM_FLOATS (64*QS_LD + 64*KS_LD + 64*PS_LD + 64*VS_LD)

__device__ __forceinline__ float redmax16(float v) {
#pragma unroll
    for (int off = 8; off; off >>= 1)
        v = fmaxf(v, __shfl_xor_sync(0xffffffffu, v, off));
    return v;
}
__device__ __forceinline__ float redsum16(float v) {
#pragma unroll
    for (int off = 8; off; off >>= 1)
        v += __shfl_xor_sync(0xffffffffu, v, off);
    return v;
}

__global__ __launch_bounds__(256) void attn_kernel(
    const float* __restrict__ q, const float* __restrict__ kvfull,
    const float* __restrict__ krope, float* __restrict__ y)
{
    extern __shared__ float sm[];
    float* Qs = sm;
    float* Ks = Qs + 64 * QS_LD;
    float* Ps = Ks + 64 * KS_LD;
    float* Vs = Ps + 64 * PS_LD;

    const int b  = blockIdx.z;
    const int h  = blockIdx.y;
    const int qt = blockIdx.x;
    const int q0 = qt * 64;
    const int tid = threadIdx.x;
    const int tx = tid & 15;
    const int ty = tid >> 4;
    const float scale = 0.07216878364870322f;   // 192^-0.5

    // load Q tile [64][192]
    for (int idx = tid; idx < 64 * 192; idx += 256) {
        int row = idx / 192, col = idx - row * 192;
        Qs[row * QS_LD + col] =
            q[(((size_t)(b * T_ + q0 + row)) * H_ + h) * QKD_ + col];
    }

    float m_i[4], l_i[4], o[4][8];
#pragma unroll
    for (int r = 0; r < 4; r++) {
        m_i[r] = -CUDART_INF_F;
        l_i[r] = 0.f;
#pragma unroll
        for (int c = 0; c < 8; c++) o[r][c] = 0.f;
    }
    __syncthreads();

    const int nkt = qt + 1;
    for (int kt = 0; kt < nkt; kt++) {
        const int k0 = kt * 64;
        float s[4][4];
#pragma unroll
        for (int r = 0; r < 4; r++)
#pragma unroll
            for (int c = 0; c < 4; c++) s[r][c] = 0.f;

        // S = Q @ K^T, streaming K in 32-wide d chunks
        for (int d0 = 0; d0 < QKD_; d0 += 32) {
            for (int idx = tid; idx < 64 * 32; idx += 256) {
                int row = idx >> 5, col = idx & 31;
                int d = d0 + col;
                size_t tkey = (size_t)(b * T_ + k0 + row);
                float v;
                if (d < NOPE_) v = kvfull[(tkey * H_ + h) * (NOPE_+VD_) + d];
                else           v = krope[tkey * ROPE_ + (d - NOPE_)];
                Ks[row * KS_LD + col] = v;
            }
            __syncthreads();
#pragma unroll
            for (int kk = 0; kk < 32; kk++) {
                float qv[4], kv[4];
#pragma unroll
                for (int r = 0; r < 4; r++)
                    qv[r] = Qs[(ty * 4 + r) * QS_LD + d0 + kk];
#pragma unroll
                for (int c = 0; c < 4; c++)
                    kv[c] = Ks[(tx * 4 + c) * KS_LD + kk];
#pragma unroll
                for (int r = 0; r < 4; r++)
#pragma unroll
                    for (int c = 0; c < 4; c++)
                        s[r][c] = fmaf(qv[r], kv[c], s[r][c]);
            }
            __syncthreads();
        }

        // scale + causal mask
#pragma unroll
        for (int r = 0; r < 4; r++) {
            int qg = q0 + ty * 4 + r;
#pragma unroll
            for (int c = 0; c < 4; c++) {
                int kg = k0 + tx * 4 + c;
                s[r][c] = (kg > qg) ? -CUDART_INF_F : s[r][c] * scale;
            }
        }

        // online softmax update
        float corr[4], m_new[4];
#pragma unroll
        for (int r = 0; r < 4; r++) {
            float tm = fmaxf(fmaxf(s[r][0], s[r][1]), fmaxf(s[r][2], s[r][3]));
            tm = redmax16(tm);
            m_new[r] = fmaxf(m_i[r], tm);
            corr[r]  = __expf(m_i[r] - m_new[r]);
            float p0 = __expf(s[r][0] - m_new[r]);
            float p1 = __expf(s[r][1] - m_new[r]);
            float p2 = __expf(s[r][2] - m_new[r]);
            float p3 = __expf(s[r][3] - m_new[r]);
            s[r][0] = p0; s[r][1] = p1; s[r][2] = p2; s[r][3] = p3;
            float rs = redsum16(p0 + p1 + p2 + p3);
            l_i[r] = l_i[r] * corr[r] + rs;
            m_i[r] = m_new[r];
#pragma unroll
            for (int c = 0; c < 8; c++) o[r][c] *= corr[r];
        }

        // write P, load V
#pragma unroll
        for (int r = 0; r < 4; r++)
#pragma unroll
            for (int c = 0; c < 4; c++)
                Ps[(ty * 4 + r) * PS_LD + tx * 4 + c] = s[r][c];

        for (int vi = tid; vi < 64 * 32; vi += 256) {   // 2048 float4
            int row = vi >> 5;
            int col = (vi & 31) * 4;
            float4 v4 = *(const float4*)&kvfull[
                ((size_t)(b * T_ + k0 + row) * H_ + h) * (NOPE_+VD_) + NOPE_ + col];
            *(float4*)&Vs[row * VS_LD + col] = v4;
        }
        __syncthreads();

        // O += P @ V
#pragma unroll 4
        for (int kk = 0; kk < 64; kk++) {
            float4 v0 = *(float4*)&Vs[kk * VS_LD + tx * 8];
            float4 v1 = *(float4*)&Vs[kk * VS_LD + tx * 8 + 4];
#pragma unroll
            for (int r = 0; r < 4; r++) {
                float p = Ps[(ty * 4 + r) * PS_LD + kk];
                o[r][0] = fmaf(p, v0.x, o[r][0]);
                o[r][1] = fmaf(p, v0.y, o[r][1]);
                o[r][2] = fmaf(p, v0.z, o[r][2]);
                o[r][3] = fmaf(p, v0.w, o[r][3]);
                o[r][4] = fmaf(p, v1.x, o[r][4]);
                o[r][5] = fmaf(p, v1.y, o[r][5]);
                o[r][6] = fmaf(p, v1.z, o[r][6]);
                o[r][7] = fmaf(p, v1.w, o[r][7]);
            }
        }
        __syncthreads();
    }

    // epilogue: normalize and write y[b][t][h][:]
#pragma unroll
    for (int r = 0; r < 4; r++) {
        float inv_l = 1.f / l_i[r];
        size_t base = ((size_t)(b * T_ + q0 + ty * 4 + r) * H_ + h) * VD_ + tx * 8;
#pragma unroll
        for (int c = 0; c < 8; c++) y[base + c] = o[r][c] * inv_l;
    }
}

// ---------------- launch ----------------
extern "C" void kernel_launch(void* const* d_in, const int* in_sizes, int n_in,
                              void* d_out, int out_size)
{
    const float* x      = (const float*)d_in[0];
    const float* wq     = (const float*)d_in[1];
    const float* wkv_a  = (const float*)d_in[2];
    const float* wkv_b  = (const float*)d_in[3];
    const float* wo     = (const float*)d_in[4];
    const float* kvw    = (const float*)d_in[5];
    float* out = (float*)d_out;

    float *qp, *kvcp, *latp, *kvfp, *krp, *yp;
    cudaGetSymbolAddress((void**)&qp,   g_q);
    cudaGetSymbolAddress((void**)&kvcp, g_kvc);
    cudaGetSymbolAddress((void**)&latp, g_lat);
    cudaGetSymbolAddress((void**)&kvfp, g_kvfull);
    cudaGetSymbolAddress((void**)&krp,  g_krope);
    cudaGetSymbolAddress((void**)&yp,   g_y);

    // q = x @ wq : [4096,2048] @ [2048,3072]
    gemm_kernel<<<dim3(3072 / 128, BT_ / 128), 256>>>(x, wq, qp, BT_, H_ * QKD_, D_);
    // kvc = x @ wkv_a : [4096,2048] @ [2048,576]
    gemm_kernel<<<dim3((KVR_ + ROPE_ + 127) / 128, BT_ / 128), 256>>>(
        x, wkv_a, kvcp, BT_, KVR_ + ROPE_, D_);
    // rmsnorm
    rmsnorm_kernel<<<BT_, 256>>>(kvcp, kvw, latp);
    // rope
    rope_q_kernel<<<(BT_ * H_ * 32) / 256, 256>>>(qp);
    rope_k_kernel<<<(BT_ * 32) / 256, 256>>>(kvcp, krp);
    // kv_full = lat @ wkv_b : [4096,512] @ [512,4096]
    gemm_kernel<<<dim3(4096 / 128, BT_ / 128), 256>>>(
        latp, wkv_b, kvfp, BT_, H_ * (NOPE_ + VD_), KVR_);
    // attention
    static const int attn_smem = ATTN_SMEM_FLOATS * 4;
    cudaFuncSetAttribute(attn_kernel, cudaFuncAttributeMaxDynamicSharedMemorySize, attn_smem);
    attn_kernel<<<dim3(T_ / 64, H_, B_), 256, attn_smem>>>(qp, kvfp, krp, yp);
    // out = y @ wo : [4096,2048] @ [2048,2048]
    gemm_kernel<<<dim3(D_ / 128, BT_ / 128), 256>>>(yp, wo, out, BT_, D_, H_ * VD_);
}

// round 5
// speedup vs baseline: 1.6099x; 1.6099x over previous
#include <cuda_runtime.h>
#include <cuda_bf16.h>
#include <math.h>
#include <math_constants.h>
#include <cstdint>

// ---------------- problem constants ----------------
#define H_     16
#define NOPE_  128
#define ROPE_  64
#define VD_    128
#define KVR_   512
#define QKD_   192        // NOPE+ROPE
#define B_     2
#define T_     2048
#define D_     2048
#define BT_    (B_*T_)    // 4096

// ---------------- scratch (device globals; no cudaMalloc allowed) ----------------
__device__ float g_q[(size_t)BT_ * H_ * QKD_];             // [B,T,H,192]
__device__ float g_kvc[(size_t)BT_ * (KVR_ + ROPE_)];      // [B,T,576]
__device__ float g_lat[(size_t)BT_ * KVR_];                // [B,T,512]
__device__ float g_kvfull[(size_t)BT_ * H_ * (NOPE_+VD_)]; // [B,T,H,256]
__device__ float g_krope[(size_t)BT_ * ROPE_];             // [B,T,64]
__device__ float g_y[(size_t)BT_ * H_ * VD_];              // [B,T,H,128]

// bf16 split operands (hi/lo)
__device__ __nv_bfloat16 g_xh[(size_t)BT_ * D_];
__device__ __nv_bfloat16 g_xl[(size_t)BT_ * D_];
__device__ __nv_bfloat16 g_lath[(size_t)BT_ * KVR_];
__device__ __nv_bfloat16 g_latl[(size_t)BT_ * KVR_];
__device__ __nv_bfloat16 g_yh[(size_t)BT_ * H_ * VD_];
__device__ __nv_bfloat16 g_yl[(size_t)BT_ * H_ * VD_];
// transposed weights [N,K] bf16 hi/lo
__device__ __nv_bfloat16 g_wqt_h[(size_t)(H_*QKD_) * D_];
__device__ __nv_bfloat16 g_wqt_l[(size_t)(H_*QKD_) * D_];
__device__ __nv_bfloat16 g_wat_h[(size_t)(KVR_+ROPE_) * D_];
__device__ __nv_bfloat16 g_wat_l[(size_t)(KVR_+ROPE_) * D_];
__device__ __nv_bfloat16 g_wbt_h[(size_t)(H_*(NOPE_+VD_)) * KVR_];
__device__ __nv_bfloat16 g_wbt_l[(size_t)(H_*(NOPE_+VD_)) * KVR_];
__device__ __nv_bfloat16 g_wot_h[(size_t)D_ * (H_*VD_)];
__device__ __nv_bfloat16 g_wot_l[(size_t)D_ * (H_*VD_)];

// ---------------- helpers ----------------
__device__ __forceinline__ uint32_t smem_u32(const void* p) {
    uint32_t a;
    asm("{ .reg .u64 t; cvta.to.shared.u64 t, %1; cvt.u32.u64 %0, t; }" : "=r"(a) : "l"(p));
    return a;
}

__device__ __forceinline__ void ldsm_x4(uint32_t* r, uint32_t addr) {
    asm volatile("ldmatrix.sync.aligned.m8n8.x4.shared.b16 {%0,%1,%2,%3}, [%4];"
                 : "=r"(r[0]), "=r"(r[1]), "=r"(r[2]), "=r"(r[3]) : "r"(addr));
}

__device__ __forceinline__ void mma16816(float* c, const uint32_t* a, const uint32_t* b) {
    asm volatile(
        "mma.sync.aligned.m16n8k16.row.col.f32.bf16.bf16.f32 "
        "{%0,%1,%2,%3}, {%4,%5,%6,%7}, {%8,%9}, {%0,%1,%2,%3};"
        : "+f"(c[0]), "+f"(c[1]), "+f"(c[2]), "+f"(c[3])
        : "r"(a[0]), "r"(a[1]), "r"(a[2]), "r"(a[3]), "r"(b[0]), "r"(b[1]));
}

// ---------------- HMMA GEMM: C[M,Nn] = (Ah+Al)[M,K] @ (Bh+Bl)[Nn,K]^T ----------------
// smem per buffer: 4 tiles (Ah,Al,Bh,Bl) of 128 rows x 32 bf16, pitch 40 bf16 (80B).
// tile bytes = 128*80 = 10240; buffer = 40960; double-buffered = 81920.
#define GT_PITCHB 80
#define GT_TILE   10240
#define GT_BUF    40960
#define GM_SMEM   (2 * GT_BUF)

__device__ __forceinline__ void gemm_load_regs(
    uint4* pf, const __nv_bfloat16* Ah, const __nv_bfloat16* Al,
    const __nv_bfloat16* Bh, const __nv_bfloat16* Bl,
    int bm0, int bn0, int K, int Nn, int k0, int tid)
{
#pragma unroll
    for (int l = 0; l < 8; l++) {
        const int u = l * 256 + tid;      // 0..2047
        const int tile = u >> 9;          // 0..3
        const int r = (u >> 2) & 127;
        const int c4 = u & 3;
        const __nv_bfloat16* src;
        int row;
        bool ok = true;
        if (tile == 0)      { src = Ah; row = bm0 + r; }
        else if (tile == 1) { src = Al; row = bm0 + r; }
        else {
            src = (tile == 2) ? Bh : Bl;
            row = bn0 + r;
            ok = (row < Nn);
        }
        pf[l] = ok ? *(const uint4*)(src + (size_t)row * K + k0 + c4 * 8)
                   : make_uint4(0u, 0u, 0u, 0u);
    }
}

__device__ __forceinline__ void gemm_store_smem(const uint4* pf, uint32_t sbase, int tid)
{
#pragma unroll
    for (int l = 0; l < 8; l++) {
        const int u = l * 256 + tid;
        const int tile = u >> 9;
        const int r = (u >> 2) & 127;
        const int c4 = u & 3;
        const uint32_t addr = sbase + tile * GT_TILE + r * GT_PITCHB + c4 * 16;
        asm volatile("st.shared.v4.b32 [%0], {%1,%2,%3,%4};"
                     :: "r"(addr), "r"(pf[l].x), "r"(pf[l].y), "r"(pf[l].z), "r"(pf[l].w)
                     : "memory");
    }
}

__device__ __forceinline__ void gemm_compute(
    uint32_t sbase, int wm, int wn, int lane, float c[4][4][4])
{
#pragma unroll
    for (int ks = 0; ks < 32; ks += 16) {
        uint32_t Ahf[4][4], Alf[4][4], Bhf[4][2], Blf[4][2];
        // A frags: rows wm*64 + mi*16, non-trans ldmatrix.x4 from [m][k]
#pragma unroll
        for (int mi = 0; mi < 4; mi++) {
            const int row = wm * 64 + mi * 16 + (lane & 15);
            const uint32_t a = sbase + row * GT_PITCHB + (ks + (lane >> 4) * 8) * 2;
            ldsm_x4(Ahf[mi], a);
            ldsm_x4(Alf[mi], a + GT_TILE);
        }
        // B frags: [n][k] K-major -> non-trans ldmatrix; one x4 covers 2 n-blocks
#pragma unroll
        for (int nj = 0; nj < 2; nj++) {
            const int nrow = wn * 32 + nj * 16 + ((lane >> 4) & 1) * 8 + (lane & 7);
            const uint32_t b = sbase + 2 * GT_TILE + nrow * GT_PITCHB
                             + (ks + ((lane >> 3) & 1) * 8) * 2;
            ldsm_x4(&Bhf[nj * 2][0], b);
            ldsm_x4(&Blf[nj * 2][0], b + GT_TILE);
        }
#pragma unroll
        for (int mi = 0; mi < 4; mi++)
#pragma unroll
            for (int ni = 0; ni < 4; ni++) {
                mma16816(c[mi][ni], Ahf[mi], Bhf[ni]);
                mma16816(c[mi][ni], Alf[mi], Bhf[ni]);
                mma16816(c[mi][ni], Ahf[mi], Blf[ni]);
            }
    }
}

__global__ __launch_bounds__(256) void gemm_mma(
    const __nv_bfloat16* __restrict__ Ah, const __nv_bfloat16* __restrict__ Al,
    const __nv_bfloat16* __restrict__ Bh, const __nv_bfloat16* __restrict__ Bl,
    float* __restrict__ C, int M, int Nn, int K)
{
    extern __shared__ char smem[];
    const uint32_t sb = smem_u32(smem);
    const int tid = threadIdx.x;
    const int lane = tid & 31;
    const int wid = tid >> 5;
    const int wm = wid & 1;          // 2 warps along M
    const int wn = wid >> 1;         // 4 warps along N
    const int bm0 = blockIdx.y * 128;
    const int bn0 = blockIdx.x * 128;

    float c[4][4][4];
#pragma unroll
    for (int mi = 0; mi < 4; mi++)
#pragma unroll
        for (int ni = 0; ni < 4; ni++)
#pragma unroll
            for (int k = 0; k < 4; k++) c[mi][ni][k] = 0.f;

    uint4 pf[8];
    gemm_load_regs(pf, Ah, Al, Bh, Bl, bm0, bn0, K, Nn, 0, tid);
    gemm_store_smem(pf, sb, tid);
    __syncthreads();

    const int nc = K >> 5;
    for (int i = 0; i < nc; i++) {
        if (i + 1 < nc)
            gemm_load_regs(pf, Ah, Al, Bh, Bl, bm0, bn0, K, Nn, (i + 1) * 32, tid);
        gemm_compute(sb + (i & 1) * GT_BUF, wm, wn, lane, c);
        if (i + 1 < nc)
            gemm_store_smem(pf, sb + ((i + 1) & 1) * GT_BUF, tid);
        __syncthreads();
    }

    // epilogue: c0,c1 -> (row g, cols 2t,2t+1); c2,c3 -> row g+8
    const int g = lane >> 2;
    const int t = lane & 3;
#pragma unroll
    for (int mi = 0; mi < 4; mi++) {
        const int row = bm0 + wm * 64 + mi * 16 + g;
#pragma unroll
        for (int ni = 0; ni < 4; ni++) {
            const int col = bn0 + wn * 32 + ni * 8 + 2 * t;
            if (col < Nn) {
                float2 v0 = make_float2(c[mi][ni][0], c[mi][ni][1]);
                float2 v1 = make_float2(c[mi][ni][2], c[mi][ni][3]);
                *(float2*)&C[(size_t)row * Nn + col] = v0;
                *(float2*)&C[(size_t)(row + 8) * Nn + col] = v1;
            }
        }
    }
}

// ---------------- bf16 hi/lo split (element-wise, float4) ----------------
__global__ __launch_bounds__(256) void split_kernel(
    const float* __restrict__ x, __nv_bfloat16* __restrict__ h,
    __nv_bfloat16* __restrict__ l, int n4)
{
    int i = blockIdx.x * 256 + threadIdx.x;
    if (i >= n4) return;
    float4 v = ((const float4*)x)[i];
    __nv_bfloat16 h0 = __float2bfloat16(v.x), h1 = __float2bfloat16(v.y);
    __nv_bfloat16 h2 = __float2bfloat16(v.z), h3 = __float2bfloat16(v.w);
    __nv_bfloat16 l0 = __float2bfloat16(v.x - __bfloat162float(h0));
    __nv_bfloat16 l1 = __float2bfloat16(v.y - __bfloat162float(h1));
    __nv_bfloat16 l2 = __float2bfloat16(v.z - __bfloat162float(h2));
    __nv_bfloat16 l3 = __float2bfloat16(v.w - __bfloat162float(h3));
    ((__nv_bfloat162*)h)[i*2]   = __nv_bfloat162(h0, h1);
    ((__nv_bfloat162*)h)[i*2+1] = __nv_bfloat162(h2, h3);
    ((__nv_bfloat162*)l)[i*2]   = __nv_bfloat162(l0, l1);
    ((__nv_bfloat162*)l)[i*2+1] = __nv_bfloat162(l2, l3);
}

// ---------------- transpose + split: W[K,N] fp32 -> Wt hi/lo [N,K] bf16 ----------------
__global__ __launch_bounds__(256) void transpose_split_kernel(
    const float* __restrict__ W, __nv_bfloat16* __restrict__ th,
    __nv_bfloat16* __restrict__ tl, int K, int N)
{
    __shared__ float tile[32][33];
    const int bx = blockIdx.x * 32;   // N
    const int by = blockIdx.y * 32;   // K
    const int txi = threadIdx.x & 31;
    const int tyi = threadIdx.x >> 5; // 0..7
#pragma unroll
    for (int j = 0; j < 32; j += 8) {
        int kk = by + tyi + j, nn = bx + txi;
        if (kk < K && nn < N) tile[tyi + j][txi] = W[(size_t)kk * N + nn];
    }
    __syncthreads();
#pragma unroll
    for (int j = 0; j < 32; j += 8) {
        int nn = bx + tyi + j, kk = by + txi;
        if (nn < N && kk < K) {
            float v = tile[txi][tyi + j];
            __nv_bfloat16 hi = __float2bfloat16(v);
            __nv_bfloat16 lo = __float2bfloat16(v - __bfloat162float(hi));
            th[(size_t)nn * K + kk] = hi;
            tl[(size_t)nn * K + kk] = lo;
        }
    }
}

// ---------------- RMSNorm on kvc[:, :512] -> lat ----------------
__global__ __launch_bounds__(256) void rmsnorm_kernel(
    const float* __restrict__ kvc, const float* __restrict__ w,
    float* __restrict__ lat)
{
    const int row = blockIdx.x;
    const float* x = kvc + (size_t)row * (KVR_ + ROPE_);
    const int tid = threadIdx.x;

    float v0 = x[tid];
    float v1 = x[tid + 256];
    float ss = v0 * v0 + v1 * v1;
#pragma unroll
    for (int off = 16; off; off >>= 1)
        ss += __shfl_xor_sync(0xffffffffu, ss, off);

    __shared__ float red[8];
    if ((tid & 31) == 0) red[tid >> 5] = ss;
    __syncthreads();
    float tot = 0.f;
#pragma unroll
    for (int i = 0; i < 8; i++) tot += red[i];

    float nrm = rsqrtf(tot * (1.f / 512.f) + 1e-6f);
    float* o = lat + (size_t)row * KVR_;
    o[tid]       = v0 * nrm * w[tid];
    o[tid + 256] = v1 * nrm * w[tid + 256];
}

// ---------------- RoPE ----------------
__global__ __launch_bounds__(256) void rope_q_kernel(float* __restrict__ q)
{
    int idx = blockIdx.x * 256 + threadIdx.x;
    if (idx >= BT_ * H_ * 32) return;
    int i  = idx & 31;
    int h  = (idx >> 5) & (H_ - 1);
    int bt = idx >> 9;
    int t  = bt & (T_ - 1);

    float inv = powf(10000.f, -(float)(2 * i) / 64.f);
    float f = (float)t * inv;
    float c = cosf(f), s = sinf(f);

    float* p = q + ((size_t)bt * H_ + h) * QKD_ + NOPE_;
    float x1 = p[i], x2 = p[i + 32];
    p[i]      = x1 * c - x2 * s;
    p[i + 32] = x2 * c + x1 * s;
}

__global__ __launch_bounds__(256) void rope_k_kernel(
    const float* __restrict__ kvc, float* __restrict__ krope)
{
    int idx = blockIdx.x * 256 + threadIdx.x;
    if (idx >= BT_ * 32) return;
    int i  = idx & 31;
    int bt = idx >> 5;
    int t  = bt & (T_ - 1);

    float inv = powf(10000.f, -(float)(2 * i) / 64.f);
    float f = (float)t * inv;
    float c = cosf(f), s = sinf(f);

    const float* p = kvc + (size_t)bt * (KVR_ + ROPE_) + KVR_;
    float x1 = p[i], x2 = p[i + 32];
    float* o = krope + (size_t)bt * ROPE_;
    o[i]      = x1 * c - x2 * s;
    o[i + 32] = x2 * c + x1 * s;
}

// ---------------- causal flash attention (fp32) ----------------
#define QS_LD 193
#define KS_LD 33
#define PS_LD 65
#define VS_LD 132
#define ATTN_SMEM_FLOATS (64*QS_LD + 64*KS_LD + 64*PS_LD + 64*VS_LD)

__device__ __forceinline__ float redmax16(float v) {
#pragma unroll
    for (int off = 8; off; off >>= 1)
        v = fmaxf(v, __shfl_xor_sync(0xffffffffu, v, off));
    return v;
}
__device__ __forceinline__ float redsum16(float v) {
#pragma unroll
    for (int off = 8; off; off >>= 1)
        v += __shfl_xor_sync(0xffffffffu, v, off);
    return v;
}

__global__ __launch_bounds__(256) void attn_kernel(
    const float* __restrict__ q, const float* __restrict__ kvfull,
    const float* __restrict__ krope, float* __restrict__ y)
{
    extern __shared__ float sm[];
    float* Qs = sm;
    float* Ks = Qs + 64 * QS_LD;
    float* Ps = Ks + 64 * KS_LD;
    float* Vs = Ps + 64 * PS_LD;

    const int b  = blockIdx.z;
    const int h  = blockIdx.y;
    const int qt = blockIdx.x;
    const int q0 = qt * 64;
    const int tid = threadIdx.x;
    const int tx = tid & 15;
    const int ty = tid >> 4;
    const float scale = 0.07216878364870322f;   // 192^-0.5

    for (int idx = tid; idx < 64 * 192; idx += 256) {
        int row = idx / 192, col = idx - row * 192;
        Qs[row * QS_LD + col] =
            q[(((size_t)(b * T_ + q0 + row)) * H_ + h) * QKD_ + col];
    }

    float m_i[4], l_i[4], o[4][8];
#pragma unroll
    for (int r = 0; r < 4; r++) {
        m_i[r] = -CUDART_INF_F;
        l_i[r] = 0.f;
#pragma unroll
        for (int c = 0; c < 8; c++) o[r][c] = 0.f;
    }
    __syncthreads();

    const int nkt = qt + 1;
    for (int kt = 0; kt < nkt; kt++) {
        const int k0 = kt * 64;
        float s[4][4];
#pragma unroll
        for (int r = 0; r < 4; r++)
#pragma unroll
            for (int c = 0; c < 4; c++) s[r][c] = 0.f;

        for (int d0 = 0; d0 < QKD_; d0 += 32) {
            for (int idx = tid; idx < 64 * 32; idx += 256) {
                int row = idx >> 5, col = idx & 31;
                int d = d0 + col;
                size_t tkey = (size_t)(b * T_ + k0 + row);
                float v;
                if (d < NOPE_) v = kvfull[(tkey * H_ + h) * (NOPE_+VD_) + d];
                else           v = krope[tkey * ROPE_ + (d - NOPE_)];
                Ks[row * KS_LD + col] = v;
            }
            __syncthreads();
#pragma unroll
            for (int kk = 0; kk < 32; kk++) {
                float qv[4], kv[4];
#pragma unroll
                for (int r = 0; r < 4; r++)
                    qv[r] = Qs[(ty * 4 + r) * QS_LD + d0 + kk];
#pragma unroll
                for (int c = 0; c < 4; c++)
                    kv[c] = Ks[(tx * 4 + c) * KS_LD + kk];
#pragma unroll
                for (int r = 0; r < 4; r++)
#pragma unroll
                    for (int c = 0; c < 4; c++)
                        s[r][c] = fmaf(qv[r], kv[c], s[r][c]);
            }
            __syncthreads();
        }

#pragma unroll
        for (int r = 0; r < 4; r++) {
            int qg = q0 + ty * 4 + r;
#pragma unroll
            for (int c = 0; c < 4; c++) {
                int kg = k0 + tx * 4 + c;
                s[r][c] = (kg > qg) ? -CUDART_INF_F : s[r][c] * scale;
            }
        }

        float corr[4], m_new[4];
#pragma unroll
        for (int r = 0; r < 4; r++) {
            float tm = fmaxf(fmaxf(s[r][0], s[r][1]), fmaxf(s[r][2], s[r][3]));
            tm = redmax16(tm);
            m_new[r] = fmaxf(m_i[r], tm);
            corr[r]  = __expf(m_i[r] - m_new[r]);
            float p0 = __expf(s[r][0] - m_new[r]);
            float p1 = __expf(s[r][1] - m_new[r]);
            float p2 = __expf(s[r][2] - m_new[r]);
            float p3 = __expf(s[r][3] - m_new[r]);
            s[r][0] = p0; s[r][1] = p1; s[r][2] = p2; s[r][3] = p3;
            float rs = redsum16(p0 + p1 + p2 + p3);
            l_i[r] = l_i[r] * corr[r] + rs;
            m_i[r] = m_new[r];
#pragma unroll
            for (int c = 0; c < 8; c++) o[r][c] *= corr[r];
        }

#pragma unroll
        for (int r = 0; r < 4; r++)
#pragma unroll
            for (int c = 0; c < 4; c++)
                Ps[(ty * 4 + r) * PS_LD + tx * 4 + c] = s[r][c];

        for (int vi = tid; vi < 64 * 32; vi += 256) {
            int row = vi >> 5;
            int col = (vi & 31) * 4;
            float4 v4 = *(const float4*)&kvfull[
                ((size_t)(b * T_ + k0 + row) * H_ + h) * (NOPE_+VD_) + NOPE_ + col];
            *(float4*)&Vs[row * VS_LD + col] = v4;
        }
        __syncthreads();

#pragma unroll 4
        for (int kk = 0; kk < 64; kk++) {
            float4 v0 = *(float4*)&Vs[kk * VS_LD + tx * 8];
            float4 v1 = *(float4*)&Vs[kk * VS_LD + tx * 8 + 4];
#pragma unroll
            for (int r = 0; r < 4; r++) {
                float p = Ps[(ty * 4 + r) * PS_LD + kk];
                o[r][0] = fmaf(p, v0.x, o[r][0]);
                o[r][1] = fmaf(p, v0.y, o[r][1]);
                o[r][2] = fmaf(p, v0.z, o[r][2]);
                o[r][3] = fmaf(p, v0.w, o[r][3]);
                o[r][4] = fmaf(p, v1.x, o[r][4]);
                o[r][5] = fmaf(p, v1.y, o[r][5]);
                o[r][6] = fmaf(p, v1.z, o[r][6]);
                o[r][7] = fmaf(p, v1.w, o[r][7]);
            }
        }
        __syncthreads();
    }

#pragma unroll
    for (int r = 0; r < 4; r++) {
        float inv_l = 1.f / l_i[r];
        size_t base = ((size_t)(b * T_ + q0 + ty * 4 + r) * H_ + h) * VD_ + tx * 8;
#pragma unroll
        for (int c = 0; c < 8; c++) y[base + c] = o[r][c] * inv_l;
    }
}

// ---------------- launch ----------------
extern "C" void kernel_launch(void* const* d_in, const int* in_sizes, int n_in,
                              void* d_out, int out_size)
{
    const float* x      = (const float*)d_in[0];
    const float* wq     = (const float*)d_in[1];
    const float* wkv_a  = (const float*)d_in[2];
    const float* wkv_b  = (const float*)d_in[3];
    const float* wo     = (const float*)d_in[4];
    const float* kvw    = (const float*)d_in[5];
    float* out = (float*)d_out;

    float *qp, *kvcp, *latp, *kvfp, *krp, *yp;
    cudaGetSymbolAddress((void**)&qp,   g_q);
    cudaGetSymbolAddress((void**)&kvcp, g_kvc);
    cudaGetSymbolAddress((void**)&latp, g_lat);
    cudaGetSymbolAddress((void**)&kvfp, g_kvfull);
    cudaGetSymbolAddress((void**)&krp,  g_krope);
    cudaGetSymbolAddress((void**)&yp,   g_y);

    __nv_bfloat16 *xh, *xl, *lath, *latl, *yh, *yl;
    __nv_bfloat16 *wqth, *wqtl, *wath, *watl, *wbth, *wbtl, *woth, *wotl;
    cudaGetSymbolAddress((void**)&xh,   g_xh);
    cudaGetSymbolAddress((void**)&xl,   g_xl);
    cudaGetSymbolAddress((void**)&lath, g_lath);
    cudaGetSymbolAddress((void**)&latl, g_latl);
    cudaGetSymbolAddress((void**)&yh,   g_yh);
    cudaGetSymbolAddress((void**)&yl,   g_yl);
    cudaGetSymbolAddress((void**)&wqth, g_wqt_h);
    cudaGetSymbolAddress((void**)&wqtl, g_wqt_l);
    cudaGetSymbolAddress((void**)&wath, g_wat_h);
    cudaGetSymbolAddress((void**)&watl, g_wat_l);
    cudaGetSymbolAddress((void**)&wbth, g_wbt_h);
    cudaGetSymbolAddress((void**)&wbtl, g_wbt_l);
    cudaGetSymbolAddress((void**)&woth, g_wot_h);
    cudaGetSymbolAddress((void**)&wotl, g_wot_l);

    cudaFuncSetAttribute(gemm_mma, cudaFuncAttributeMaxDynamicSharedMemorySize, GM_SMEM);
    const int attn_smem = ATTN_SMEM_FLOATS * 4;
    cudaFuncSetAttribute(attn_kernel, cudaFuncAttributeMaxDynamicSharedMemorySize, attn_smem);

    // ---- prep: split x; transpose+split weights ----
    split_kernel<<<(BT_*D_/4 + 255)/256, 256>>>(x, xh, xl, BT_*D_/4);
    transpose_split_kernel<<<dim3((H_*QKD_)/32, D_/32), 256>>>(wq, wqth, wqtl, D_, H_*QKD_);
    transpose_split_kernel<<<dim3((KVR_+ROPE_)/32, D_/32), 256>>>(wkv_a, wath, watl, D_, KVR_+ROPE_);
    transpose_split_kernel<<<dim3((H_*(NOPE_+VD_))/32, KVR_/32), 256>>>(wkv_b, wbth, wbtl, KVR_, H_*(NOPE_+VD_));
    transpose_split_kernel<<<dim3(D_/32, (H_*VD_)/32), 256>>>(wo, woth, wotl, H_*VD_, D_);

    // ---- q = x @ wq : [4096,3072] ----
    gemm_mma<<<dim3(3072/128, BT_/128), 256, GM_SMEM>>>(xh, xl, wqth, wqtl, qp, BT_, H_*QKD_, D_);
    // ---- kvc = x @ wkv_a : [4096,576] ----
    gemm_mma<<<dim3((KVR_+ROPE_+127)/128, BT_/128), 256, GM_SMEM>>>(xh, xl, wath, watl, kvcp, BT_, KVR_+ROPE_, D_);
    // ---- rmsnorm + rope ----
    rmsnorm_kernel<<<BT_, 256>>>(kvcp, kvw, latp);
    rope_q_kernel<<<(BT_*H_*32)/256, 256>>>(qp);
    rope_k_kernel<<<(BT_*32)/256, 256>>>(kvcp, krp);
    // ---- split latent, kv_full = lat @ wkv_b : [4096,4096] ----
    split_kernel<<<(BT_*KVR_/4 + 255)/256, 256>>>(latp, lath, latl, BT_*KVR_/4);
    gemm_mma<<<dim3(4096/128, BT_/128), 256, GM_SMEM>>>(lath, latl, wbth, wbtl, kvfp, BT_, H_*(NOPE_+VD_), KVR_);
    // ---- attention ----
    attn_kernel<<<dim3(T_/64, H_, B_), 256, attn_smem>>>(qp, kvfp, krp, yp);
    // ---- split y, out = y @ wo : [4096,2048] ----
    split_kernel<<<(BT_*H_*VD_/4 + 255)/256, 256>>>(yp, yh, yl, BT_*H_*VD_/4);
    gemm_mma<<<dim3(D_/128, BT_/128), 256, GM_SMEM>>>(yh, yl, woth, wotl, out, BT_, D_, H_*VD_);
}

// round 7
// speedup vs baseline: 2.8381x; 1.7629x over previous
#include <cuda_runtime.h>
#include <cuda_bf16.h>
#include <math.h>
#include <math_constants.h>
#include <cstdint>

// ---------------- problem constants ----------------
#define H_     16
#define NOPE_  128
#define ROPE_  64
#define VD_    128
#define KVR_   512
#define QKD_   192        // NOPE+ROPE
#define B_     2
#define T_     2048
#define D_     2048
#define BT_    (B_*T_)    // 4096

// ---------------- scratch (device globals; no cudaMalloc allowed) ----------------
__device__ float g_q[(size_t)BT_ * H_ * QKD_];             // [B,T,H,192]
__device__ float g_kvc[(size_t)BT_ * (KVR_ + ROPE_)];      // [B,T,576]
__device__ float g_lat[(size_t)BT_ * KVR_];                // [B,T,512]
__device__ float g_kvfull[(size_t)BT_ * H_ * (NOPE_+VD_)]; // [B,T,H,256]
__device__ float g_krope[(size_t)BT_ * ROPE_];             // [B,T,64]
__device__ float g_y[(size_t)BT_ * H_ * VD_];              // [B,T,H,128]

// bf16 split operands (hi/lo)
__device__ __nv_bfloat16 g_xh[(size_t)BT_ * D_];
__device__ __nv_bfloat16 g_xl[(size_t)BT_ * D_];
__device__ __nv_bfloat16 g_lath[(size_t)BT_ * KVR_];
__device__ __nv_bfloat16 g_latl[(size_t)BT_ * KVR_];
__device__ __nv_bfloat16 g_yh[(size_t)BT_ * H_ * VD_];
__device__ __nv_bfloat16 g_yl[(size_t)BT_ * H_ * VD_];
// transposed weights [N,K] bf16 hi/lo
__device__ __nv_bfloat16 g_wqt_h[(size_t)(H_*QKD_) * D_];
__device__ __nv_bfloat16 g_wqt_l[(size_t)(H_*QKD_) * D_];
__device__ __nv_bfloat16 g_wat_h[(size_t)(KVR_+ROPE_) * D_];
__device__ __nv_bfloat16 g_wat_l[(size_t)(KVR_+ROPE_) * D_];
__device__ __nv_bfloat16 g_wbt_h[(size_t)(H_*(NOPE_+VD_)) * KVR_];
__device__ __nv_bfloat16 g_wbt_l[(size_t)(H_*(NOPE_+VD_)) * KVR_];
__device__ __nv_bfloat16 g_wot_h[(size_t)D_ * (H_*VD_)];
__device__ __nv_bfloat16 g_wot_l[(size_t)D_ * (H_*VD_)];

// ---------------- helpers ----------------
__device__ __forceinline__ uint32_t smem_u32(const void* p) {
    uint32_t a;
    asm("{ .reg .u64 t; cvta.to.shared.u64 t, %1; cvt.u32.u64 %0, t; }" : "=r"(a) : "l"(p));
    return a;
}

__device__ __forceinline__ void ldsm_x4(uint32_t* r, uint32_t addr) {
    asm volatile("ldmatrix.sync.aligned.m8n8.x4.shared.b16 {%0,%1,%2,%3}, [%4];"
                 : "=r"(r[0]), "=r"(r[1]), "=r"(r[2]), "=r"(r[3]) : "r"(addr));
}
__device__ __forceinline__ void ldsm_x4_trans(uint32_t* r, uint32_t addr) {
    asm volatile("ldmatrix.sync.aligned.m8n8.x4.trans.shared.b16 {%0,%1,%2,%3}, [%4];"
                 : "=r"(r[0]), "=r"(r[1]), "=r"(r[2]), "=r"(r[3]) : "r"(addr));
}

__device__ __forceinline__ void mma16816(float* c, const uint32_t* a, const uint32_t* b) {
    asm volatile(
        "mma.sync.aligned.m16n8k16.row.col.f32.bf16.bf16.f32 "
        "{%0,%1,%2,%3}, {%4,%5,%6,%7}, {%8,%9}, {%0,%1,%2,%3};"
        : "+f"(c[0]), "+f"(c[1]), "+f"(c[2]), "+f"(c[3])
        : "r"(a[0]), "r"(a[1]), "r"(a[2]), "r"(a[3]), "r"(b[0]), "r"(b[1]));
}

// pack two floats to bf16x2: low half = first arg, high half = second
__device__ __forceinline__ uint32_t pack_bf16x2(float lo, float hi) {
    uint32_t d;
    asm("cvt.rn.bf16x2.f32 %0, %1, %2;" : "=r"(d) : "f"(hi), "f"(lo));
    return d;
}

// split float4 to hi/lo bf16x2 pairs and store 8B each to smem
__device__ __forceinline__ void split_store8(uint32_t addr_h, uint32_t addr_l, float4 v) {
    uint32_t h0 = pack_bf16x2(v.x, v.y);
    uint32_t h1 = pack_bf16x2(v.z, v.w);
    float l0 = v.x - __uint_as_float(h0 << 16);
    float l1 = v.y - __uint_as_float(h0 & 0xffff0000u);
    float l2 = v.z - __uint_as_float(h1 << 16);
    float l3 = v.w - __uint_as_float(h1 & 0xffff0000u);
    uint32_t p0 = pack_bf16x2(l0, l1);
    uint32_t p1 = pack_bf16x2(l2, l3);
    asm volatile("st.shared.v2.b32 [%0], {%1,%2};" :: "r"(addr_h), "r"(h0), "r"(h1) : "memory");
    asm volatile("st.shared.v2.b32 [%0], {%1,%2};" :: "r"(addr_l), "r"(p0), "r"(p1) : "memory");
}

// ---------------- HMMA GEMM: C[M,Nn] = (Ah+Al)[M,K] @ (Bh+Bl)[Nn,K]^T ----------------
#define GT_PITCHB 80
#define GT_TILE   10240
#define GT_BUF    40960
#define GM_SMEM   (2 * GT_BUF)

__device__ __forceinline__ void gemm_load_regs(
    uint4* pf, const __nv_bfloat16* Ah, const __nv_bfloat16* Al,
    const __nv_bfloat16* Bh, const __nv_bfloat16* Bl,
    int bm0, int bn0, int K, int Nn, int k0, int tid)
{
#pragma unroll
    for (int l = 0; l < 8; l++) {
        const int u = l * 256 + tid;
        const int tile = u >> 9;
        const int r = (u >> 2) & 127;
        const int c4 = u & 3;
        const __nv_bfloat16* src;
        int row;
        bool ok = true;
        if (tile == 0)      { src = Ah; row = bm0 + r; }
        else if (tile == 1) { src = Al; row = bm0 + r; }
        else {
            src = (tile == 2) ? Bh : Bl;
            row = bn0 + r;
            ok = (row < Nn);
        }
        pf[l] = ok ? *(const uint4*)(src + (size_t)row * K + k0 + c4 * 8)
                   : make_uint4(0u, 0u, 0u, 0u);
    }
}

__device__ __forceinline__ void gemm_store_smem(const uint4* pf, uint32_t sbase, int tid)
{
#pragma unroll
    for (int l = 0; l < 8; l++) {
        const int u = l * 256 + tid;
        const int tile = u >> 9;
        const int r = (u >> 2) & 127;
        const int c4 = u & 3;
        const uint32_t addr = sbase + tile * GT_TILE + r * GT_PITCHB + c4 * 16;
        asm volatile("st.shared.v4.b32 [%0], {%1,%2,%3,%4};"
                     :: "r"(addr), "r"(pf[l].x), "r"(pf[l].y), "r"(pf[l].z), "r"(pf[l].w)
                     : "memory");
    }
}

__device__ __forceinline__ void gemm_compute(
    uint32_t sbase, int wm, int wn, int lane, float c[4][4][4])
{
#pragma unroll
    for (int ks = 0; ks < 32; ks += 16) {
        uint32_t Ahf[4][4], Alf[4][4], Bhf[4][2], Blf[4][2];
#pragma unroll
        for (int mi = 0; mi < 4; mi++) {
            const int row = wm * 64 + mi * 16 + (lane & 15);
            const uint32_t a = sbase + row * GT_PITCHB + (ks + (lane >> 4) * 8) * 2;
            ldsm_x4(Ahf[mi], a);
            ldsm_x4(Alf[mi], a + GT_TILE);
        }
#pragma unroll
        for (int nj = 0; nj < 2; nj++) {
            const int nrow = wn * 32 + nj * 16 + ((lane >> 4) & 1) * 8 + (lane & 7);
            const uint32_t b = sbase + 2 * GT_TILE + nrow * GT_PITCHB
                             + (ks + ((lane >> 3) & 1) * 8) * 2;
            ldsm_x4(&Bhf[nj * 2][0], b);
            ldsm_x4(&Blf[nj * 2][0], b + GT_TILE);
        }
#pragma unroll
        for (int mi = 0; mi < 4; mi++)
#pragma unroll
            for (int ni = 0; ni < 4; ni++) {
                mma16816(c[mi][ni], Ahf[mi], Bhf[ni]);
                mma16816(c[mi][ni], Alf[mi], Bhf[ni]);
                mma16816(c[mi][ni], Ahf[mi], Blf[ni]);
            }
    }
}

__global__ __launch_bounds__(256) void gemm_mma(
    const __nv_bfloat16* __restrict__ Ah, const __nv_bfloat16* __restrict__ Al,
    const __nv_bfloat16* __restrict__ Bh, const __nv_bfloat16* __restrict__ Bl,
    float* __restrict__ C, int M, int Nn, int K)
{
    extern __shared__ char smem[];
    const uint32_t sb = smem_u32(smem);
    const int tid = threadIdx.x;
    const int lane = tid & 31;
    const int wid = tid >> 5;
    const int wm = wid & 1;
    const int wn = wid >> 1;
    const int bm0 = blockIdx.y * 128;
    const int bn0 = blockIdx.x * 128;

    float c[4][4][4];
#pragma unroll
    for (int mi = 0; mi < 4; mi++)
#pragma unroll
        for (int ni = 0; ni < 4; ni++)
#pragma unroll
            for (int k = 0; k < 4; k++) c[mi][ni][k] = 0.f;

    uint4 pf[8];
    gemm_load_regs(pf, Ah, Al, Bh, Bl, bm0, bn0, K, Nn, 0, tid);
    gemm_store_smem(pf, sb, tid);
    __syncthreads();

    const int nc = K >> 5;
    for (int i = 0; i < nc; i++) {
        if (i + 1 < nc)
            gemm_load_regs(pf, Ah, Al, Bh, Bl, bm0, bn0, K, Nn, (i + 1) * 32, tid);
        gemm_compute(sb + (i & 1) * GT_BUF, wm, wn, lane, c);
        if (i + 1 < nc)
            gemm_store_smem(pf, sb + ((i + 1) & 1) * GT_BUF, tid);
        __syncthreads();
    }

    const int g = lane >> 2;
    const int t = lane & 3;
#pragma unroll
    for (int mi = 0; mi < 4; mi++) {
        const int row = bm0 + wm * 64 + mi * 16 + g;
#pragma unroll
        for (int ni = 0; ni < 4; ni++) {
            const int col = bn0 + wn * 32 + ni * 8 + 2 * t;
            if (col < Nn) {
                float2 v0 = make_float2(c[mi][ni][0], c[mi][ni][1]);
                float2 v1 = make_float2(c[mi][ni][2], c[mi][ni][3]);
                *(float2*)&C[(size_t)row * Nn + col] = v0;
                *(float2*)&C[(size_t)(row + 8) * Nn + col] = v1;
            }
        }
    }
}

// ---------------- bf16 hi/lo split (element-wise, float4) ----------------
__global__ __launch_bounds__(256) void split_kernel(
    const float* __restrict__ x, __nv_bfloat16* __restrict__ h,
    __nv_bfloat16* __restrict__ l, int n4)
{
    int i = blockIdx.x * 256 + threadIdx.x;
    if (i >= n4) return;
    float4 v = ((const float4*)x)[i];
    __nv_bfloat16 h0 = __float2bfloat16(v.x), h1 = __float2bfloat16(v.y);
    __nv_bfloat16 h2 = __float2bfloat16(v.z), h3 = __float2bfloat16(v.w);
    __nv_bfloat16 l0 = __float2bfloat16(v.x - __bfloat162float(h0));
    __nv_bfloat16 l1 = __float2bfloat16(v.y - __bfloat162float(h1));
    __nv_bfloat16 l2 = __float2bfloat16(v.z - __bfloat162float(h2));
    __nv_bfloat16 l3 = __float2bfloat16(v.w - __bfloat162float(h3));
    ((__nv_bfloat162*)h)[i*2]   = __nv_bfloat162(h0, h1);
    ((__nv_bfloat162*)h)[i*2+1] = __nv_bfloat162(h2, h3);
    ((__nv_bfloat162*)l)[i*2]   = __nv_bfloat162(l0, l1);
    ((__nv_bfloat162*)l)[i*2+1] = __nv_bfloat162(l2, l3);
}

// ---------------- transpose + split: W[K,N] fp32 -> Wt hi/lo [N,K] bf16 ----------------
__global__ __launch_bounds__(256) void transpose_split_kernel(
    const float* __restrict__ W, __nv_bfloat16* __restrict__ th,
    __nv_bfloat16* __restrict__ tl, int K, int N)
{
    __shared__ float tile[32][33];
    const int bx = blockIdx.x * 32;
    const int by = blockIdx.y * 32;
    const int txi = threadIdx.x & 31;
    const int tyi = threadIdx.x >> 5;
#pragma unroll
    for (int j = 0; j < 32; j += 8) {
        int kk = by + tyi + j, nn = bx + txi;
        if (kk < K && nn < N) tile[tyi + j][txi] = W[(size_t)kk * N + nn];
    }
    __syncthreads();
#pragma unroll
    for (int j = 0; j < 32; j += 8) {
        int nn = bx + tyi + j, kk = by + txi;
        if (nn < N && kk < K) {
            float v = tile[txi][tyi + j];
            __nv_bfloat16 hi = __float2bfloat16(v);
            __nv_bfloat16 lo = __float2bfloat16(v - __bfloat162float(hi));
            th[(size_t)nn * K + kk] = hi;
            tl[(size_t)nn * K + kk] = lo;
        }
    }
}

// ---------------- RMSNorm on kvc[:, :512] -> lat ----------------
__global__ __launch_bounds__(256) void rmsnorm_kernel(
    const float* __restrict__ kvc, const float* __restrict__ w,
    float* __restrict__ lat)
{
    const int row = blockIdx.x;
    const float* x = kvc + (size_t)row * (KVR_ + ROPE_);
    const int tid = threadIdx.x;

    float v0 = x[tid];
    float v1 = x[tid + 256];
    float ss = v0 * v0 + v1 * v1;
#pragma unroll
    for (int off = 16; off; off >>= 1)
        ss += __shfl_xor_sync(0xffffffffu, ss, off);

    __shared__ float red[8];
    if ((tid & 31) == 0) red[tid >> 5] = ss;
    __syncthreads();
    float tot = 0.f;
#pragma unroll
    for (int i = 0; i < 8; i++) tot += red[i];

    float nrm = rsqrtf(tot * (1.f / 512.f) + 1e-6f);
    float* o = lat + (size_t)row * KVR_;
    o[tid]       = v0 * nrm * w[tid];
    o[tid + 256] = v1 * nrm * w[tid + 256];
}

// ---------------- RoPE ----------------
__global__ __launch_bounds__(256) void rope_q_kernel(float* __restrict__ q)
{
    int idx = blockIdx.x * 256 + threadIdx.x;
    if (idx >= BT_ * H_ * 32) return;
    int i  = idx & 31;
    int h  = (idx >> 5) & (H_ - 1);
    int bt = idx >> 9;
    int t  = bt & (T_ - 1);

    float inv = powf(10000.f, -(float)(2 * i) / 64.f);
    float f = (float)t * inv;
    float c = cosf(f), s = sinf(f);

    float* p = q + ((size_t)bt * H_ + h) * QKD_ + NOPE_;
    float x1 = p[i], x2 = p[i + 32];
    p[i]      = x1 * c - x2 * s;
    p[i + 32] = x2 * c + x1 * s;
}

__global__ __launch_bounds__(256) void rope_k_kernel(
    const float* __restrict__ kvc, float* __restrict__ krope)
{
    int idx = blockIdx.x * 256 + threadIdx.x;
    if (idx >= BT_ * 32) return;
    int i  = idx & 31;
    int bt = idx >> 5;
    int t  = bt & (T_ - 1);

    float inv = powf(10000.f, -(float)(2 * i) / 64.f);
    float f = (float)t * inv;
    float c = cosf(f), s = sinf(f);

    const float* p = kvc + (size_t)bt * (KVR_ + ROPE_) + KVR_;
    float x1 = p[i], x2 = p[i + 32];
    float* o = krope + (size_t)bt * ROPE_;
    o[i]      = x1 * c - x2 * s;
    o[i + 32] = x2 * c + x1 * s;
}

// ---------------- HMMA causal flash attention ----------------
// BQ=128, BK=64, 8 warps (one per 16 q-rows). Hi/lo bf16 compensation on both matmuls.
#define ABQ 128
#define ABK 64
#define AQ_PITCH 400   // bytes per Q smem row (200 bf16)
#define AK_PITCH 400
#define AV_PITCH 272   // 136 bf16
#define OFF_QH 0
#define OFF_QL 51200
#define OFF_KH 102400
#define OFF_KL 128000
#define OFF_VH 153600
#define OFF_VL 171008
#define ATTN_SMEM 188416

__device__ __forceinline__ float quadmax(float v) {
    v = fmaxf(v, __shfl_xor_sync(0xffffffffu, v, 1));
    v = fmaxf(v, __shfl_xor_sync(0xffffffffu, v, 2));
    return v;
}
__device__ __forceinline__ float quadsum(float v) {
    v += __shfl_xor_sync(0xffffffffu, v, 1);
    v += __shfl_xor_sync(0xffffffffu, v, 2);
    return v;
}

__global__ __launch_bounds__(256) void attn_mma_kernel(
    const float* __restrict__ q, const float* __restrict__ kvfull,
    const float* __restrict__ krope, float* __restrict__ y)
{
    extern __shared__ char smem[];
    const uint32_t sb = smem_u32(smem);
    const int b  = blockIdx.z;
    const int h  = blockIdx.y;
    const int qt = blockIdx.x;
    const int q0 = qt * ABQ;
    const int tid = threadIdx.x;
    const int lane = tid & 31;
    const int w = tid >> 5;
    const int g = lane >> 2;
    const int t = lane & 3;
    const float scale = 0.07216878364870322f;   // 192^-0.5

    // load Q tile [128][192] fp32 -> hi/lo bf16 smem
#pragma unroll
    for (int l = 0; l < 24; l++) {
        int u = l * 256 + tid;
        int row = u / 48, c4 = u % 48, d = c4 * 4;
        float4 v = *(const float4*)&q[(((size_t)(b * T_ + q0 + row)) * H_ + h) * QKD_ + d];
        uint32_t ah = sb + OFF_QH + row * AQ_PITCH + d * 2;
        split_store8(ah, ah + (OFF_QL - OFF_QH), v);
    }

    float oc[16][4];
#pragma unroll
    for (int d = 0; d < 16; d++) { oc[d][0]=0.f; oc[d][1]=0.f; oc[d][2]=0.f; oc[d][3]=0.f; }
    float m0 = -CUDART_INF_F, m1 = -CUDART_INF_F, l0s = 0.f, l1s = 0.f;

    const int row0 = q0 + w * 16 + g;        // this lane's first row
    const int wrow_max = q0 + w * 16 + 15;

    const int nkt = 2 * qt + 2;
    for (int kt = 0; kt < nkt; kt++) {
        const int k0 = kt * ABK;
        __syncthreads();   // previous compute done before overwriting K/V smem

        // load K tile [64][192]
#pragma unroll
        for (int l = 0; l < 12; l++) {
            int u = l * 256 + tid;
            int row = u / 48, c4 = u % 48, d = c4 * 4;
            size_t tok = (size_t)(b * T_ + k0 + row);
            float4 v;
            if (d < NOPE_) v = *(const float4*)&kvfull[(tok * H_ + h) * (NOPE_+VD_) + d];
            else           v = *(const float4*)&krope[tok * ROPE_ + (d - NOPE_)];
            uint32_t ah = sb + OFF_KH + row * AK_PITCH + d * 2;
            split_store8(ah, ah + (OFF_KL - OFF_KH), v);
        }
        // load V tile [64][128]
#pragma unroll
        for (int l = 0; l < 8; l++) {
            int u = l * 256 + tid;
            int row = u >> 5, c4 = u & 31, d = c4 * 4;
            size_t tok = (size_t)(b * T_ + k0 + row);
            float4 v = *(const float4*)&kvfull[(tok * H_ + h) * (NOPE_+VD_) + NOPE_ + d];
            uint32_t ah = sb + OFF_VH + row * AV_PITCH + d * 2;
            split_store8(ah, ah + (OFF_VL - OFF_VH), v);
        }
        __syncthreads();

        if (k0 > wrow_max) continue;   // tile fully above diagonal for this warp

        // ---- S = Q @ K^T (hi/lo 3-product) ----
        float sc[8][4];
#pragma unroll
        for (int j = 0; j < 8; j++) { sc[j][0]=0.f; sc[j][1]=0.f; sc[j][2]=0.f; sc[j][3]=0.f; }

#pragma unroll
        for (int kb = 0; kb < 12; kb++) {
            uint32_t qa = sb + OFF_QH + (w * 16 + (lane & 15)) * AQ_PITCH
                        + (kb * 16 + (lane >> 4) * 8) * 2;
            uint32_t aqh[4], aql[4];
            ldsm_x4(aqh, qa);
            ldsm_x4(aql, qa + (OFF_QL - OFF_QH));
            uint32_t kh[8][2], kl[8][2];
#pragma unroll
            for (int nj = 0; nj < 4; nj++) {
                uint32_t ka = sb + OFF_KH
                            + (nj * 16 + ((lane >> 4) & 1) * 8 + (lane & 7)) * AK_PITCH
                            + (kb * 16 + ((lane >> 3) & 1) * 8) * 2;
                ldsm_x4(&kh[nj * 2][0], ka);
                ldsm_x4(&kl[nj * 2][0], ka + (OFF_KL - OFF_KH));
            }
#pragma unroll
            for (int j = 0; j < 8; j++) {
                mma16816(sc[j], aqh, kh[j]);
                mma16816(sc[j], aql, kh[j]);
                mma16816(sc[j], aqh, kl[j]);
            }
        }

        // ---- scale + causal mask ----
        const bool need_mask = (k0 + ABK - 1 > q0 + w * 16);
#pragma unroll
        for (int j = 0; j < 8; j++) {
            int cbase = k0 + 8 * j + 2 * t;
#pragma unroll
            for (int e = 0; e < 4; e++) {
                int col = cbase + (e & 1);
                int row = (e < 2) ? row0 : row0 + 8;
                float v = sc[j][e] * scale;
                sc[j][e] = (need_mask && col > row) ? -CUDART_INF_F : v;
            }
        }

        // ---- online softmax ----
        float tm0 = -CUDART_INF_F, tm1 = -CUDART_INF_F;
#pragma unroll
        for (int j = 0; j < 8; j++) {
            tm0 = fmaxf(tm0, fmaxf(sc[j][0], sc[j][1]));
            tm1 = fmaxf(tm1, fmaxf(sc[j][2], sc[j][3]));
        }
        tm0 = quadmax(tm0); tm1 = quadmax(tm1);
        float mn0 = fmaxf(m0, tm0), mn1 = fmaxf(m1, tm1);
        float corr0 = __expf(m0 - mn0), corr1 = __expf(m1 - mn1);
        float rs0 = 0.f, rs1 = 0.f;
#pragma unroll
        for (int j = 0; j < 8; j++) {
            sc[j][0] = __expf(sc[j][0] - mn0);
            sc[j][1] = __expf(sc[j][1] - mn0);
            sc[j][2] = __expf(sc[j][2] - mn1);
            sc[j][3] = __expf(sc[j][3] - mn1);
            rs0 += sc[j][0] + sc[j][1];
            rs1 += sc[j][2] + sc[j][3];
        }
        rs0 = quadsum(rs0); rs1 = quadsum(rs1);
        l0s = l0s * corr0 + rs0;
        l1s = l1s * corr1 + rs1;
        m0 = mn0; m1 = mn1;
#pragma unroll
        for (int d = 0; d < 16; d++) {
            oc[d][0] *= corr0; oc[d][1] *= corr0;
            oc[d][2] *= corr1; oc[d][3] *= corr1;
        }

        // ---- O += P @ V (P frags from S accumulators; hi/lo 3-product) ----
#pragma unroll
        for (int kb2 = 0; kb2 < 4; kb2++) {
            uint32_t pah[4], pal[4];
#pragma unroll
            for (int half = 0; half < 2; half++) {
                int j = 2 * kb2 + half;
                uint32_t ph0 = pack_bf16x2(sc[j][0], sc[j][1]);
                uint32_t ph1 = pack_bf16x2(sc[j][2], sc[j][3]);
                float lo0 = sc[j][0] - __uint_as_float(ph0 << 16);
                float lo1 = sc[j][1] - __uint_as_float(ph0 & 0xffff0000u);
                float lo2 = sc[j][2] - __uint_as_float(ph1 << 16);
                float lo3 = sc[j][3] - __uint_as_float(ph1 & 0xffff0000u);
                pah[half * 2 + 0] = ph0;
                pah[half * 2 + 1] = ph1;
                pal[half * 2 + 0] = pack_bf16x2(lo0, lo1);
                pal[half * 2 + 1] = pack_bf16x2(lo2, lo3);
            }
#pragma unroll
            for (int dp = 0; dp < 8; dp++) {
                uint32_t vh[4], vl[4];
                uint32_t va = sb + OFF_VH
                            + (kb2 * 16 + (lane & 7) + ((lane >> 3) & 1) * 8) * AV_PITCH
                            + (dp * 16 + (lane >> 4) * 8) * 2;
                ldsm_x4_trans(vh, va);
                ldsm_x4_trans(vl, va + (OFF_VL - OFF_VH));
                mma16816(oc[dp * 2],     pah, &vh[0]);
                mma16816(oc[dp * 2],     pal, &vh[0]);
                mma16816(oc[dp * 2],     pah, &vl[0]);
                mma16816(oc[dp * 2 + 1], pah, &vh[2]);
                mma16816(oc[dp * 2 + 1], pal, &vh[2]);
                mma16816(oc[dp * 2 + 1], pah, &vl[2]);
            }
        }
    }

    // ---- epilogue ----
    float inv0 = 1.f / l0s, inv1 = 1.f / l1s;
#pragma unroll
    for (int d = 0; d < 16; d++) {
        int col = d * 8 + 2 * t;
        size_t base0 = (((size_t)(b * T_ + row0)) * H_ + h) * VD_ + col;
        size_t base1 = (((size_t)(b * T_ + row0 + 8)) * H_ + h) * VD_ + col;
        *(float2*)&y[base0] = make_float2(oc[d][0] * inv0, oc[d][1] * inv0);
        *(float2*)&y[base1] = make_float2(oc[d][2] * inv1, oc[d][3] * inv1);
    }
}

// ---------------- launch ----------------
extern "C" void kernel_launch(void* const* d_in, const int* in_sizes, int n_in,
                              void* d_out, int out_size)
{
    const float* x      = (const float*)d_in[0];
    const float* wq     = (const float*)d_in[1];
    const float* wkv_a  = (const float*)d_in[2];
    const float* wkv_b  = (const float*)d_in[3];
    const float* wo     = (const float*)d_in[4];
    const float* kvw    = (const float*)d_in[5];
    float* out = (float*)d_out;

    float *qp, *kvcp, *latp, *kvfp, *krp, *yp;
    cudaGetSymbolAddress((void**)&qp,   g_q);
    cudaGetSymbolAddress((void**)&kvcp, g_kvc);
    cudaGetSymbolAddress((void**)&latp, g_lat);
    cudaGetSymbolAddress((void**)&kvfp, g_kvfull);
    cudaGetSymbolAddress((void**)&krp,  g_krope);
    cudaGetSymbolAddress((void**)&yp,   g_y);

    __nv_bfloat16 *xh, *xl, *lath, *latl, *yh, *yl;
    __nv_bfloat16 *wqth, *wqtl, *wath, *watl, *wbth, *wbtl, *woth, *wotl;
    cudaGetSymbolAddress((void**)&xh,   g_xh);
    cudaGetSymbolAddress((void**)&xl,   g_xl);
    cudaGetSymbolAddress((void**)&lath, g_lath);
    cudaGetSymbolAddress((void**)&latl, g_latl);
    cudaGetSymbolAddress((void**)&yh,   g_yh);
    cudaGetSymbolAddress((void**)&yl,   g_yl);
    cudaGetSymbolAddress((void**)&wqth, g_wqt_h);
    cudaGetSymbolAddress((void**)&wqtl, g_wqt_l);
    cudaGetSymbolAddress((void**)&wath, g_wat_h);
    cudaGetSymbolAddress((void**)&watl, g_wat_l);
    cudaGetSymbolAddress((void**)&wbth, g_wbt_h);
    cudaGetSymbolAddress((void**)&wbtl, g_wbt_l);
    cudaGetSymbolAddress((void**)&woth, g_wot_h);
    cudaGetSymbolAddress((void**)&wotl, g_wot_l);

    cudaFuncSetAttribute(gemm_mma, cudaFuncAttributeMaxDynamicSharedMemorySize, GM_SMEM);
    cudaFuncSetAttribute(attn_mma_kernel, cudaFuncAttributeMaxDynamicSharedMemorySize, ATTN_SMEM);

    // ---- prep: split x; transpose+split weights ----
    split_kernel<<<(BT_*D_/4 + 255)/256, 256>>>(x, xh, xl, BT_*D_/4);
    transpose_split_kernel<<<dim3((H_*QKD_)/32, D_/32), 256>>>(wq, wqth, wqtl, D_, H_*QKD_);
    transpose_split_kernel<<<dim3((KVR_+ROPE_)/32, D_/32), 256>>>(wkv_a, wath, watl, D_, KVR_+ROPE_);
    transpose_split_kernel<<<dim3((H_*(NOPE_+VD_))/32, KVR_/32), 256>>>(wkv_b, wbth, wbtl, KVR_, H_*(NOPE_+VD_));
    transpose_split_kernel<<<dim3(D_/32, (H_*VD_)/32), 256>>>(wo, woth, wotl, H_*VD_, D_);

    // ---- q = x @ wq ----
    gemm_mma<<<dim3(3072/128, BT_/128), 256, GM_SMEM>>>(xh, xl, wqth, wqtl, qp, BT_, H_*QKD_, D_);
    // ---- kvc = x @ wkv_a ----
    gemm_mma<<<dim3((KVR_+ROPE_+127)/128, BT_/128), 256, GM_SMEM>>>(xh, xl, wath, watl, kvcp, BT_, KVR_+ROPE_, D_);
    // ---- rmsnorm + rope ----
    rmsnorm_kernel<<<BT_, 256>>>(kvcp, kvw, latp);
    rope_q_kernel<<<(BT_*H_*32)/256, 256>>>(qp);
    rope_k_kernel<<<(BT_*32)/256, 256>>>(kvcp, krp);
    // ---- kv_full = lat @ wkv_b ----
    split_kernel<<<(BT_*KVR_/4 + 255)/256, 256>>>(latp, lath, latl, BT_*KVR_/4);
    gemm_mma<<<dim3(4096/128, BT_/128), 256, GM_SMEM>>>(lath, latl, wbth, wbtl, kvfp, BT_, H_*(NOPE_+VD_), KVR_);
    // ---- attention (HMMA flash) ----
    attn_mma_kernel<<<dim3(T_/ABQ, H_, B_), 256, ATTN_SMEM>>>(qp, kvfp, krp, yp);
    // ---- out = y @ wo ----
    split_kernel<<<(BT_*H_*VD_/4 + 255)/256, 256>>>(yp, yh, yl, BT_*H_*VD_/4);
    gemm_mma<<<dim3(D_/128, BT_/128), 256, GM_SMEM>>>(yh, yl, woth, wotl, out, BT_, D_, H_*VD_);
}

// round 8
// speedup vs baseline: 2.9040x; 1.0232x over previous
#include <cuda_runtime.h>
#include <cuda_bf16.h>
#include <math.h>
#include <math_constants.h>
#include <cstdint>

// ---------------- problem constants ----------------
#define H_     16
#define NOPE_  128
#define ROPE_  64
#define VD_    128
#define KVR_   512
#define QKD_   192        // NOPE+ROPE
#define B_     2
#define T_     2048
#define D_     2048
#define BT_    (B_*T_)    // 4096

// ---------------- scratch (device globals; no cudaMalloc allowed) ----------------
__device__ float g_q[(size_t)BT_ * H_ * QKD_];
__device__ float g_kvc[(size_t)BT_ * (KVR_ + ROPE_)];
__device__ float g_lat[(size_t)BT_ * KVR_];
__device__ float g_kvfull[(size_t)BT_ * H_ * (NOPE_+VD_)];
__device__ float g_krope[(size_t)BT_ * ROPE_];
__device__ float g_y[(size_t)BT_ * H_ * VD_];

__device__ __nv_bfloat16 g_xh[(size_t)BT_ * D_];
__device__ __nv_bfloat16 g_xl[(size_t)BT_ * D_];
__device__ __nv_bfloat16 g_lath[(size_t)BT_ * KVR_];
__device__ __nv_bfloat16 g_latl[(size_t)BT_ * KVR_];
__device__ __nv_bfloat16 g_yh[(size_t)BT_ * H_ * VD_];
__device__ __nv_bfloat16 g_yl[(size_t)BT_ * H_ * VD_];
__device__ __nv_bfloat16 g_wqt_h[(size_t)(H_*QKD_) * D_];
__device__ __nv_bfloat16 g_wqt_l[(size_t)(H_*QKD_) * D_];
__device__ __nv_bfloat16 g_wat_h[(size_t)(KVR_+ROPE_) * D_];
__device__ __nv_bfloat16 g_wat_l[(size_t)(KVR_+ROPE_) * D_];
__device__ __nv_bfloat16 g_wbt_h[(size_t)(H_*(NOPE_+VD_)) * KVR_];
__device__ __nv_bfloat16 g_wbt_l[(size_t)(H_*(NOPE_+VD_)) * KVR_];
__device__ __nv_bfloat16 g_wot_h[(size_t)D_ * (H_*VD_)];
__device__ __nv_bfloat16 g_wot_l[(size_t)D_ * (H_*VD_)];

// ---------------- helpers ----------------
__device__ __forceinline__ uint32_t smem_u32(const void* p) {
    uint32_t a;
    asm("{ .reg .u64 t; cvta.to.shared.u64 t, %1; cvt.u32.u64 %0, t; }" : "=r"(a) : "l"(p));
    return a;
}

__device__ __forceinline__ void ldsm_x4(uint32_t* r, uint32_t addr) {
    asm volatile("ldmatrix.sync.aligned.m8n8.x4.shared.b16 {%0,%1,%2,%3}, [%4];"
                 : "=r"(r[0]), "=r"(r[1]), "=r"(r[2]), "=r"(r[3]) : "r"(addr));
}
__device__ __forceinline__ void ldsm_x4_trans(uint32_t* r, uint32_t addr) {
    asm volatile("ldmatrix.sync.aligned.m8n8.x4.trans.shared.b16 {%0,%1,%2,%3}, [%4];"
                 : "=r"(r[0]), "=r"(r[1]), "=r"(r[2]), "=r"(r[3]) : "r"(addr));
}

__device__ __forceinline__ void mma16816(float* c, const uint32_t* a, const uint32_t* b) {
    asm volatile(
        "mma.sync.aligned.m16n8k16.row.col.f32.bf16.bf16.f32 "
        "{%0,%1,%2,%3}, {%4,%5,%6,%7}, {%8,%9}, {%0,%1,%2,%3};"
        : "+f"(c[0]), "+f"(c[1]), "+f"(c[2]), "+f"(c[3])
        : "r"(a[0]), "r"(a[1]), "r"(a[2]), "r"(a[3]), "r"(b[0]), "r"(b[1]));
}

__device__ __forceinline__ uint32_t pack_bf16x2(float lo, float hi) {
    uint32_t d;
    asm("cvt.rn.bf16x2.f32 %0, %1, %2;" : "=r"(d) : "f"(hi), "f"(lo));
    return d;
}

__device__ __forceinline__ void split_store8(uint32_t addr_h, uint32_t addr_l, float4 v) {
    uint32_t h0 = pack_bf16x2(v.x, v.y);
    uint32_t h1 = pack_bf16x2(v.z, v.w);
    float l0 = v.x - __uint_as_float(h0 << 16);
    float l1 = v.y - __uint_as_float(h0 & 0xffff0000u);
    float l2 = v.z - __uint_as_float(h1 << 16);
    float l3 = v.w - __uint_as_float(h1 & 0xffff0000u);
    uint32_t p0 = pack_bf16x2(l0, l1);
    uint32_t p1 = pack_bf16x2(l2, l3);
    asm volatile("st.shared.v2.b32 [%0], {%1,%2};" :: "r"(addr_h), "r"(h0), "r"(h1) : "memory");
    asm volatile("st.shared.v2.b32 [%0], {%1,%2};" :: "r"(addr_l), "r"(p0), "r"(p1) : "memory");
}

// cp.async 16B with predicated src-size (0 => zero-fill)
__device__ __forceinline__ void cp16(uint32_t dst, const void* src, bool pred) {
    int sz = pred ? 16 : 0;
    asm volatile("cp.async.cg.shared.global [%0], [%1], 16, %2;"
                 :: "r"(dst), "l"(src), "r"(sz) : "memory");
}
#define CP_COMMIT() asm volatile("cp.async.commit_group;" ::: "memory")
#define CP_WAIT1()  asm volatile("cp.async.wait_group 1;" ::: "memory")

// ---------------- HMMA GEMM with cp.async 3-stage pipeline ----------------
#define GT_PITCHB 80
#define GT_TILE   10240
#define GT_BUF    40960
#define GM_SMEM   (3 * GT_BUF)

__device__ __forceinline__ void gemm_cp_chunk(
    uint32_t sbase, const __nv_bfloat16* Ah, const __nv_bfloat16* Al,
    const __nv_bfloat16* Bh, const __nv_bfloat16* Bl,
    int bm0, int bn0, int K, int Nn, int k0, int tid)
{
#pragma unroll
    for (int l = 0; l < 8; l++) {
        const int u = l * 256 + tid;      // 0..2047
        const int tile = u >> 9;          // 0..3
        const int r = (u >> 2) & 127;
        const int c4 = u & 3;
        const uint32_t dst = sbase + tile * GT_TILE + r * GT_PITCHB + c4 * 16;
        const __nv_bfloat16* src;
        int row;
        bool ok = true;
        if (tile == 0)      { src = Ah; row = bm0 + r; }
        else if (tile == 1) { src = Al; row = bm0 + r; }
        else {
            src = (tile == 2) ? Bh : Bl;
            row = bn0 + r;
            ok = (row < Nn);
            if (!ok) row = Nn - 1;
        }
        cp16(dst, src + (size_t)row * K + k0 + c4 * 8, ok);
    }
}

__device__ __forceinline__ void gemm_compute(
    uint32_t sbase, int wm, int wn, int lane, float c[4][4][4])
{
#pragma unroll
    for (int ks = 0; ks < 32; ks += 16) {
        uint32_t Bhf[4][2], Blf[4][2];
#pragma unroll
        for (int nj = 0; nj < 2; nj++) {
            const int nrow = wn * 32 + nj * 16 + ((lane >> 4) & 1) * 8 + (lane & 7);
            const uint32_t b = sbase + 2 * GT_TILE + nrow * GT_PITCHB
                             + (ks + ((lane >> 3) & 1) * 8) * 2;
            ldsm_x4(&Bhf[nj * 2][0], b);
            ldsm_x4(&Blf[nj * 2][0], b + GT_TILE);
        }
#pragma unroll
        for (int mi = 0; mi < 4; mi++) {
            uint32_t ah[4], al[4];
            const int row = wm * 64 + mi * 16 + (lane & 15);
            const uint32_t a = sbase + row * GT_PITCHB + (ks + (lane >> 4) * 8) * 2;
            ldsm_x4(ah, a);
            ldsm_x4(al, a + GT_TILE);
#pragma unroll
            for (int ni = 0; ni < 4; ni++) {
                mma16816(c[mi][ni], ah, Bhf[ni]);
                mma16816(c[mi][ni], al, Bhf[ni]);
                mma16816(c[mi][ni], ah, Blf[ni]);
            }
        }
    }
}

__global__ __launch_bounds__(256) void gemm_mma(
    const __nv_bfloat16* __restrict__ Ah, const __nv_bfloat16* __restrict__ Al,
    const __nv_bfloat16* __restrict__ Bh, const __nv_bfloat16* __restrict__ Bl,
    float* __restrict__ C, int M, int Nn, int K)
{
    extern __shared__ char smem[];
    const uint32_t sb = smem_u32(smem);
    const int tid = threadIdx.x;
    const int lane = tid & 31;
    const int wid = tid >> 5;
    const int wm = wid & 1;
    const int wn = wid >> 1;
    const int bm0 = blockIdx.y * 128;
    const int bn0 = blockIdx.x * 128;

    float c[4][4][4];
#pragma unroll
    for (int mi = 0; mi < 4; mi++)
#pragma unroll
        for (int ni = 0; ni < 4; ni++)
#pragma unroll
            for (int k = 0; k < 4; k++) c[mi][ni][k] = 0.f;

    const int nc = K >> 5;

    gemm_cp_chunk(sb,          Ah, Al, Bh, Bl, bm0, bn0, K, Nn, 0,  tid);
    CP_COMMIT();
    gemm_cp_chunk(sb + GT_BUF, Ah, Al, Bh, Bl, bm0, bn0, K, Nn, 32, tid);
    CP_COMMIT();

    int buf = 0;
    for (int i = 0; i < nc; i++) {
        CP_WAIT1();
        __syncthreads();
        if (i + 2 < nc) {
            int nbuf = buf + 2; if (nbuf >= 3) nbuf -= 3;
            gemm_cp_chunk(sb + nbuf * GT_BUF, Ah, Al, Bh, Bl,
                          bm0, bn0, K, Nn, (i + 2) * 32, tid);
        }
        CP_COMMIT();
        gemm_compute(sb + buf * GT_BUF, wm, wn, lane, c);
        if (++buf == 3) buf = 0;
    }

    const int g = lane >> 2;
    const int t = lane & 3;
#pragma unroll
    for (int mi = 0; mi < 4; mi++) {
        const int row = bm0 + wm * 64 + mi * 16 + g;
#pragma unroll
        for (int ni = 0; ni < 4; ni++) {
            const int col = bn0 + wn * 32 + ni * 8 + 2 * t;
            if (col < Nn) {
                float2 v0 = make_float2(c[mi][ni][0], c[mi][ni][1]);
                float2 v1 = make_float2(c[mi][ni][2], c[mi][ni][3]);
                *(float2*)&C[(size_t)row * Nn + col] = v0;
                *(float2*)&C[(size_t)(row + 8) * Nn + col] = v1;
            }
        }
    }
}

// ---------------- bf16 hi/lo split ----------------
__global__ __launch_bounds__(256) void split_kernel(
    const float* __restrict__ x, __nv_bfloat16* __restrict__ h,
    __nv_bfloat16* __restrict__ l, int n4)
{
    int i = blockIdx.x * 256 + threadIdx.x;
    if (i >= n4) return;
    float4 v = ((const float4*)x)[i];
    __nv_bfloat16 h0 = __float2bfloat16(v.x), h1 = __float2bfloat16(v.y);
    __nv_bfloat16 h2 = __float2bfloat16(v.z), h3 = __float2bfloat16(v.w);
    __nv_bfloat16 l0 = __float2bfloat16(v.x - __bfloat162float(h0));
    __nv_bfloat16 l1 = __float2bfloat16(v.y - __bfloat162float(h1));
    __nv_bfloat16 l2 = __float2bfloat16(v.z - __bfloat162float(h2));
    __nv_bfloat16 l3 = __float2bfloat16(v.w - __bfloat162float(h3));
    ((__nv_bfloat162*)h)[i*2]   = __nv_bfloat162(h0, h1);
    ((__nv_bfloat162*)h)[i*2+1] = __nv_bfloat162(h2, h3);
    ((__nv_bfloat162*)l)[i*2]   = __nv_bfloat162(l0, l1);
    ((__nv_bfloat162*)l)[i*2+1] = __nv_bfloat162(l2, l3);
}

// ---------------- transpose + split ----------------
__global__ __launch_bounds__(256) void transpose_split_kernel(
    const float* __restrict__ W, __nv_bfloat16* __restrict__ th,
    __nv_bfloat16* __restrict__ tl, int K, int N)
{
    __shared__ float tile[32][33];
    const int bx = blockIdx.x * 32;
    const int by = blockIdx.y * 32;
    const int txi = threadIdx.x & 31;
    const int tyi = threadIdx.x >> 5;
#pragma unroll
    for (int j = 0; j < 32; j += 8) {
        int kk = by + tyi + j, nn = bx + txi;
        if (kk < K && nn < N) tile[tyi + j][txi] = W[(size_t)kk * N + nn];
    }
    __syncthreads();
#pragma unroll
    for (int j = 0; j < 32; j += 8) {
        int nn = bx + tyi + j, kk = by + txi;
        if (nn < N && kk < K) {
            float v = tile[txi][tyi + j];
            __nv_bfloat16 hi = __float2bfloat16(v);
            __nv_bfloat16 lo = __float2bfloat16(v - __bfloat162float(hi));
            th[(size_t)nn * K + kk] = hi;
            tl[(size_t)nn * K + kk] = lo;
        }
    }
}

// ---------------- RMSNorm ----------------
__global__ __launch_bounds__(256) void rmsnorm_kernel(
    const float* __restrict__ kvc, const float* __restrict__ w,
    float* __restrict__ lat)
{
    const int row = blockIdx.x;
    const float* x = kvc + (size_t)row * (KVR_ + ROPE_);
    const int tid = threadIdx.x;

    float v0 = x[tid];
    float v1 = x[tid + 256];
    float ss = v0 * v0 + v1 * v1;
#pragma unroll
    for (int off = 16; off; off >>= 1)
        ss += __shfl_xor_sync(0xffffffffu, ss, off);

    __shared__ float red[8];
    if ((tid & 31) == 0) red[tid >> 5] = ss;
    __syncthreads();
    float tot = 0.f;
#pragma unroll
    for (int i = 0; i < 8; i++) tot += red[i];

    float nrm = rsqrtf(tot * (1.f / 512.f) + 1e-6f);
    float* o = lat + (size_t)row * KVR_;
    o[tid]       = v0 * nrm * w[tid];
    o[tid + 256] = v1 * nrm * w[tid + 256];
}

// ---------------- RoPE ----------------
__global__ __launch_bounds__(256) void rope_q_kernel(float* __restrict__ q)
{
    int idx = blockIdx.x * 256 + threadIdx.x;
    if (idx >= BT_ * H_ * 32) return;
    int i  = idx & 31;
    int h  = (idx >> 5) & (H_ - 1);
    int bt = idx >> 9;
    int t  = bt & (T_ - 1);

    float inv = powf(10000.f, -(float)(2 * i) / 64.f);
    float f = (float)t * inv;
    float c = cosf(f), s = sinf(f);

    float* p = q + ((size_t)bt * H_ + h) * QKD_ + NOPE_;
    float x1 = p[i], x2 = p[i + 32];
    p[i]      = x1 * c - x2 * s;
    p[i + 32] = x2 * c + x1 * s;
}

__global__ __launch_bounds__(256) void rope_k_kernel(
    const float* __restrict__ kvc, float* __restrict__ krope)
{
    int idx = blockIdx.x * 256 + threadIdx.x;
    if (idx >= BT_ * 32) return;
    int i  = idx & 31;
    int bt = idx >> 5;
    int t  = bt & (T_ - 1);

    float inv = powf(10000.f, -(float)(2 * i) / 64.f);
    float f = (float)t * inv;
    float c = cosf(f), s = sinf(f);

    const float* p = kvc + (size_t)bt * (KVR_ + ROPE_) + KVR_;
    float x1 = p[i], x2 = p[i + 32];
    float* o = krope + (size_t)bt * ROPE_;
    o[i]      = x1 * c - x2 * s;
    o[i + 32] = x2 * c + x1 * s;
}

// ---------------- HMMA causal flash attention (unchanged from R7) ----------------
#define ABQ 128
#define ABK 64
#define AQ_PITCH 400
#define AK_PITCH 400
#define AV_PITCH 272
#define OFF_QH 0
#define OFF_QL 51200
#define OFF_KH 102400
#define OFF_KL 128000
#define OFF_VH 153600
#define OFF_VL 171008
#define ATTN_SMEM 188416

__device__ __forceinline__ float quadmax(float v) {
    v = fmaxf(v, __shfl_xor_sync(0xffffffffu, v, 1));
    v = fmaxf(v, __shfl_xor_sync(0xffffffffu, v, 2));
    return v;
}
__device__ __forceinline__ float quadsum(float v) {
    v += __shfl_xor_sync(0xffffffffu, v, 1);
    v += __shfl_xor_sync(0xffffffffu, v, 2);
    return v;
}

__global__ __launch_bounds__(256) void attn_mma_kernel(
    const float* __restrict__ q, const float* __restrict__ kvfull,
    const float* __restrict__ krope, float* __restrict__ y)
{
    extern __shared__ char smem[];
    const uint32_t sb = smem_u32(smem);
    const int b  = blockIdx.z;
    const int h  = blockIdx.y;
    const int qt = blockIdx.x;
    const int q0 = qt * ABQ;
    const int tid = threadIdx.x;
    const int lane = tid & 31;
    const int w = tid >> 5;
    const int g = lane >> 2;
    const int t = lane & 3;
    const float scale = 0.07216878364870322f;

#pragma unroll
    for (int l = 0; l < 24; l++) {
        int u = l * 256 + tid;
        int row = u / 48, c4 = u % 48, d = c4 * 4;
        float4 v = *(const float4*)&q[(((size_t)(b * T_ + q0 + row)) * H_ + h) * QKD_ + d];
        uint32_t ah = sb + OFF_QH + row * AQ_PITCH + d * 2;
        split_store8(ah, ah + (OFF_QL - OFF_QH), v);
    }

    float oc[16][4];
#pragma unroll
    for (int d = 0; d < 16; d++) { oc[d][0]=0.f; oc[d][1]=0.f; oc[d][2]=0.f; oc[d][3]=0.f; }
    float m0 = -CUDART_INF_F, m1 = -CUDART_INF_F, l0s = 0.f, l1s = 0.f;

    const int row0 = q0 + w * 16 + g;
    const int wrow_max = q0 + w * 16 + 15;

    const int nkt = 2 * qt + 2;
    for (int kt = 0; kt < nkt; kt++) {
        const int k0 = kt * ABK;
        __syncthreads();

#pragma unroll
        for (int l = 0; l < 12; l++) {
            int u = l * 256 + tid;
            int row = u / 48, c4 = u % 48, d = c4 * 4;
            size_t tok = (size_t)(b * T_ + k0 + row);
            float4 v;
            if (d < NOPE_) v = *(const float4*)&kvfull[(tok * H_ + h) * (NOPE_+VD_) + d];
            else           v = *(const float4*)&krope[tok * ROPE_ + (d - NOPE_)];
            uint32_t ah = sb + OFF_KH + row * AK_PITCH + d * 2;
            split_store8(ah, ah + (OFF_KL - OFF_KH), v);
        }
#pragma unroll
        for (int l = 0; l < 8; l++) {
            int u = l * 256 + tid;
            int row = u >> 5, c4 = u & 31, d = c4 * 4;
            size_t tok = (size_t)(b * T_ + k0 + row);
            float4 v = *(const float4*)&kvfull[(tok * H_ + h) * (NOPE_+VD_) + NOPE_ + d];
            uint32_t ah = sb + OFF_VH + row * AV_PITCH + d * 2;
            split_store8(ah, ah + (OFF_VL - OFF_VH), v);
        }
        __syncthreads();

        if (k0 > wrow_max) continue;

        float sc[8][4];
#pragma unroll
        for (int j = 0; j < 8; j++) { sc[j][0]=0.f; sc[j][1]=0.f; sc[j][2]=0.f; sc[j][3]=0.f; }

#pragma unroll
        for (int kb = 0; kb < 12; kb++) {
            uint32_t qa = sb + OFF_QH + (w * 16 + (lane & 15)) * AQ_PITCH
                        + (kb * 16 + (lane >> 4) * 8) * 2;
            uint32_t aqh[4], aql[4];
            ldsm_x4(aqh, qa);
            ldsm_x4(aql, qa + (OFF_QL - OFF_QH));
            uint32_t kh[8][2], kl[8][2];
#pragma unroll
            for (int nj = 0; nj < 4; nj++) {
                uint32_t ka = sb + OFF_KH
                            + (nj * 16 + ((lane >> 4) & 1) * 8 + (lane & 7)) * AK_PITCH
                            + (kb * 16 + ((lane >> 3) & 1) * 8) * 2;
                ldsm_x4(&kh[nj * 2][0], ka);
                ldsm_x4(&kl[nj * 2][0], ka + (OFF_KL - OFF_KH));
            }
#pragma unroll
            for (int j = 0; j < 8; j++) {
                mma16816(sc[j], aqh, kh[j]);
                mma16816(sc[j], aql, kh[j]);
                mma16816(sc[j], aqh, kl[j]);
            }
        }

        const bool need_mask = (k0 + ABK - 1 > q0 + w * 16);
#pragma unroll
        for (int j = 0; j < 8; j++) {
            int cbase = k0 + 8 * j + 2 * t;
#pragma unroll
            for (int e = 0; e < 4; e++) {
                int col = cbase + (e & 1);
                int row = (e < 2) ? row0 : row0 + 8;
                float v = sc[j][e] * scale;
                sc[j][e] = (need_mask && col > row) ? -CUDART_INF_F : v;
            }
        }

        float tm0 = -CUDART_INF_F, tm1 = -CUDART_INF_F;
#pragma unroll
        for (int j = 0; j < 8; j++) {
            tm0 = fmaxf(tm0, fmaxf(sc[j][0], sc[j][1]));
            tm1 = fmaxf(tm1, fmaxf(sc[j][2], sc[j][3]));
        }
        tm0 = quadmax(tm0); tm1 = quadmax(tm1);
        float mn0 = fmaxf(m0, tm0), mn1 = fmaxf(m1, tm1);
        float corr0 = __expf(m0 - mn0), corr1 = __expf(m1 - mn1);
        float rs0 = 0.f, rs1 = 0.f;
#pragma unroll
        for (int j = 0; j < 8; j++) {
            sc[j][0] = __expf(sc[j][0] - mn0);
            sc[j][1] = __expf(sc[j][1] - mn0);
            sc[j][2] = __expf(sc[j][2] - mn1);
            sc[j][3] = __expf(sc[j][3] - mn1);
            rs0 += sc[j][0] + sc[j][1];
            rs1 += sc[j][2] + sc[j][3];
        }
        rs0 = quadsum(rs0); rs1 = quadsum(rs1);
        l0s = l0s * corr0 + rs0;
        l1s = l1s * corr1 + rs1;
        m0 = mn0; m1 = mn1;
#pragma unroll
        for (int d = 0; d < 16; d++) {
            oc[d][0] *= corr0; oc[d][1] *= corr0;
            oc[d][2] *= corr1; oc[d][3] *= corr1;
        }

#pragma unroll
        for (int kb2 = 0; kb2 < 4; kb2++) {
            uint32_t pah[4], pal[4];
#pragma unroll
            for (int half = 0; half < 2; half++) {
                int j = 2 * kb2 + half;
                uint32_t ph0 = pack_bf16x2(sc[j][0], sc[j][1]);
                uint32_t ph1 = pack_bf16x2(sc[j][2], sc[j][3]);
                float lo0 = sc[j][0] - __uint_as_float(ph0 << 16);
                float lo1 = sc[j][1] - __uint_as_float(ph0 & 0xffff0000u);
                float lo2 = sc[j][2] - __uint_as_float(ph1 << 16);
                float lo3 = sc[j][3] - __uint_as_float(ph1 & 0xffff0000u);
                pah[half * 2 + 0] = ph0;
                pah[half * 2 + 1] = ph1;
                pal[half * 2 + 0] = pack_bf16x2(lo0, lo1);
                pal[half * 2 + 1] = pack_bf16x2(lo2, lo3);
            }
#pragma unroll
            for (int dp = 0; dp < 8; dp++) {
                uint32_t vh[4], vl[4];
                uint32_t va = sb + OFF_VH
                            + (kb2 * 16 + (lane & 7) + ((lane >> 3) & 1) * 8) * AV_PITCH
                            + (dp * 16 + (lane >> 4) * 8) * 2;
                ldsm_x4_trans(vh, va);
                ldsm_x4_trans(vl, va + (OFF_VL - OFF_VH));
                mma16816(oc[dp * 2],     pah, &vh[0]);
                mma16816(oc[dp * 2],     pal, &vh[0]);
                mma16816(oc[dp * 2],     pah, &vl[0]);
                mma16816(oc[dp * 2 + 1], pah, &vh[2]);
                mma16816(oc[dp * 2 + 1], pal, &vh[2]);
                mma16816(oc[dp * 2 + 1], pah, &vl[2]);
            }
        }
    }

    float inv0 = 1.f / l0s, inv1 = 1.f / l1s;
#pragma unroll
    for (int d = 0; d < 16; d++) {
        int col = d * 8 + 2 * t;
        size_t base0 = (((size_t)(b * T_ + row0)) * H_ + h) * VD_ + col;
        size_t base1 = (((size_t)(b * T_ + row0 + 8)) * H_ + h) * VD_ + col;
        *(float2*)&y[base0] = make_float2(oc[d][0] * inv0, oc[d][1] * inv0);
        *(float2*)&y[base1] = make_float2(oc[d][2] * inv1, oc[d][3] * inv1);
    }
}

// ---------------- launch ----------------
extern "C" void kernel_launch(void* const* d_in, const int* in_sizes, int n_in,
                              void* d_out, int out_size)
{
    const float* x      = (const float*)d_in[0];
    const float* wq     = (const float*)d_in[1];
    const float* wkv_a  = (const float*)d_in[2];
    const float* wkv_b  = (const float*)d_in[3];
    const float* wo     = (const float*)d_in[4];
    const float* kvw    = (const float*)d_in[5];
    float* out = (float*)d_out;

    float *qp, *kvcp, *latp, *kvfp, *krp, *yp;
    cudaGetSymbolAddress((void**)&qp,   g_q);
    cudaGetSymbolAddress((void**)&kvcp, g_kvc);
    cudaGetSymbolAddress((void**)&latp, g_lat);
    cudaGetSymbolAddress((void**)&kvfp, g_kvfull);
    cudaGetSymbolAddress((void**)&krp,  g_krope);
    cudaGetSymbolAddress((void**)&yp,   g_y);

    __nv_bfloat16 *xh, *xl, *lath, *latl, *yh, *yl;
    __nv_bfloat16 *wqth, *wqtl, *wath, *watl, *wbth, *wbtl, *woth, *wotl;
    cudaGetSymbolAddress((void**)&xh,   g_xh);
    cudaGetSymbolAddress((void**)&xl,   g_xl);
    cudaGetSymbolAddress((void**)&lath, g_lath);
    cudaGetSymbolAddress((void**)&latl, g_latl);
    cudaGetSymbolAddress((void**)&yh,   g_yh);
    cudaGetSymbolAddress((void**)&yl,   g_yl);
    cudaGetSymbolAddress((void**)&wqth, g_wqt_h);
    cudaGetSymbolAddress((void**)&wqtl, g_wqt_l);
    cudaGetSymbolAddress((void**)&wath, g_wat_h);
    cudaGetSymbolAddress((void**)&watl, g_wat_l);
    cudaGetSymbolAddress((void**)&wbth, g_wbt_h);
    cudaGetSymbolAddress((void**)&wbtl, g_wbt_l);
    cudaGetSymbolAddress((void**)&woth, g_wot_h);
    cudaGetSymbolAddress((void**)&wotl, g_wot_l);

    cudaFuncSetAttribute(gemm_mma, cudaFuncAttributeMaxDynamicSharedMemorySize, GM_SMEM);
    cudaFuncSetAttribute(attn_mma_kernel, cudaFuncAttributeMaxDynamicSharedMemorySize, ATTN_SMEM);

    // ---- prep ----
    split_kernel<<<(BT_*D_/4 + 255)/256, 256>>>(x, xh, xl, BT_*D_/4);
    transpose_split_kernel<<<dim3((H_*QKD_)/32, D_/32), 256>>>(wq, wqth, wqtl, D_, H_*QKD_);
    transpose_split_kernel<<<dim3((KVR_+ROPE_)/32, D_/32), 256>>>(wkv_a, wath, watl, D_, KVR_+ROPE_);
    transpose_split_kernel<<<dim3((H_*(NOPE_+VD_))/32, KVR_/32), 256>>>(wkv_b, wbth, wbtl, KVR_, H_*(NOPE_+VD_));
    transpose_split_kernel<<<dim3(D_/32, (H_*VD_)/32), 256>>>(wo, woth, wotl, H_*VD_, D_);

    // ---- GEMMs + elementwise ----
    gemm_mma<<<dim3(3072/128, BT_/128), 256, GM_SMEM>>>(xh, xl, wqth, wqtl, qp, BT_, H_*QKD_, D_);
    gemm_mma<<<dim3((KVR_+ROPE_+127)/128, BT_/128), 256, GM_SMEM>>>(xh, xl, wath, watl, kvcp, BT_, KVR_+ROPE_, D_);
    rmsnorm_kernel<<<BT_, 256>>>(kvcp, kvw, latp);
    rope_q_kernel<<<(BT_*H_*32)/256, 256>>>(qp);
    rope_k_kernel<<<(BT_*32)/256, 256>>>(kvcp, krp);
    split_kernel<<<(BT_*KVR_/4 + 255)/256, 256>>>(latp, lath, latl, BT_*KVR_/4);
    gemm_mma<<<dim3(4096/128, BT_/128), 256, GM_SMEM>>>(lath, latl, wbth, wbtl, kvfp, BT_, H_*(NOPE_+VD_), KVR_);
    attn_mma_kernel<<<dim3(T_/ABQ, H_, B_), 256, ATTN_SMEM>>>(qp, kvfp, krp, yp);
    split_kernel<<<(BT_*H_*VD_/4 + 255)/256, 256>>>(yp, yh, yl, BT_*H_*VD_/4);
    gemm_mma<<<dim3(D_/128, BT_/128), 256, GM_SMEM>>>(yh, yl, woth, wotl, out, BT_, D_, H_*VD_);
}

// round 9
// speedup vs baseline: 3.1642x; 1.0896x over previous
#include <cuda_runtime.h>
#include <cuda_bf16.h>
#include <math.h>
#include <math_constants.h>
#include <cstdint>

// ---------------- problem constants ----------------
#define H_     16
#define NOPE_  128
#define ROPE_  64
#define VD_    128
#define KVR_   512
#define QKD_   192        // NOPE+ROPE
#define B_     2
#define T_     2048
#define D_     2048
#define BT_    (B_*T_)    // 4096

// ---------------- scratch (device globals; no cudaMalloc allowed) ----------------
__device__ float g_q[(size_t)BT_ * H_ * QKD_];
__device__ float g_kvc[(size_t)BT_ * (KVR_ + ROPE_)];
__device__ float g_lat[(size_t)BT_ * KVR_];
__device__ float g_kvfull[(size_t)BT_ * H_ * (NOPE_+VD_)];
__device__ float g_krope[(size_t)BT_ * ROPE_];
__device__ float g_y[(size_t)BT_ * H_ * VD_];

__device__ __nv_bfloat16 g_xh[(size_t)BT_ * D_];
__device__ __nv_bfloat16 g_xl[(size_t)BT_ * D_];
__device__ __nv_bfloat16 g_lath[(size_t)BT_ * KVR_];
__device__ __nv_bfloat16 g_latl[(size_t)BT_ * KVR_];
__device__ __nv_bfloat16 g_yh[(size_t)BT_ * H_ * VD_];
__device__ __nv_bfloat16 g_yl[(size_t)BT_ * H_ * VD_];
__device__ __nv_bfloat16 g_wqt_h[(size_t)(H_*QKD_) * D_];
__device__ __nv_bfloat16 g_wqt_l[(size_t)(H_*QKD_) * D_];
__device__ __nv_bfloat16 g_wat_h[(size_t)(KVR_+ROPE_) * D_];
__device__ __nv_bfloat16 g_wat_l[(size_t)(KVR_+ROPE_) * D_];
__device__ __nv_bfloat16 g_wbt_h[(size_t)(H_*(NOPE_+VD_)) * KVR_];
__device__ __nv_bfloat16 g_wbt_l[(size_t)(H_*(NOPE_+VD_)) * KVR_];
__device__ __nv_bfloat16 g_wot_h[(size_t)D_ * (H_*VD_)];
__device__ __nv_bfloat16 g_wot_l[(size_t)D_ * (H_*VD_)];

// ---------------- helpers ----------------
__device__ __forceinline__ uint32_t smem_u32(const void* p) {
    uint32_t a;
    asm("{ .reg .u64 t; cvta.to.shared.u64 t, %1; cvt.u32.u64 %0, t; }" : "=r"(a) : "l"(p));
    return a;
}

__device__ __forceinline__ void ldsm_x4(uint32_t* r, uint32_t addr) {
    asm volatile("ldmatrix.sync.aligned.m8n8.x4.shared.b16 {%0,%1,%2,%3}, [%4];"
                 : "=r"(r[0]), "=r"(r[1]), "=r"(r[2]), "=r"(r[3]) : "r"(addr));
}
__device__ __forceinline__ void ldsm_x4_trans(uint32_t* r, uint32_t addr) {
    asm volatile("ldmatrix.sync.aligned.m8n8.x4.trans.shared.b16 {%0,%1,%2,%3}, [%4];"
                 : "=r"(r[0]), "=r"(r[1]), "=r"(r[2]), "=r"(r[3]) : "r"(addr));
}

__device__ __forceinline__ void mma16816(float* c, const uint32_t* a, const uint32_t* b) {
    asm volatile(
        "mma.sync.aligned.m16n8k16.row.col.f32.bf16.bf16.f32 "
        "{%0,%1,%2,%3}, {%4,%5,%6,%7}, {%8,%9}, {%0,%1,%2,%3};"
        : "+f"(c[0]), "+f"(c[1]), "+f"(c[2]), "+f"(c[3])
        : "r"(a[0]), "r"(a[1]), "r"(a[2]), "r"(a[3]), "r"(b[0]), "r"(b[1]));
}

__device__ __forceinline__ uint32_t pack_bf16x2(float lo, float hi) {
    uint32_t d;
    asm("cvt.rn.bf16x2.f32 %0, %1, %2;" : "=r"(d) : "f"(hi), "f"(lo));
    return d;
}

__device__ __forceinline__ void split_store8(uint32_t addr_h, uint32_t addr_l, float4 v) {
    uint32_t h0 = pack_bf16x2(v.x, v.y);
    uint32_t h1 = pack_bf16x2(v.z, v.w);
    float l0 = v.x - __uint_as_float(h0 << 16);
    float l1 = v.y - __uint_as_float(h0 & 0xffff0000u);
    float l2 = v.z - __uint_as_float(h1 << 16);
    float l3 = v.w - __uint_as_float(h1 & 0xffff0000u);
    uint32_t p0 = pack_bf16x2(l0, l1);
    uint32_t p1 = pack_bf16x2(l2, l3);
    asm volatile("st.shared.v2.b32 [%0], {%1,%2};" :: "r"(addr_h), "r"(h0), "r"(h1) : "memory");
    asm volatile("st.shared.v2.b32 [%0], {%1,%2};" :: "r"(addr_l), "r"(p0), "r"(p1) : "memory");
}

// cp.async 16B with predicated src-size (0 => zero-fill)
__device__ __forceinline__ void cp16(uint32_t dst, const void* src, bool pred) {
    int sz = pred ? 16 : 0;
    asm volatile("cp.async.cg.shared.global [%0], [%1], 16, %2;"
                 :: "r"(dst), "l"(src), "r"(sz) : "memory");
}
#define CP_COMMIT() asm volatile("cp.async.commit_group;" ::: "memory")
#define CP_WAIT0()  asm volatile("cp.async.wait_group 0;" ::: "memory")

// ---------------- HMMA GEMM: 2-stage cp.async, 2 CTAs/SM ----------------
#define GT_PITCHB 80
#define GT_TILE   10240
#define GT_BUF    40960
#define GM_SMEM   (2 * GT_BUF)   // 80 KB -> 2 CTAs/SM

__device__ __forceinline__ void gemm_cp_chunk(
    uint32_t sbase, const __nv_bfloat16* Ah, const __nv_bfloat16* Al,
    const __nv_bfloat16* Bh, const __nv_bfloat16* Bl,
    int bm0, int bn0, int K, int Nn, int k0, int tid)
{
#pragma unroll
    for (int l = 0; l < 8; l++) {
        const int u = l * 256 + tid;      // 0..2047
        const int tile = u >> 9;          // 0..3
        const int r = (u >> 2) & 127;
        const int c4 = u & 3;
        const uint32_t dst = sbase + tile * GT_TILE + r * GT_PITCHB + c4 * 16;
        const __nv_bfloat16* src;
        int row;
        bool ok = true;
        if (tile == 0)      { src = Ah; row = bm0 + r; }
        else if (tile == 1) { src = Al; row = bm0 + r; }
        else {
            src = (tile == 2) ? Bh : Bl;
            row = bn0 + r;
            ok = (row < Nn);
            if (!ok) row = Nn - 1;
        }
        cp16(dst, src + (size_t)row * K + k0 + c4 * 8, ok);
    }
}

__device__ __forceinline__ void gemm_compute(
    uint32_t sbase, int wm, int wn, int lane, float c[4][4][4])
{
#pragma unroll
    for (int ks = 0; ks < 32; ks += 16) {
        uint32_t Bhf[4][2], Blf[4][2];
#pragma unroll
        for (int nj = 0; nj < 2; nj++) {
            const int nrow = wn * 32 + nj * 16 + ((lane >> 4) & 1) * 8 + (lane & 7);
            const uint32_t b = sbase + 2 * GT_TILE + nrow * GT_PITCHB
                             + (ks + ((lane >> 3) & 1) * 8) * 2;
            ldsm_x4(&Bhf[nj * 2][0], b);
            ldsm_x4(&Blf[nj * 2][0], b + GT_TILE);
        }
#pragma unroll
        for (int mi = 0; mi < 4; mi++) {
            uint32_t ah[4], al[4];
            const int row = wm * 64 + mi * 16 + (lane & 15);
            const uint32_t a = sbase + row * GT_PITCHB + (ks + (lane >> 4) * 8) * 2;
            ldsm_x4(ah, a);
            ldsm_x4(al, a + GT_TILE);
#pragma unroll
            for (int ni = 0; ni < 4; ni++) {
                mma16816(c[mi][ni], ah, Bhf[ni]);
                mma16816(c[mi][ni], al, Bhf[ni]);
                mma16816(c[mi][ni], ah, Blf[ni]);
            }
        }
    }
}

__global__ void __launch_bounds__(256, 2) gemm_mma(
    const __nv_bfloat16* __restrict__ Ah, const __nv_bfloat16* __restrict__ Al,
    const __nv_bfloat16* __restrict__ Bh, const __nv_bfloat16* __restrict__ Bl,
    float* __restrict__ C, int M, int Nn, int K)
{
    extern __shared__ char smem[];
    const uint32_t sb = smem_u32(smem);
    const int tid = threadIdx.x;
    const int lane = tid & 31;
    const int wid = tid >> 5;
    const int wm = wid & 1;
    const int wn = wid >> 1;
    const int bm0 = blockIdx.y * 128;
    const int bn0 = blockIdx.x * 128;

    float c[4][4][4];
#pragma unroll
    for (int mi = 0; mi < 4; mi++)
#pragma unroll
        for (int ni = 0; ni < 4; ni++)
#pragma unroll
            for (int k = 0; k < 4; k++) c[mi][ni][k] = 0.f;

    const int nc = K >> 5;

    gemm_cp_chunk(sb, Ah, Al, Bh, Bl, bm0, bn0, K, Nn, 0, tid);
    CP_COMMIT();

    for (int i = 0; i < nc; i++) {
        CP_WAIT0();            // chunk i resident
        __syncthreads();       // visible CTA-wide; all warps done with compute(i-1)
        if (i + 1 < nc) {
            gemm_cp_chunk(sb + ((i + 1) & 1) * GT_BUF, Ah, Al, Bh, Bl,
                          bm0, bn0, K, Nn, (i + 1) * 32, tid);
            CP_COMMIT();
        }
        gemm_compute(sb + (i & 1) * GT_BUF, wm, wn, lane, c);
    }

    const int g = lane >> 2;
    const int t = lane & 3;
#pragma unroll
    for (int mi = 0; mi < 4; mi++) {
        const int row = bm0 + wm * 64 + mi * 16 + g;
#pragma unroll
        for (int ni = 0; ni < 4; ni++) {
            const int col = bn0 + wn * 32 + ni * 8 + 2 * t;
            if (col < Nn) {
                float2 v0 = make_float2(c[mi][ni][0], c[mi][ni][1]);
                float2 v1 = make_float2(c[mi][ni][2], c[mi][ni][3]);
                *(float2*)&C[(size_t)row * Nn + col] = v0;
                *(float2*)&C[(size_t)(row + 8) * Nn + col] = v1;
            }
        }
    }
}

// ---------------- bf16 hi/lo split ----------------
__global__ __launch_bounds__(256) void split_kernel(
    const float* __restrict__ x, __nv_bfloat16* __restrict__ h,
    __nv_bfloat16* __restrict__ l, int n4)
{
    int i = blockIdx.x * 256 + threadIdx.x;
    if (i >= n4) return;
    float4 v = ((const float4*)x)[i];
    __nv_bfloat16 h0 = __float2bfloat16(v.x), h1 = __float2bfloat16(v.y);
    __nv_bfloat16 h2 = __float2bfloat16(v.z), h3 = __float2bfloat16(v.w);
    __nv_bfloat16 l0 = __float2bfloat16(v.x - __bfloat162float(h0));
    __nv_bfloat16 l1 = __float2bfloat16(v.y - __bfloat162float(h1));
    __nv_bfloat16 l2 = __float2bfloat16(v.z - __bfloat162float(h2));
    __nv_bfloat16 l3 = __float2bfloat16(v.w - __bfloat162float(h3));
    ((__nv_bfloat162*)h)[i*2]   = __nv_bfloat162(h0, h1);
    ((__nv_bfloat162*)h)[i*2+1] = __nv_bfloat162(h2, h3);
    ((__nv_bfloat162*)l)[i*2]   = __nv_bfloat162(l0, l1);
    ((__nv_bfloat162*)l)[i*2+1] = __nv_bfloat162(l2, l3);
}

// ---------------- transpose + split ----------------
__global__ __launch_bounds__(256) void transpose_split_kernel(
    const float* __restrict__ W, __nv_bfloat16* __restrict__ th,
    __nv_bfloat16* __restrict__ tl, int K, int N)
{
    __shared__ float tile[32][33];
    const int bx = blockIdx.x * 32;
    const int by = blockIdx.y * 32;
    const int txi = threadIdx.x & 31;
    const int tyi = threadIdx.x >> 5;
#pragma unroll
    for (int j = 0; j < 32; j += 8) {
        int kk = by + tyi + j, nn = bx + txi;
        if (kk < K && nn < N) tile[tyi + j][txi] = W[(size_t)kk * N + nn];
    }
    __syncthreads();
#pragma unroll
    for (int j = 0; j < 32; j += 8) {
        int nn = bx + tyi + j, kk = by + txi;
        if (nn < N && kk < K) {
            float v = tile[txi][tyi + j];
            __nv_bfloat16 hi = __float2bfloat16(v);
            __nv_bfloat16 lo = __float2bfloat16(v - __bfloat162float(hi));
            th[(size_t)nn * K + kk] = hi;
            tl[(size_t)nn * K + kk] = lo;
        }
    }
}

// ---------------- RMSNorm ----------------
__global__ __launch_bounds__(256) void rmsnorm_kernel(
    const float* __restrict__ kvc, const float* __restrict__ w,
    float* __restrict__ lat)
{
    const int row = blockIdx.x;
    const float* x = kvc + (size_t)row * (KVR_ + ROPE_);
    const int tid = threadIdx.x;

    float v0 = x[tid];
    float v1 = x[tid + 256];
    float ss = v0 * v0 + v1 * v1;
#pragma unroll
    for (int off = 16; off; off >>= 1)
        ss += __shfl_xor_sync(0xffffffffu, ss, off);

    __shared__ float red[8];
    if ((tid & 31) == 0) red[tid >> 5] = ss;
    __syncthreads();
    float tot = 0.f;
#pragma unroll
    for (int i = 0; i < 8; i++) tot += red[i];

    float nrm = rsqrtf(tot * (1.f / 512.f) + 1e-6f);
    float* o = lat + (size_t)row * KVR_;
    o[tid]       = v0 * nrm * w[tid];
    o[tid + 256] = v1 * nrm * w[tid + 256];
}

// ---------------- RoPE ----------------
__global__ __launch_bounds__(256) void rope_q_kernel(float* __restrict__ q)
{
    int idx = blockIdx.x * 256 + threadIdx.x;
    if (idx >= BT_ * H_ * 32) return;
    int i  = idx & 31;
    int h  = (idx >> 5) & (H_ - 1);
    int bt = idx >> 9;
    int t  = bt & (T_ - 1);

    float inv = powf(10000.f, -(float)(2 * i) / 64.f);
    float f = (float)t * inv;
    float c = cosf(f), s = sinf(f);

    float* p = q + ((size_t)bt * H_ + h) * QKD_ + NOPE_;
    float x1 = p[i], x2 = p[i + 32];
    p[i]      = x1 * c - x2 * s;
    p[i + 32] = x2 * c + x1 * s;
}

__global__ __launch_bounds__(256) void rope_k_kernel(
    const float* __restrict__ kvc, float* __restrict__ krope)
{
    int idx = blockIdx.x * 256 + threadIdx.x;
    if (idx >= BT_ * 32) return;
    int i  = idx & 31;
    int bt = idx >> 5;
    int t  = bt & (T_ - 1);

    float inv = powf(10000.f, -(float)(2 * i) / 64.f);
    float f = (float)t * inv;
    float c = cosf(f), s = sinf(f);

    const float* p = kvc + (size_t)bt * (KVR_ + ROPE_) + KVR_;
    float x1 = p[i], x2 = p[i + 32];
    float* o = krope + (size_t)bt * ROPE_;
    o[i]      = x1 * c - x2 * s;
    o[i + 32] = x2 * c + x1 * s;
}

// ---------------- HMMA causal flash attention (unchanged) ----------------
#define ABQ 128
#define ABK 64
#define AQ_PITCH 400
#define AK_PITCH 400
#define AV_PITCH 272
#define OFF_QH 0
#define OFF_QL 51200
#define OFF_KH 102400
#define OFF_KL 128000
#define OFF_VH 153600
#define OFF_VL 171008
#define ATTN_SMEM 188416

__device__ __forceinline__ float quadmax(float v) {
    v = fmaxf(v, __shfl_xor_sync(0xffffffffu, v, 1));
    v = fmaxf(v, __shfl_xor_sync(0xffffffffu, v, 2));
    return v;
}
__device__ __forceinline__ float quadsum(float v) {
    v += __shfl_xor_sync(0xffffffffu, v, 1);
    v += __shfl_xor_sync(0xffffffffu, v, 2);
    return v;
}

__global__ __launch_bounds__(256) void attn_mma_kernel(
    const float* __restrict__ q, const float* __restrict__ kvfull,
    const float* __restrict__ krope, float* __restrict__ y)
{
    extern __shared__ char smem[];
    const uint32_t sb = smem_u32(smem);
    const int b  = blockIdx.z;
    const int h  = blockIdx.y;
    const int qt = blockIdx.x;
    const int q0 = qt * ABQ;
    const int tid = threadIdx.x;
    const int lane = tid & 31;
    const int w = tid >> 5;
    const int g = lane >> 2;
    const int t = lane & 3;
    const float scale = 0.07216878364870322f;

#pragma unroll
    for (int l = 0; l < 24; l++) {
        int u = l * 256 + tid;
        int row = u / 48, c4 = u % 48, d = c4 * 4;
        float4 v = *(const float4*)&q[(((size_t)(b * T_ + q0 + row)) * H_ + h) * QKD_ + d];
        uint32_t ah = sb + OFF_QH + row * AQ_PITCH + d * 2;
        split_store8(ah, ah + (OFF_QL - OFF_QH), v);
    }

    float oc[16][4];
#pragma unroll
    for (int d = 0; d < 16; d++) { oc[d][0]=0.f; oc[d][1]=0.f; oc[d][2]=0.f; oc[d][3]=0.f; }
    float m0 = -CUDART_INF_F, m1 = -CUDART_INF_F, l0s = 0.f, l1s = 0.f;

    const int row0 = q0 + w * 16 + g;
    const int wrow_max = q0 + w * 16 + 15;

    const int nkt = 2 * qt + 2;
    for (int kt = 0; kt < nkt; kt++) {
        const int k0 = kt * ABK;
        __syncthreads();

#pragma unroll
        for (int l = 0; l < 12; l++) {
            int u = l * 256 + tid;
            int row = u / 48, c4 = u % 48, d = c4 * 4;
            size_t tok = (size_t)(b * T_ + k0 + row);
            float4 v;
            if (d < NOPE_) v = *(const float4*)&kvfull[(tok * H_ + h) * (NOPE_+VD_) + d];
            else           v = *(const float4*)&krope[tok * ROPE_ + (d - NOPE_)];
            uint32_t ah = sb + OFF_KH + row * AK_PITCH + d * 2;
            split_store8(ah, ah + (OFF_KL - OFF_KH), v);
        }
#pragma unroll
        for (int l = 0; l < 8; l++) {
            int u = l * 256 + tid;
            int row = u >> 5, c4 = u & 31, d = c4 * 4;
            size_t tok = (size_t)(b * T_ + k0 + row);
            float4 v = *(const float4*)&kvfull[(tok * H_ + h) * (NOPE_+VD_) + NOPE_ + d];
            uint32_t ah = sb + OFF_VH + row * AV_PITCH + d * 2;
            split_store8(ah, ah + (OFF_VL - OFF_VH), v);
        }
        __syncthreads();

        if (k0 > wrow_max) continue;

        float sc[8][4];
#pragma unroll
        for (int j = 0; j < 8; j++) { sc[j][0]=0.f; sc[j][1]=0.f; sc[j][2]=0.f; sc[j][3]=0.f; }

#pragma unroll
        for (int kb = 0; kb < 12; kb++) {
            uint32_t qa = sb + OFF_QH + (w * 16 + (lane & 15)) * AQ_PITCH
                        + (kb * 16 + (lane >> 4) * 8) * 2;
            uint32_t aqh[4], aql[4];
            ldsm_x4(aqh, qa);
            ldsm_x4(aql, qa + (OFF_QL - OFF_QH));
            uint32_t kh[8][2], kl[8][2];
#pragma unroll
            for (int nj = 0; nj < 4; nj++) {
                uint32_t ka = sb + OFF_KH
                            + (nj * 16 + ((lane >> 4) & 1) * 8 + (lane & 7)) * AK_PITCH
                            + (kb * 16 + ((lane >> 3) & 1) * 8) * 2;
                ldsm_x4(&kh[nj * 2][0], ka);
                ldsm_x4(&kl[nj * 2][0], ka + (OFF_KL - OFF_KH));
            }
#pragma unroll
            for (int j = 0; j < 8; j++) {
                mma16816(sc[j], aqh, kh[j]);
                mma16816(sc[j], aql, kh[j]);
                mma16816(sc[j], aqh, kl[j]);
            }
        }

        const bool need_mask = (k0 + ABK - 1 > q0 + w * 16);
#pragma unroll
        for (int j = 0; j < 8; j++) {
            int cbase = k0 + 8 * j + 2 * t;
#pragma unroll
            for (int e = 0; e < 4; e++) {
                int col = cbase + (e & 1);
                int row = (e < 2) ? row0 : row0 + 8;
                float v = sc[j][e] * scale;
                sc[j][e] = (need_mask && col > row) ? -CUDART_INF_F : v;
            }
        }

        float tm0 = -CUDART_INF_F, tm1 = -CUDART_INF_F;
#pragma unroll
        for (int j = 0; j < 8; j++) {
            tm0 = fmaxf(tm0, fmaxf(sc[j][0], sc[j][1]));
            tm1 = fmaxf(tm1, fmaxf(sc[j][2], sc[j][3]));
        }
        tm0 = quadmax(tm0); tm1 = quadmax(tm1);
        float mn0 = fmaxf(m0, tm0), mn1 = fmaxf(m1, tm1);
        float corr0 = __expf(m0 - mn0), corr1 = __expf(m1 - mn1);
        float rs0 = 0.f, rs1 = 0.f;
#pragma unroll
        for (int j = 0; j < 8; j++) {
            sc[j][0] = __expf(sc[j][0] - mn0);
            sc[j][1] = __expf(sc[j][1] - mn0);
            sc[j][2] = __expf(sc[j][2] - mn1);
            sc[j][3] = __expf(sc[j][3] - mn1);
            rs0 += sc[j][0] + sc[j][1];
            rs1 += sc[j][2] + sc[j][3];
        }
        rs0 = quadsum(rs0); rs1 = quadsum(rs1);
        l0s = l0s * corr0 + rs0;
        l1s = l1s * corr1 + rs1;
        m0 = mn0; m1 = mn1;
#pragma unroll
        for (int d = 0; d < 16; d++) {
            oc[d][0] *= corr0; oc[d][1] *= corr0;
            oc[d][2] *= corr1; oc[d][3] *= corr1;
        }

#pragma unroll
        for (int kb2 = 0; kb2 < 4; kb2++) {
            uint32_t pah[4], pal[4];
#pragma unroll
            for (int half = 0; half < 2; half++) {
                int j = 2 * kb2 + half;
                uint32_t ph0 = pack_bf16x2(sc[j][0], sc[j][1]);
                uint32_t ph1 = pack_bf16x2(sc[j][2], sc[j][3]);
                float lo0 = sc[j][0] - __uint_as_float(ph0 << 16);
                float lo1 = sc[j][1] - __uint_as_float(ph0 & 0xffff0000u);
                float lo2 = sc[j][2] - __uint_as_float(ph1 << 16);
                float lo3 = sc[j][3] - __uint_as_float(ph1 & 0xffff0000u);
                pah[half * 2 + 0] = ph0;
                pah[half * 2 + 1] = ph1;
                pal[half * 2 + 0] = pack_bf16x2(lo0, lo1);
                pal[half * 2 + 1] = pack_bf16x2(lo2, lo3);
            }
#pragma unroll
            for (int dp = 0; dp < 8; dp++) {
                uint32_t vh[4], vl[4];
                uint32_t va = sb + OFF_VH
                            + (kb2 * 16 + (lane & 7) + ((lane >> 3) & 1) * 8) * AV_PITCH
                            + (dp * 16 + (lane >> 4) * 8) * 2;
                ldsm_x4_trans(vh, va);
                ldsm_x4_trans(vl, va + (OFF_VL - OFF_VH));
                mma16816(oc[dp * 2],     pah, &vh[0]);
                mma16816(oc[dp * 2],     pal, &vh[0]);
                mma16816(oc[dp * 2],     pah, &vl[0]);
                mma16816(oc[dp * 2 + 1], pah, &vh[2]);
                mma16816(oc[dp * 2 + 1], pal, &vh[2]);
                mma16816(oc[dp * 2 + 1], pah, &vl[2]);
            }
        }
    }

    float inv0 = 1.f / l0s, inv1 = 1.f / l1s;
#pragma unroll
    for (int d = 0; d < 16; d++) {
        int col = d * 8 + 2 * t;
        size_t base0 = (((size_t)(b * T_ + row0)) * H_ + h) * VD_ + col;
        size_t base1 = (((size_t)(b * T_ + row0 + 8)) * H_ + h) * VD_ + col;
        *(float2*)&y[base0] = make_float2(oc[d][0] * inv0, oc[d][1] * inv0);
        *(float2*)&y[base1] = make_float2(oc[d][2] * inv1, oc[d][3] * inv1);
    }
}

// ---------------- launch ----------------
extern "C" void kernel_launch(void* const* d_in, const int* in_sizes, int n_in,
                              void* d_out, int out_size)
{
    const float* x      = (const float*)d_in[0];
    const float* wq     = (const float*)d_in[1];
    const float* wkv_a  = (const float*)d_in[2];
    const float* wkv_b  = (const float*)d_in[3];
    const float* wo     = (const float*)d_in[4];
    const float* kvw    = (const float*)d_in[5];
    float* out = (float*)d_out;

    float *qp, *kvcp, *latp, *kvfp, *krp, *yp;
    cudaGetSymbolAddress((void**)&qp,   g_q);
    cudaGetSymbolAddress((void**)&kvcp, g_kvc);
    cudaGetSymbolAddress((void**)&latp, g_lat);
    cudaGetSymbolAddress((void**)&kvfp, g_kvfull);
    cudaGetSymbolAddress((void**)&krp,  g_krope);
    cudaGetSymbolAddress((void**)&yp,   g_y);

    __nv_bfloat16 *xh, *xl, *lath, *latl, *yh, *yl;
    __nv_bfloat16 *wqth, *wqtl, *wath, *watl, *wbth, *wbtl, *woth, *wotl;
    cudaGetSymbolAddress((void**)&xh,   g_xh);
    cudaGetSymbolAddress((void**)&xl,   g_xl);
    cudaGetSymbolAddress((void**)&lath, g_lath);
    cudaGetSymbolAddress((void**)&latl, g_latl);
    cudaGetSymbolAddress((void**)&yh,   g_yh);
    cudaGetSymbolAddress((void**)&yl,   g_yl);
    cudaGetSymbolAddress((void**)&wqth, g_wqt_h);
    cudaGetSymbolAddress((void**)&wqtl, g_wqt_l);
    cudaGetSymbolAddress((void**)&wath, g_wat_h);
    cudaGetSymbolAddress((void**)&watl, g_wat_l);
    cudaGetSymbolAddress((void**)&wbth, g_wbt_h);
    cudaGetSymbolAddress((void**)&wbtl, g_wbt_l);
    cudaGetSymbolAddress((void**)&woth, g_wot_h);
    cudaGetSymbolAddress((void**)&wotl, g_wot_l);

    cudaFuncSetAttribute(gemm_mma, cudaFuncAttributeMaxDynamicSharedMemorySize, GM_SMEM);
    cudaFuncSetAttribute(attn_mma_kernel, cudaFuncAttributeMaxDynamicSharedMemorySize, ATTN_SMEM);

    // ---- prep ----
    split_kernel<<<(BT_*D_/4 + 255)/256, 256>>>(x, xh, xl, BT_*D_/4);
    transpose_split_kernel<<<dim3((H_*QKD_)/32, D_/32), 256>>>(wq, wqth, wqtl, D_, H_*QKD_);
    transpose_split_kernel<<<dim3((KVR_+ROPE_)/32, D_/32), 256>>>(wkv_a, wath, watl, D_, KVR_+ROPE_);
    transpose_split_kernel<<<dim3((H_*(NOPE_+VD_))/32, KVR_/32), 256>>>(wkv_b, wbth, wbtl, KVR_, H_*(NOPE_+VD_));
    transpose_split_kernel<<<dim3(D_/32, (H_*VD_)/32), 256>>>(wo, woth, wotl, H_*VD_, D_);

    // ---- GEMMs + elementwise ----
    gemm_mma<<<dim3(3072/128, BT_/128), 256, GM_SMEM>>>(xh, xl, wqth, wqtl, qp, BT_, H_*QKD_, D_);
    gemm_mma<<<dim3((KVR_+ROPE_+127)/128, BT_/128), 256, GM_SMEM>>>(xh, xl, wath, watl, kvcp, BT_, KVR_+ROPE_, D_);
    rmsnorm_kernel<<<BT_, 256>>>(kvcp, kvw, latp);
    rope_q_kernel<<<(BT_*H_*32)/256, 256>>>(qp);
    rope_k_kernel<<<(BT_*32)/256, 256>>>(kvcp, krp);
    split_kernel<<<(BT_*KVR_/4 + 255)/256, 256>>>(latp, lath, latl, BT_*KVR_/4);
    gemm_mma<<<dim3(4096/128, BT_/128), 256, GM_SMEM>>>(lath, latl, wbth, wbtl, kvfp, BT_, H_*(NOPE_+VD_), KVR_);
    attn_mma_kernel<<<dim3(T_/ABQ, H_, B_), 256, ATTN_SMEM>>>(qp, kvfp, krp, yp);
    split_kernel<<<(BT_*H_*VD_/4 + 255)/256, 256>>>(yp, yh, yl, BT_*H_*VD_/4);
    gemm_mma<<<dim3(D_/128, BT_/128), 256, GM_SMEM>>>(yh, yl, woth, wotl, out, BT_, D_, H_*VD_);
}

// round 10
// speedup vs baseline: 3.9155x; 1.2374x over previous
#include <cuda_runtime.h>
#include <cuda_bf16.h>
#include <cuda_fp16.h>
#include <math.h>
#include <math_constants.h>
#include <cstdint>

// ---------------- problem constants ----------------
#define H_     16
#define NOPE_  128
#define ROPE_  64
#define VD_    128
#define KVR_   512
#define QKD_   192        // NOPE+ROPE
#define B_     2
#define T_     2048
#define D_     2048
#define BT_    (B_*T_)    // 4096

// ---------------- scratch (device globals; no cudaMalloc allowed) ----------------
__device__ float g_q[(size_t)BT_ * H_ * QKD_];
__device__ float g_kvc[(size_t)BT_ * (KVR_ + ROPE_)];
__device__ float g_lat[(size_t)BT_ * KVR_];
__device__ float g_kvfull[(size_t)BT_ * H_ * (NOPE_+VD_)];
__device__ float g_krope[(size_t)BT_ * ROPE_];
__device__ float g_y[(size_t)BT_ * H_ * VD_];

// fp16 split operands (A: hi/lo; B: hi only)
__device__ __half g_xh[(size_t)BT_ * D_];
__device__ __half g_xl[(size_t)BT_ * D_];
__device__ __half g_lath[(size_t)BT_ * KVR_];
__device__ __half g_latl[(size_t)BT_ * KVR_];
__device__ __half g_yh[(size_t)BT_ * H_ * VD_];
__device__ __half g_yl[(size_t)BT_ * H_ * VD_];
__device__ __half g_wqt_h[(size_t)(H_*QKD_) * D_];
__device__ __half g_wat_h[(size_t)(KVR_+ROPE_) * D_];
__device__ __half g_wbt_h[(size_t)(H_*(NOPE_+VD_)) * KVR_];
__device__ __half g_wot_h[(size_t)D_ * (H_*VD_)];

// ---------------- helpers ----------------
__device__ __forceinline__ uint32_t smem_u32(const void* p) {
    uint32_t a;
    asm("{ .reg .u64 t; cvta.to.shared.u64 t, %1; cvt.u32.u64 %0, t; }" : "=r"(a) : "l"(p));
    return a;
}

__device__ __forceinline__ void ldsm_x4(uint32_t* r, uint32_t addr) {
    asm volatile("ldmatrix.sync.aligned.m8n8.x4.shared.b16 {%0,%1,%2,%3}, [%4];"
                 : "=r"(r[0]), "=r"(r[1]), "=r"(r[2]), "=r"(r[3]) : "r"(addr));
}
__device__ __forceinline__ void ldsm_x4_trans(uint32_t* r, uint32_t addr) {
    asm volatile("ldmatrix.sync.aligned.m8n8.x4.trans.shared.b16 {%0,%1,%2,%3}, [%4];"
                 : "=r"(r[0]), "=r"(r[1]), "=r"(r[2]), "=r"(r[3]) : "r"(addr));
}

// bf16 mma (attention)
__device__ __forceinline__ void mma16816(float* c, const uint32_t* a, const uint32_t* b) {
    asm volatile(
        "mma.sync.aligned.m16n8k16.row.col.f32.bf16.bf16.f32 "
        "{%0,%1,%2,%3}, {%4,%5,%6,%7}, {%8,%9}, {%0,%1,%2,%3};"
        : "+f"(c[0]), "+f"(c[1]), "+f"(c[2]), "+f"(c[3])
        : "r"(a[0]), "r"(a[1]), "r"(a[2]), "r"(a[3]), "r"(b[0]), "r"(b[1]));
}
// fp16 mma (GEMM)
__device__ __forceinline__ void mma16816h(float* c, const uint32_t* a, const uint32_t* b) {
    asm volatile(
        "mma.sync.aligned.m16n8k16.row.col.f32.f16.f16.f32 "
        "{%0,%1,%2,%3}, {%4,%5,%6,%7}, {%8,%9}, {%0,%1,%2,%3};"
        : "+f"(c[0]), "+f"(c[1]), "+f"(c[2]), "+f"(c[3])
        : "r"(a[0]), "r"(a[1]), "r"(a[2]), "r"(a[3]), "r"(b[0]), "r"(b[1]));
}

__device__ __forceinline__ uint32_t pack_bf16x2(float lo, float hi) {
    uint32_t d;
    asm("cvt.rn.bf16x2.f32 %0, %1, %2;" : "=r"(d) : "f"(hi), "f"(lo));
    return d;
}

// bf16 split float4 -> hi/lo smem (attention path)
__device__ __forceinline__ void split_store8(uint32_t addr_h, uint32_t addr_l, float4 v) {
    uint32_t h0 = pack_bf16x2(v.x, v.y);
    uint32_t h1 = pack_bf16x2(v.z, v.w);
    float l0 = v.x - __uint_as_float(h0 << 16);
    float l1 = v.y - __uint_as_float(h0 & 0xffff0000u);
    float l2 = v.z - __uint_as_float(h1 << 16);
    float l3 = v.w - __uint_as_float(h1 & 0xffff0000u);
    uint32_t p0 = pack_bf16x2(l0, l1);
    uint32_t p1 = pack_bf16x2(l2, l3);
    asm volatile("st.shared.v2.b32 [%0], {%1,%2};" :: "r"(addr_h), "r"(h0), "r"(h1) : "memory");
    asm volatile("st.shared.v2.b32 [%0], {%1,%2};" :: "r"(addr_l), "r"(p0), "r"(p1) : "memory");
}

// cp.async 16B with predicated src-size (0 => zero-fill)
__device__ __forceinline__ void cp16(uint32_t dst, const void* src, bool pred) {
    int sz = pred ? 16 : 0;
    asm volatile("cp.async.cg.shared.global [%0], [%1], 16, %2;"
                 :: "r"(dst), "l"(src), "r"(sz) : "memory");
}
#define CP_COMMIT() asm volatile("cp.async.commit_group;" ::: "memory")
#define CP_WAIT0()  asm volatile("cp.async.wait_group 0;" ::: "memory")

// ---------------- fp16 HMMA GEMM: C = (Ah+Al)[M,K] @ Bh[Nn,K]^T ----------------
// 3 tiles per chunk (Ah, Al, Bh) of 128 rows x 32 fp16, pitch 80B. 2-stage, 2 CTAs/SM.
#define GT_PITCHB 80
#define GT_TILE   10240
#define GT_BUF    30720
#define GM_SMEM   (2 * GT_BUF)   // 60 KB

__device__ __forceinline__ void gemm_cp_chunk(
    uint32_t sbase, const __half* Ah, const __half* Al, const __half* Bh,
    int bm0, int bn0, int K, int Nn, int k0, int tid)
{
#pragma unroll
    for (int l = 0; l < 6; l++) {
        const int u = l * 256 + tid;      // 0..1535
        const int tile = u >> 9;          // 0..2
        const int r = (u >> 2) & 127;
        const int c4 = u & 3;
        const uint32_t dst = sbase + tile * GT_TILE + r * GT_PITCHB + c4 * 16;
        const __half* src;
        int row;
        bool ok = true;
        if (tile == 0)      { src = Ah; row = bm0 + r; }
        else if (tile == 1) { src = Al; row = bm0 + r; }
        else {
            src = Bh;
            row = bn0 + r;
            ok = (row < Nn);
            if (!ok) row = Nn - 1;
        }
        cp16(dst, src + (size_t)row * K + k0 + c4 * 8, ok);
    }
}

__device__ __forceinline__ void gemm_compute(
    uint32_t sbase, int wm, int wn, int lane, float c[4][4][4])
{
#pragma unroll
    for (int ks = 0; ks < 32; ks += 16) {
        uint32_t Bhf[4][2];
#pragma unroll
        for (int nj = 0; nj < 2; nj++) {
            const int nrow = wn * 32 + nj * 16 + ((lane >> 4) & 1) * 8 + (lane & 7);
            const uint32_t b = sbase + 2 * GT_TILE + nrow * GT_PITCHB
                             + (ks + ((lane >> 3) & 1) * 8) * 2;
            ldsm_x4(&Bhf[nj * 2][0], b);
        }
#pragma unroll
        for (int mi = 0; mi < 4; mi++) {
            uint32_t ah[4], al[4];
            const int row = wm * 64 + mi * 16 + (lane & 15);
            const uint32_t a = sbase + row * GT_PITCHB + (ks + (lane >> 4) * 8) * 2;
            ldsm_x4(ah, a);
            ldsm_x4(al, a + GT_TILE);
#pragma unroll
            for (int ni = 0; ni < 4; ni++) {
                mma16816h(c[mi][ni], ah, Bhf[ni]);
                mma16816h(c[mi][ni], al, Bhf[ni]);
            }
        }
    }
}

__global__ void __launch_bounds__(256, 2) gemm_mma(
    const __half* __restrict__ Ah, const __half* __restrict__ Al,
    const __half* __restrict__ Bh,
    float* __restrict__ C, int M, int Nn, int K)
{
    extern __shared__ char smem[];
    const uint32_t sb = smem_u32(smem);
    const int tid = threadIdx.x;
    const int lane = tid & 31;
    const int wid = tid >> 5;
    const int wm = wid & 1;
    const int wn = wid >> 1;
    const int bm0 = blockIdx.y * 128;
    const int bn0 = blockIdx.x * 128;

    float c[4][4][4];
#pragma unroll
    for (int mi = 0; mi < 4; mi++)
#pragma unroll
        for (int ni = 0; ni < 4; ni++)
#pragma unroll
            for (int k = 0; k < 4; k++) c[mi][ni][k] = 0.f;

    const int nc = K >> 5;

    gemm_cp_chunk(sb, Ah, Al, Bh, bm0, bn0, K, Nn, 0, tid);
    CP_COMMIT();

    for (int i = 0; i < nc; i++) {
        CP_WAIT0();
        __syncthreads();
        if (i + 1 < nc) {
            gemm_cp_chunk(sb + ((i + 1) & 1) * GT_BUF, Ah, Al, Bh,
                          bm0, bn0, K, Nn, (i + 1) * 32, tid);
            CP_COMMIT();
        }
        gemm_compute(sb + (i & 1) * GT_BUF, wm, wn, lane, c);
    }

    const int g = lane >> 2;
    const int t = lane & 3;
#pragma unroll
    for (int mi = 0; mi < 4; mi++) {
        const int row = bm0 + wm * 64 + mi * 16 + g;
#pragma unroll
        for (int ni = 0; ni < 4; ni++) {
            const int col = bn0 + wn * 32 + ni * 8 + 2 * t;
            if (col < Nn) {
                float2 v0 = make_float2(c[mi][ni][0], c[mi][ni][1]);
                float2 v1 = make_float2(c[mi][ni][2], c[mi][ni][3]);
                *(float2*)&C[(size_t)row * Nn + col] = v0;
                *(float2*)&C[(size_t)(row + 8) * Nn + col] = v1;
            }
        }
    }
}

// ---------------- fp16 hi/lo split (element-wise, float4) ----------------
__global__ __launch_bounds__(256) void split_kernel(
    const float* __restrict__ x, __half* __restrict__ h,
    __half* __restrict__ l, int n4)
{
    int i = blockIdx.x * 256 + threadIdx.x;
    if (i >= n4) return;
    float4 v = ((const float4*)x)[i];
    __half h0 = __float2half_rn(v.x), h1 = __float2half_rn(v.y);
    __half h2 = __float2half_rn(v.z), h3 = __float2half_rn(v.w);
    __half l0 = __float2half_rn(v.x - __half2float(h0));
    __half l1 = __float2half_rn(v.y - __half2float(h1));
    __half l2 = __float2half_rn(v.z - __half2float(h2));
    __half l3 = __float2half_rn(v.w - __half2float(h3));
    ((__half2*)h)[i*2]   = __halves2half2(h0, h1);
    ((__half2*)h)[i*2+1] = __halves2half2(h2, h3);
    ((__half2*)l)[i*2]   = __halves2half2(l0, l1);
    ((__half2*)l)[i*2+1] = __halves2half2(l2, l3);
}

// ---------------- transpose + fp16 convert: W[K,N] fp32 -> Wt [N,K] fp16 ----------------
__global__ __launch_bounds__(256) void transpose_split_kernel(
    const float* __restrict__ W, __half* __restrict__ th, int K, int N)
{
    __shared__ float tile[32][33];
    const int bx = blockIdx.x * 32;
    const int by = blockIdx.y * 32;
    const int txi = threadIdx.x & 31;
    const int tyi = threadIdx.x >> 5;
#pragma unroll
    for (int j = 0; j < 32; j += 8) {
        int kk = by + tyi + j, nn = bx + txi;
        if (kk < K && nn < N) tile[tyi + j][txi] = W[(size_t)kk * N + nn];
    }
    __syncthreads();
#pragma unroll
    for (int j = 0; j < 32; j += 8) {
        int nn = bx + tyi + j, kk = by + txi;
        if (nn < N && kk < K)
            th[(size_t)nn * K + kk] = __float2half_rn(tile[txi][tyi + j]);
    }
}

// ---------------- RMSNorm ----------------
__global__ __launch_bounds__(256) void rmsnorm_kernel(
    const float* __restrict__ kvc, const float* __restrict__ w,
    float* __restrict__ lat)
{
    const int row = blockIdx.x;
    const float* x = kvc + (size_t)row * (KVR_ + ROPE_);
    const int tid = threadIdx.x;

    float v0 = x[tid];
    float v1 = x[tid + 256];
    float ss = v0 * v0 + v1 * v1;
#pragma unroll
    for (int off = 16; off; off >>= 1)
        ss += __shfl_xor_sync(0xffffffffu, ss, off);

    __shared__ float red[8];
    if ((tid & 31) == 0) red[tid >> 5] = ss;
    __syncthreads();
    float tot = 0.f;
#pragma unroll
    for (int i = 0; i < 8; i++) tot += red[i];

    float nrm = rsqrtf(tot * (1.f / 512.f) + 1e-6f);
    float* o = lat + (size_t)row * KVR_;
    o[tid]       = v0 * nrm * w[tid];
    o[tid + 256] = v1 * nrm * w[tid + 256];
}

// ---------------- RoPE ----------------
__global__ __launch_bounds__(256) void rope_q_kernel(float* __restrict__ q)
{
    int idx = blockIdx.x * 256 + threadIdx.x;
    if (idx >= BT_ * H_ * 32) return;
    int i  = idx & 31;
    int h  = (idx >> 5) & (H_ - 1);
    int bt = idx >> 9;
    int t  = bt & (T_ - 1);

    float inv = powf(10000.f, -(float)(2 * i) / 64.f);
    float f = (float)t * inv;
    float c = cosf(f), s = sinf(f);

    float* p = q + ((size_t)bt * H_ + h) * QKD_ + NOPE_;
    float x1 = p[i], x2 = p[i + 32];
    p[i]      = x1 * c - x2 * s;
    p[i + 32] = x2 * c + x1 * s;
}

__global__ __launch_bounds__(256) void rope_k_kernel(
    const float* __restrict__ kvc, float* __restrict__ krope)
{
    int idx = blockIdx.x * 256 + threadIdx.x;
    if (idx >= BT_ * 32) return;
    int i  = idx & 31;
    int bt = idx >> 5;
    int t  = bt & (T_ - 1);

    float inv = powf(10000.f, -(float)(2 * i) / 64.f);
    float f = (float)t * inv;
    float c = cosf(f), s = sinf(f);

    const float* p = kvc + (size_t)bt * (KVR_ + ROPE_) + KVR_;
    float x1 = p[i], x2 = p[i + 32];
    float* o = krope + (size_t)bt * ROPE_;
    o[i]      = x1 * c - x2 * s;
    o[i + 32] = x2 * c + x1 * s;
}

// ---------------- HMMA causal flash attention (bf16 hi/lo; unchanged) ----------------
#define ABQ 128
#define ABK 64
#define AQ_PITCH 400
#define AK_PITCH 400
#define AV_PITCH 272
#define OFF_QH 0
#define OFF_QL 51200
#define OFF_KH 102400
#define OFF_KL 128000
#define OFF_VH 153600
#define OFF_VL 171008
#define ATTN_SMEM 188416

__device__ __forceinline__ float quadmax(float v) {
    v = fmaxf(v, __shfl_xor_sync(0xffffffffu, v, 1));
    v = fmaxf(v, __shfl_xor_sync(0xffffffffu, v, 2));
    return v;
}
__device__ __forceinline__ float quadsum(float v) {
    v += __shfl_xor_sync(0xffffffffu, v, 1);
    v += __shfl_xor_sync(0xffffffffu, v, 2);
    return v;
}

__global__ __launch_bounds__(256) void attn_mma_kernel(
    const float* __restrict__ q, const float* __restrict__ kvfull,
    const float* __restrict__ krope, float* __restrict__ y)
{
    extern __shared__ char smem[];
    const uint32_t sb = smem_u32(smem);
    const int b  = blockIdx.z;
    const int h  = blockIdx.y;
    const int qt = blockIdx.x;
    const int q0 = qt * ABQ;
    const int tid = threadIdx.x;
    const int lane = tid & 31;
    const int w = tid >> 5;
    const int g = lane >> 2;
    const int t = lane & 3;
    const float scale = 0.07216878364870322f;

#pragma unroll
    for (int l = 0; l < 24; l++) {
        int u = l * 256 + tid;
        int row = u / 48, c4 = u % 48, d = c4 * 4;
        float4 v = *(const float4*)&q[(((size_t)(b * T_ + q0 + row)) * H_ + h) * QKD_ + d];
        uint32_t ah = sb + OFF_QH + row * AQ_PITCH + d * 2;
        split_store8(ah, ah + (OFF_QL - OFF_QH), v);
    }

    float oc[16][4];
#pragma unroll
    for (int d = 0; d < 16; d++) { oc[d][0]=0.f; oc[d][1]=0.f; oc[d][2]=0.f; oc[d][3]=0.f; }
    float m0 = -CUDART_INF_F, m1 = -CUDART_INF_F, l0s = 0.f, l1s = 0.f;

    const int row0 = q0 + w * 16 + g;
    const int wrow_max = q0 + w * 16 + 15;

    const int nkt = 2 * qt + 2;
    for (int kt = 0; kt < nkt; kt++) {
        const int k0 = kt * ABK;
        __syncthreads();

#pragma unroll
        for (int l = 0; l < 12; l++) {
            int u = l * 256 + tid;
            int row = u / 48, c4 = u % 48, d = c4 * 4;
            size_t tok = (size_t)(b * T_ + k0 + row);
            float4 v;
            if (d < NOPE_) v = *(const float4*)&kvfull[(tok * H_ + h) * (NOPE_+VD_) + d];
            else           v = *(const float4*)&krope[tok * ROPE_ + (d - NOPE_)];
            uint32_t ah = sb + OFF_KH + row * AK_PITCH + d * 2;
            split_store8(ah, ah + (OFF_KL - OFF_KH), v);
        }
#pragma unroll
        for (int l = 0; l < 8; l++) {
            int u = l * 256 + tid;
            int row = u >> 5, c4 = u & 31, d = c4 * 4;
            size_t tok = (size_t)(b * T_ + k0 + row);
            float4 v = *(const float4*)&kvfull[(tok * H_ + h) * (NOPE_+VD_) + NOPE_ + d];
            uint32_t ah = sb + OFF_VH + row * AV_PITCH + d * 2;
            split_store8(ah, ah + (OFF_VL - OFF_VH), v);
        }
        __syncthreads();

        if (k0 > wrow_max) continue;

        float sc[8][4];
#pragma unroll
        for (int j = 0; j < 8; j++) { sc[j][0]=0.f; sc[j][1]=0.f; sc[j][2]=0.f; sc[j][3]=0.f; }

#pragma unroll
        for (int kb = 0; kb < 12; kb++) {
            uint32_t qa = sb + OFF_QH + (w * 16 + (lane & 15)) * AQ_PITCH
                        + (kb * 16 + (lane >> 4) * 8) * 2;
            uint32_t aqh[4], aql[4];
            ldsm_x4(aqh, qa);
            ldsm_x4(aql, qa + (OFF_QL - OFF_QH));
            uint32_t kh[8][2], kl[8][2];
#pragma unroll
            for (int nj = 0; nj < 4; nj++) {
                uint32_t ka = sb + OFF_KH
                            + (nj * 16 + ((lane >> 4) & 1) * 8 + (lane & 7)) * AK_PITCH
                            + (kb * 16 + ((lane >> 3) & 1) * 8) * 2;
                ldsm_x4(&kh[nj * 2][0], ka);
                ldsm_x4(&kl[nj * 2][0], ka + (OFF_KL - OFF_KH));
            }
#pragma unroll
            for (int j = 0; j < 8; j++) {
                mma16816(sc[j], aqh, kh[j]);
                mma16816(sc[j], aql, kh[j]);
                mma16816(sc[j], aqh, kl[j]);
            }
        }

        const bool need_mask = (k0 + ABK - 1 > q0 + w * 16);
#pragma unroll
        for (int j = 0; j < 8; j++) {
            int cbase = k0 + 8 * j + 2 * t;
#pragma unroll
            for (int e = 0; e < 4; e++) {
                int col = cbase + (e & 1);
                int row = (e < 2) ? row0 : row0 + 8;
                float v = sc[j][e] * scale;
                sc[j][e] = (need_mask && col > row) ? -CUDART_INF_F : v;
            }
        }

        float tm0 = -CUDART_INF_F, tm1 = -CUDART_INF_F;
#pragma unroll
        for (int j = 0; j < 8; j++) {
            tm0 = fmaxf(tm0, fmaxf(sc[j][0], sc[j][1]));
            tm1 = fmaxf(tm1, fmaxf(sc[j][2], sc[j][3]));
        }
        tm0 = quadmax(tm0); tm1 = quadmax(tm1);
        float mn0 = fmaxf(m0, tm0), mn1 = fmaxf(m1, tm1);
        float corr0 = __expf(m0 - mn0), corr1 = __expf(m1 - mn1);
        float rs0 = 0.f, rs1 = 0.f;
#pragma unroll
        for (int j = 0; j < 8; j++) {
            sc[j][0] = __expf(sc[j][0] - mn0);
            sc[j][1] = __expf(sc[j][1] - mn0);
            sc[j][2] = __expf(sc[j][2] - mn1);
            sc[j][3] = __expf(sc[j][3] - mn1);
            rs0 += sc[j][0] + sc[j][1];
            rs1 += sc[j][2] + sc[j][3];
        }
        rs0 = quadsum(rs0); rs1 = quadsum(rs1);
        l0s = l0s * corr0 + rs0;
        l1s = l1s * corr1 + rs1;
        m0 = mn0; m1 = mn1;
#pragma unroll
        for (int d = 0; d < 16; d++) {
            oc[d][0] *= corr0; oc[d][1] *= corr0;
            oc[d][2] *= corr1; oc[d][3] *= corr1;
        }

#pragma unroll
        for (int kb2 = 0; kb2 < 4; kb2++) {
            uint32_t pah[4], pal[4];
#pragma unroll
            for (int half = 0; half < 2; half++) {
                int j = 2 * kb2 + half;
                uint32_t ph0 = pack_bf16x2(sc[j][0], sc[j][1]);
                uint32_t ph1 = pack_bf16x2(sc[j][2], sc[j][3]);
                float lo0 = sc[j][0] - __uint_as_float(ph0 << 16);
                float lo1 = sc[j][1] - __uint_as_float(ph0 & 0xffff0000u);
                float lo2 = sc[j][2] - __uint_as_float(ph1 << 16);
                float lo3 = sc[j][3] - __uint_as_float(ph1 & 0xffff0000u);
                pah[half * 2 + 0] = ph0;
                pah[half * 2 + 1] = ph1;
                pal[half * 2 + 0] = pack_bf16x2(lo0, lo1);
                pal[half * 2 + 1] = pack_bf16x2(lo2, lo3);
            }
#pragma unroll
            for (int dp = 0; dp < 8; dp++) {
                uint32_t vh[4], vl[4];
                uint32_t va = sb + OFF_VH
                            + (kb2 * 16 + (lane & 7) + ((lane >> 3) & 1) * 8) * AV_PITCH
                            + (dp * 16 + (lane >> 4) * 8) * 2;
                ldsm_x4_trans(vh, va);
                ldsm_x4_trans(vl, va + (OFF_VL - OFF_VH));
                mma16816(oc[dp * 2],     pah, &vh[0]);
                mma16816(oc[dp * 2],     pal, &vh[0]);
                mma16816(oc[dp * 2],     pah, &vl[0]);
                mma16816(oc[dp * 2 + 1], pah, &vh[2]);
                mma16816(oc[dp * 2 + 1], pal, &vh[2]);
                mma16816(oc[dp * 2 + 1], pah, &vl[2]);
            }
        }
    }

    float inv0 = 1.f / l0s, inv1 = 1.f / l1s;
#pragma unroll
    for (int d = 0; d < 16; d++) {
        int col = d * 8 + 2 * t;
        size_t base0 = (((size_t)(b * T_ + row0)) * H_ + h) * VD_ + col;
        size_t base1 = (((size_t)(b * T_ + row0 + 8)) * H_ + h) * VD_ + col;
        *(float2*)&y[base0] = make_float2(oc[d][0] * inv0, oc[d][1] * inv0);
        *(float2*)&y[base1] = make_float2(oc[d][2] * inv1, oc[d][3] * inv1);
    }
}

// ---------------- launch ----------------
extern "C" void kernel_launch(void* const* d_in, const int* in_sizes, int n_in,
                              void* d_out, int out_size)
{
    const float* x      = (const float*)d_in[0];
    const float* wq     = (const float*)d_in[1];
    const float* wkv_a  = (const float*)d_in[2];
    const float* wkv_b  = (const float*)d_in[3];
    const float* wo     = (const float*)d_in[4];
    const float* kvw    = (const float*)d_in[5];
    float* out = (float*)d_out;

    float *qp, *kvcp, *latp, *kvfp, *krp, *yp;
    cudaGetSymbolAddress((void**)&qp,   g_q);
    cudaGetSymbolAddress((void**)&kvcp, g_kvc);
    cudaGetSymbolAddress((void**)&latp, g_lat);
    cudaGetSymbolAddress((void**)&kvfp, g_kvfull);
    cudaGetSymbolAddress((void**)&krp,  g_krope);
    cudaGetSymbolAddress((void**)&yp,   g_y);

    __half *xh, *xl, *lath, *latl, *yh, *yl;
    __half *wqth, *wath, *wbth, *woth;
    cudaGetSymbolAddress((void**)&xh,   g_xh);
    cudaGetSymbolAddress((void**)&xl,   g_xl);
    cudaGetSymbolAddress((void**)&lath, g_lath);
    cudaGetSymbolAddress((void**)&latl, g_latl);
    cudaGetSymbolAddress((void**)&yh,   g_yh);
    cudaGetSymbolAddress((void**)&yl,   g_yl);
    cudaGetSymbolAddress((void**)&wqth, g_wqt_h);
    cudaGetSymbolAddress((void**)&wath, g_wat_h);
    cudaGetSymbolAddress((void**)&wbth, g_wbt_h);
    cudaGetSymbolAddress((void**)&woth, g_wot_h);

    cudaFuncSetAttribute(gemm_mma, cudaFuncAttributeMaxDynamicSharedMemorySize, GM_SMEM);
    cudaFuncSetAttribute(attn_mma_kernel, cudaFuncAttributeMaxDynamicSharedMemorySize, ATTN_SMEM);

    // ---- prep ----
    split_kernel<<<(BT_*D_/4 + 255)/256, 256>>>(x, xh, xl, BT_*D_/4);
    transpose_split_kernel<<<dim3((H_*QKD_)/32, D_/32), 256>>>(wq, wqth, D_, H_*QKD_);
    transpose_split_kernel<<<dim3((KVR_+ROPE_)/32, D_/32), 256>>>(wkv_a, wath, D_, KVR_+ROPE_);
    transpose_split_kernel<<<dim3((H_*(NOPE_+VD_))/32, KVR_/32), 256>>>(wkv_b, wbth, KVR_, H_*(NOPE_+VD_));
    transpose_split_kernel<<<dim3(D_/32, (H_*VD_)/32), 256>>>(wo, woth, H_*VD_, D_);

    // ---- GEMMs + elementwise ----
    gemm_mma<<<dim3(3072/128, BT_/128), 256, GM_SMEM>>>(xh, xl, wqth, qp, BT_, H_*QKD_, D_);
    gemm_mma<<<dim3((KVR_+ROPE_+127)/128, BT_/128), 256, GM_SMEM>>>(xh, xl, wath, kvcp, BT_, KVR_+ROPE_, D_);
    rmsnorm_kernel<<<BT_, 256>>>(kvcp, kvw, latp);
    rope_q_kernel<<<(BT_*H_*32)/256, 256>>>(qp);
    rope_k_kernel<<<(BT_*32)/256, 256>>>(kvcp, krp);
    split_kernel<<<(BT_*KVR_/4 + 255)/256, 256>>>(latp, lath, latl, BT_*KVR_/4);
    gemm_mma<<<dim3(4096/128, BT_/128), 256, GM_SMEM>>>(lath, latl, wbth, kvfp, BT_, H_*(NOPE_+VD_), KVR_);
    attn_mma_kernel<<<dim3(T_/ABQ, H_, B_), 256, ATTN_SMEM>>>(qp, kvfp, krp, yp);
    split_kernel<<<(BT_*H_*VD_/4 + 255)/256, 256>>>(yp, yh, yl, BT_*H_*VD_/4);
    gemm_mma<<<dim3(D_/128, BT_/128), 256, GM_SMEM>>>(yh, yl, woth, out, BT_, D_, H_*VD_);
}

// round 11
// speedup vs baseline: 5.1892x; 1.3253x over previous
#include <cuda_runtime.h>
#include <cuda_bf16.h>
#include <cuda_fp16.h>
#include <math.h>
#include <math_constants.h>
#include <cstdint>

// ---------------- problem constants ----------------
#define H_     16
#define NOPE_  128
#define ROPE_  64
#define VD_    128
#define KVR_   512
#define QKD_   192        // NOPE+ROPE
#define B_     2
#define T_     2048
#define D_     2048
#define BT_    (B_*T_)    // 4096

// ---------------- scratch (device globals; no cudaMalloc allowed) ----------------
__device__ float g_q[(size_t)BT_ * H_ * QKD_];
__device__ float g_kvc[(size_t)BT_ * (KVR_ + ROPE_)];
__device__ float g_lat[(size_t)BT_ * KVR_];
__device__ float g_kvfull[(size_t)BT_ * H_ * (NOPE_+VD_)];
__device__ float g_krope[(size_t)BT_ * ROPE_];
__device__ float g_y[(size_t)BT_ * H_ * VD_];

// fp16 operands (single precision level, no compensation)
__device__ __half g_xh[(size_t)BT_ * D_];
__device__ __half g_lath[(size_t)BT_ * KVR_];
__device__ __half g_yh[(size_t)BT_ * H_ * VD_];
__device__ __half g_wqt_h[(size_t)(H_*QKD_) * D_];
__device__ __half g_wat_h[(size_t)(KVR_+ROPE_) * D_];
__device__ __half g_wbt_h[(size_t)(H_*(NOPE_+VD_)) * KVR_];
__device__ __half g_wot_h[(size_t)D_ * (H_*VD_)];

// ---------------- helpers ----------------
__device__ __forceinline__ uint32_t smem_u32(const void* p) {
    uint32_t a;
    asm("{ .reg .u64 t; cvta.to.shared.u64 t, %1; cvt.u32.u64 %0, t; }" : "=r"(a) : "l"(p));
    return a;
}

__device__ __forceinline__ void ldsm_x4(uint32_t* r, uint32_t addr) {
    asm volatile("ldmatrix.sync.aligned.m8n8.x4.shared.b16 {%0,%1,%2,%3}, [%4];"
                 : "=r"(r[0]), "=r"(r[1]), "=r"(r[2]), "=r"(r[3]) : "r"(addr));
}
__device__ __forceinline__ void ldsm_x4_trans(uint32_t* r, uint32_t addr) {
    asm volatile("ldmatrix.sync.aligned.m8n8.x4.trans.shared.b16 {%0,%1,%2,%3}, [%4];"
                 : "=r"(r[0]), "=r"(r[1]), "=r"(r[2]), "=r"(r[3]) : "r"(addr));
}

// bf16 mma (attention)
__device__ __forceinline__ void mma16816(float* c, const uint32_t* a, const uint32_t* b) {
    asm volatile(
        "mma.sync.aligned.m16n8k16.row.col.f32.bf16.bf16.f32 "
        "{%0,%1,%2,%3}, {%4,%5,%6,%7}, {%8,%9}, {%0,%1,%2,%3};"
        : "+f"(c[0]), "+f"(c[1]), "+f"(c[2]), "+f"(c[3])
        : "r"(a[0]), "r"(a[1]), "r"(a[2]), "r"(a[3]), "r"(b[0]), "r"(b[1]));
}
// fp16 mma (GEMM)
__device__ __forceinline__ void mma16816h(float* c, const uint32_t* a, const uint32_t* b) {
    asm volatile(
        "mma.sync.aligned.m16n8k16.row.col.f32.f16.f16.f32 "
        "{%0,%1,%2,%3}, {%4,%5,%6,%7}, {%8,%9}, {%0,%1,%2,%3};"
        : "+f"(c[0]), "+f"(c[1]), "+f"(c[2]), "+f"(c[3])
        : "r"(a[0]), "r"(a[1]), "r"(a[2]), "r"(a[3]), "r"(b[0]), "r"(b[1]));
}

__device__ __forceinline__ uint32_t pack_bf16x2(float lo, float hi) {
    uint32_t d;
    asm("cvt.rn.bf16x2.f32 %0, %1, %2;" : "=r"(d) : "f"(hi), "f"(lo));
    return d;
}

// bf16 split float4 -> hi/lo smem (attention path)
__device__ __forceinline__ void split_store8(uint32_t addr_h, uint32_t addr_l, float4 v) {
    uint32_t h0 = pack_bf16x2(v.x, v.y);
    uint32_t h1 = pack_bf16x2(v.z, v.w);
    float l0 = v.x - __uint_as_float(h0 << 16);
    float l1 = v.y - __uint_as_float(h0 & 0xffff0000u);
    float l2 = v.z - __uint_as_float(h1 << 16);
    float l3 = v.w - __uint_as_float(h1 & 0xffff0000u);
    uint32_t p0 = pack_bf16x2(l0, l1);
    uint32_t p1 = pack_bf16x2(l2, l3);
    asm volatile("st.shared.v2.b32 [%0], {%1,%2};" :: "r"(addr_h), "r"(h0), "r"(h1) : "memory");
    asm volatile("st.shared.v2.b32 [%0], {%1,%2};" :: "r"(addr_l), "r"(p0), "r"(p1) : "memory");
}

// cp.async 16B with predicated src-size (0 => zero-fill)
__device__ __forceinline__ void cp16(uint32_t dst, const void* src, bool pred) {
    int sz = pred ? 16 : 0;
    asm volatile("cp.async.cg.shared.global [%0], [%1], 16, %2;"
                 :: "r"(dst), "l"(src), "r"(sz) : "memory");
}
#define CP_COMMIT() asm volatile("cp.async.commit_group;" ::: "memory")
#define CP_WAIT0()  asm volatile("cp.async.wait_group 0;" ::: "memory")

// ---------------- fp16 HMMA GEMM (single product): C = A[M,K] @ B[Nn,K]^T ----------------
// 2 tiles per chunk (A, B) of 128 rows x 32 fp16, pitch 80B. 2-stage, 2 CTAs/SM.
#define GT_PITCHB 80
#define GT_TILE   10240
#define GT_BUF    20480
#define GM_SMEM   (2 * GT_BUF)   // 40 KB

__device__ __forceinline__ void gemm_cp_chunk(
    uint32_t sbase, const __half* A, const __half* Bm,
    int bm0, int bn0, int K, int Nn, int k0, int tid)
{
#pragma unroll
    for (int l = 0; l < 4; l++) {
        const int u = l * 256 + tid;      // 0..1023
        const int tile = u >> 9;          // 0..1
        const int r = (u >> 2) & 127;
        const int c4 = u & 3;
        const uint32_t dst = sbase + tile * GT_TILE + r * GT_PITCHB + c4 * 16;
        const __half* src;
        int row;
        bool ok = true;
        if (tile == 0) { src = A; row = bm0 + r; }
        else {
            src = Bm;
            row = bn0 + r;
            ok = (row < Nn);
            if (!ok) row = Nn - 1;
        }
        cp16(dst, src + (size_t)row * K + k0 + c4 * 8, ok);
    }
}

__device__ __forceinline__ void gemm_compute(
    uint32_t sbase, int wm, int wn, int lane, float c[4][4][4])
{
#pragma unroll
    for (int ks = 0; ks < 32; ks += 16) {
        uint32_t Bhf[4][2];
#pragma unroll
        for (int nj = 0; nj < 2; nj++) {
            const int nrow = wn * 32 + nj * 16 + ((lane >> 4) & 1) * 8 + (lane & 7);
            const uint32_t b = sbase + GT_TILE + nrow * GT_PITCHB
                             + (ks + ((lane >> 3) & 1) * 8) * 2;
            ldsm_x4(&Bhf[nj * 2][0], b);
        }
#pragma unroll
        for (int mi = 0; mi < 4; mi++) {
            uint32_t ah[4];
            const int row = wm * 64 + mi * 16 + (lane & 15);
            const uint32_t a = sbase + row * GT_PITCHB + (ks + (lane >> 4) * 8) * 2;
            ldsm_x4(ah, a);
#pragma unroll
            for (int ni = 0; ni < 4; ni++)
                mma16816h(c[mi][ni], ah, Bhf[ni]);
        }
    }
}

__global__ void __launch_bounds__(256, 2) gemm_mma(
    const __half* __restrict__ A, const __half* __restrict__ Bm,
    float* __restrict__ C, int M, int Nn, int K)
{
    extern __shared__ char smem[];
    const uint32_t sb = smem_u32(smem);
    const int tid = threadIdx.x;
    const int lane = tid & 31;
    const int wid = tid >> 5;
    const int wm = wid & 1;
    const int wn = wid >> 1;
    const int bm0 = blockIdx.y * 128;
    const int bn0 = blockIdx.x * 128;

    float c[4][4][4];
#pragma unroll
    for (int mi = 0; mi < 4; mi++)
#pragma unroll
        for (int ni = 0; ni < 4; ni++)
#pragma unroll
            for (int k = 0; k < 4; k++) c[mi][ni][k] = 0.f;

    const int nc = K >> 5;

    gemm_cp_chunk(sb, A, Bm, bm0, bn0, K, Nn, 0, tid);
    CP_COMMIT();

    for (int i = 0; i < nc; i++) {
        CP_WAIT0();
        __syncthreads();
        if (i + 1 < nc) {
            gemm_cp_chunk(sb + ((i + 1) & 1) * GT_BUF, A, Bm,
                          bm0, bn0, K, Nn, (i + 1) * 32, tid);
            CP_COMMIT();
        }
        gemm_compute(sb + (i & 1) * GT_BUF, wm, wn, lane, c);
    }

    const int g = lane >> 2;
    const int t = lane & 3;
#pragma unroll
    for (int mi = 0; mi < 4; mi++) {
        const int row = bm0 + wm * 64 + mi * 16 + g;
#pragma unroll
        for (int ni = 0; ni < 4; ni++) {
            const int col = bn0 + wn * 32 + ni * 8 + 2 * t;
            if (col < Nn) {
                float2 v0 = make_float2(c[mi][ni][0], c[mi][ni][1]);
                float2 v1 = make_float2(c[mi][ni][2], c[mi][ni][3]);
                *(float2*)&C[(size_t)row * Nn + col] = v0;
                *(float2*)&C[(size_t)(row + 8) * Nn + col] = v1;
            }
        }
    }
}

// ---------------- fp32 -> fp16 convert (element-wise, float4) ----------------
__global__ __launch_bounds__(256) void convert_kernel(
    const float* __restrict__ x, __half* __restrict__ h, int n4)
{
    int i = blockIdx.x * 256 + threadIdx.x;
    if (i >= n4) return;
    float4 v = ((const float4*)x)[i];
    ((__half2*)h)[i*2]   = __halves2half2(__float2half_rn(v.x), __float2half_rn(v.y));
    ((__half2*)h)[i*2+1] = __halves2half2(__float2half_rn(v.z), __float2half_rn(v.w));
}

// ---------------- transpose + fp16 convert: W[K,N] fp32 -> Wt [N,K] fp16 ----------------
__global__ __launch_bounds__(256) void transpose_split_kernel(
    const float* __restrict__ W, __half* __restrict__ th, int K, int N)
{
    __shared__ float tile[32][33];
    const int bx = blockIdx.x * 32;
    const int by = blockIdx.y * 32;
    const int txi = threadIdx.x & 31;
    const int tyi = threadIdx.x >> 5;
#pragma unroll
    for (int j = 0; j < 32; j += 8) {
        int kk = by + tyi + j, nn = bx + txi;
        if (kk < K && nn < N) tile[tyi + j][txi] = W[(size_t)kk * N + nn];
    }
    __syncthreads();
#pragma unroll
    for (int j = 0; j < 32; j += 8) {
        int nn = bx + tyi + j, kk = by + txi;
        if (nn < N && kk < K)
            th[(size_t)nn * K + kk] = __float2half_rn(tile[txi][tyi + j]);
    }
}

// ---------------- RMSNorm ----------------
__global__ __launch_bounds__(256) void rmsnorm_kernel(
    const float* __restrict__ kvc, const float* __restrict__ w,
    float* __restrict__ lat)
{
    const int row = blockIdx.x;
    const float* x = kvc + (size_t)row * (KVR_ + ROPE_);
    const int tid = threadIdx.x;

    float v0 = x[tid];
    float v1 = x[tid + 256];
    float ss = v0 * v0 + v1 * v1;
#pragma unroll
    for (int off = 16; off; off >>= 1)
        ss += __shfl_xor_sync(0xffffffffu, ss, off);

    __shared__ float red[8];
    if ((tid & 31) == 0) red[tid >> 5] = ss;
    __syncthreads();
    float tot = 0.f;
#pragma unroll
    for (int i = 0; i < 8; i++) tot += red[i];

    float nrm = rsqrtf(tot * (1.f / 512.f) + 1e-6f);
    float* o = lat + (size_t)row * KVR_;
    o[tid]       = v0 * nrm * w[tid];
    o[tid + 256] = v1 * nrm * w[tid + 256];
}

// ---------------- RoPE ----------------
__global__ __launch_bounds__(256) void rope_q_kernel(float* __restrict__ q)
{
    int idx = blockIdx.x * 256 + threadIdx.x;
    if (idx >= BT_ * H_ * 32) return;
    int i  = idx & 31;
    int h  = (idx >> 5) & (H_ - 1);
    int bt = idx >> 9;
    int t  = bt & (T_ - 1);

    float inv = powf(10000.f, -(float)(2 * i) / 64.f);
    float f = (float)t * inv;
    float c = cosf(f), s = sinf(f);

    float* p = q + ((size_t)bt * H_ + h) * QKD_ + NOPE_;
    float x1 = p[i], x2 = p[i + 32];
    p[i]      = x1 * c - x2 * s;
    p[i + 32] = x2 * c + x1 * s;
}

__global__ __launch_bounds__(256) void rope_k_kernel(
    const float* __restrict__ kvc, float* __restrict__ krope)
{
    int idx = blockIdx.x * 256 + threadIdx.x;
    if (idx >= BT_ * 32) return;
    int i  = idx & 31;
    int bt = idx >> 5;
    int t  = bt & (T_ - 1);

    float inv = powf(10000.f, -(float)(2 * i) / 64.f);
    float f = (float)t * inv;
    float c = cosf(f), s = sinf(f);

    const float* p = kvc + (size_t)bt * (KVR_ + ROPE_) + KVR_;
    float x1 = p[i], x2 = p[i + 32];
    float* o = krope + (size_t)bt * ROPE_;
    o[i]      = x1 * c - x2 * s;
    o[i + 32] = x2 * c + x1 * s;
}

// ---------------- HMMA causal flash attention (bf16 hi/lo; unchanged) ----------------
#define ABQ 128
#define ABK 64
#define AQ_PITCH 400
#define AK_PITCH 400
#define AV_PITCH 272
#define OFF_QH 0
#define OFF_QL 51200
#define OFF_KH 102400
#define OFF_KL 128000
#define OFF_VH 153600
#define OFF_VL 171008
#define ATTN_SMEM 188416

__device__ __forceinline__ float quadmax(float v) {
    v = fmaxf(v, __shfl_xor_sync(0xffffffffu, v, 1));
    v = fmaxf(v, __shfl_xor_sync(0xffffffffu, v, 2));
    return v;
}
__device__ __forceinline__ float quadsum(float v) {
    v += __shfl_xor_sync(0xffffffffu, v, 1);
    v += __shfl_xor_sync(0xffffffffu, v, 2);
    return v;
}

__global__ __launch_bounds__(256) void attn_mma_kernel(
    const float* __restrict__ q, const float* __restrict__ kvfull,
    const float* __restrict__ krope, float* __restrict__ y)
{
    extern __shared__ char smem[];
    const uint32_t sb = smem_u32(smem);
    const int b  = blockIdx.z;
    const int h  = blockIdx.y;
    const int qt = blockIdx.x;
    const int q0 = qt * ABQ;
    const int tid = threadIdx.x;
    const int lane = tid & 31;
    const int w = tid >> 5;
    const int g = lane >> 2;
    const int t = lane & 3;
    const float scale = 0.07216878364870322f;

#pragma unroll
    for (int l = 0; l < 24; l++) {
        int u = l * 256 + tid;
        int row = u / 48, c4 = u % 48, d = c4 * 4;
        float4 v = *(const float4*)&q[(((size_t)(b * T_ + q0 + row)) * H_ + h) * QKD_ + d];
        uint32_t ah = sb + OFF_QH + row * AQ_PITCH + d * 2;
        split_store8(ah, ah + (OFF_QL - OFF_QH), v);
    }

    float oc[16][4];
#pragma unroll
    for (int d = 0; d < 16; d++) { oc[d][0]=0.f; oc[d][1]=0.f; oc[d][2]=0.f; oc[d][3]=0.f; }
    float m0 = -CUDART_INF_F, m1 = -CUDART_INF_F, l0s = 0.f, l1s = 0.f;

    const int row0 = q0 + w * 16 + g;
    const int wrow_max = q0 + w * 16 + 15;

    const int nkt = 2 * qt + 2;
    for (int kt = 0; kt < nkt; kt++) {
        const int k0 = kt * ABK;
        __syncthreads();

#pragma unroll
        for (int l = 0; l < 12; l++) {
            int u = l * 256 + tid;
            int row = u / 48, c4 = u % 48, d = c4 * 4;
            size_t tok = (size_t)(b * T_ + k0 + row);
            float4 v;
            if (d < NOPE_) v = *(const float4*)&kvfull[(tok * H_ + h) * (NOPE_+VD_) + d];
            else           v = *(const float4*)&krope[tok * ROPE_ + (d - NOPE_)];
            uint32_t ah = sb + OFF_KH + row * AK_PITCH + d * 2;
            split_store8(ah, ah + (OFF_KL - OFF_KH), v);
        }
#pragma unroll
        for (int l = 0; l < 8; l++) {
            int u = l * 256 + tid;
            int row = u >> 5, c4 = u & 31, d = c4 * 4;
            size_t tok = (size_t)(b * T_ + k0 + row);
            float4 v = *(const float4*)&kvfull[(tok * H_ + h) * (NOPE_+VD_) + NOPE_ + d];
            uint32_t ah = sb + OFF_VH + row * AV_PITCH + d * 2;
            split_store8(ah, ah + (OFF_VL - OFF_VH), v);
        }
        __syncthreads();

        if (k0 > wrow_max) continue;

        float sc[8][4];
#pragma unroll
        for (int j = 0; j < 8; j++) { sc[j][0]=0.f; sc[j][1]=0.f; sc[j][2]=0.f; sc[j][3]=0.f; }

#pragma unroll
        for (int kb = 0; kb < 12; kb++) {
            uint32_t qa = sb + OFF_QH + (w * 16 + (lane & 15)) * AQ_PITCH
                        + (kb * 16 + (lane >> 4) * 8) * 2;
            uint32_t aqh[4], aql[4];
            ldsm_x4(aqh, qa);
            ldsm_x4(aql, qa + (OFF_QL - OFF_QH));
            uint32_t kh[8][2], kl[8][2];
#pragma unroll
            for (int nj = 0; nj < 4; nj++) {
                uint32_t ka = sb + OFF_KH
                            + (nj * 16 + ((lane >> 4) & 1) * 8 + (lane & 7)) * AK_PITCH
                            + (kb * 16 + ((lane >> 3) & 1) * 8) * 2;
                ldsm_x4(&kh[nj * 2][0], ka);
                ldsm_x4(&kl[nj * 2][0], ka + (OFF_KL - OFF_KH));
            }
#pragma unroll
            for (int j = 0; j < 8; j++) {
                mma16816(sc[j], aqh, kh[j]);
                mma16816(sc[j], aql, kh[j]);
                mma16816(sc[j], aqh, kl[j]);
            }
        }

        const bool need_mask = (k0 + ABK - 1 > q0 + w * 16);
#pragma unroll
        for (int j = 0; j < 8; j++) {
            int cbase = k0 + 8 * j + 2 * t;
#pragma unroll
            for (int e = 0; e < 4; e++) {
                int col = cbase + (e & 1);
                int row = (e < 2) ? row0 : row0 + 8;
                float v = sc[j][e] * scale;
                sc[j][e] = (need_mask && col > row) ? -CUDART_INF_F : v;
            }
        }

        float tm0 = -CUDART_INF_F, tm1 = -CUDART_INF_F;
#pragma unroll
        for (int j = 0; j < 8; j++) {
            tm0 = fmaxf(tm0, fmaxf(sc[j][0], sc[j][1]));
            tm1 = fmaxf(tm1, fmaxf(sc[j][2], sc[j][3]));
        }
        tm0 = quadmax(tm0); tm1 = quadmax(tm1);
        float mn0 = fmaxf(m0, tm0), mn1 = fmaxf(m1, tm1);
        float corr0 = __expf(m0 - mn0), corr1 = __expf(m1 - mn1);
        float rs0 = 0.f, rs1 = 0.f;
#pragma unroll
        for (int j = 0; j < 8; j++) {
            sc[j][0] = __expf(sc[j][0] - mn0);
            sc[j][1] = __expf(sc[j][1] - mn0);
            sc[j][2] = __expf(sc[j][2] - mn1);
            sc[j][3] = __expf(sc[j][3] - mn1);
            rs0 += sc[j][0] + sc[j][1];
            rs1 += sc[j][2] + sc[j][3];
        }
        rs0 = quadsum(rs0); rs1 = quadsum(rs1);
        l0s = l0s * corr0 + rs0;
        l1s = l1s * corr1 + rs1;
        m0 = mn0; m1 = mn1;
#pragma unroll
        for (int d = 0; d < 16; d++) {
            oc[d][0] *= corr0; oc[d][1] *= corr0;
            oc[d][2] *= corr1; oc[d][3] *= corr1;
        }

#pragma unroll
        for (int kb2 = 0; kb2 < 4; kb2++) {
            uint32_t pah[4], pal[4];
#pragma unroll
            for (int half = 0; half < 2; half++) {
                int j = 2 * kb2 + half;
                uint32_t ph0 = pack_bf16x2(sc[j][0], sc[j][1]);
                uint32_t ph1 = pack_bf16x2(sc[j][2], sc[j][3]);
                float lo0 = sc[j][0] - __uint_as_float(ph0 << 16);
                float lo1 = sc[j][1] - __uint_as_float(ph0 & 0xffff0000u);
                float lo2 = sc[j][2] - __uint_as_float(ph1 << 16);
                float lo3 = sc[j][3] - __uint_as_float(ph1 & 0xffff0000u);
                pah[half * 2 + 0] = ph0;
                pah[half * 2 + 1] = ph1;
                pal[half * 2 + 0] = pack_bf16x2(lo0, lo1);
                pal[half * 2 + 1] = pack_bf16x2(lo2, lo3);
            }
#pragma unroll
            for (int dp = 0; dp < 8; dp++) {
                uint32_t vh[4], vl[4];
                uint32_t va = sb + OFF_VH
                            + (kb2 * 16 + (lane & 7) + ((lane >> 3) & 1) * 8) * AV_PITCH
                            + (dp * 16 + (lane >> 4) * 8) * 2;
                ldsm_x4_trans(vh, va);
                ldsm_x4_trans(vl, va + (OFF_VL - OFF_VH));
                mma16816(oc[dp * 2],     pah, &vh[0]);
                mma16816(oc[dp * 2],     pal, &vh[0]);
                mma16816(oc[dp * 2],     pah, &vl[0]);
                mma16816(oc[dp * 2 + 1], pah, &vh[2]);
                mma16816(oc[dp * 2 + 1], pal, &vh[2]);
                mma16816(oc[dp * 2 + 1], pah, &vl[2]);
            }
        }
    }

    float inv0 = 1.f / l0s, inv1 = 1.f / l1s;
#pragma unroll
    for (int d = 0; d < 16; d++) {
        int col = d * 8 + 2 * t;
        size_t base0 = (((size_t)(b * T_ + row0)) * H_ + h) * VD_ + col;
        size_t base1 = (((size_t)(b * T_ + row0 + 8)) * H_ + h) * VD_ + col;
        *(float2*)&y[base0] = make_float2(oc[d][0] * inv0, oc[d][1] * inv0);
        *(float2*)&y[base1] = make_float2(oc[d][2] * inv1, oc[d][3] * inv1);
    }
}

// ---------------- launch ----------------
extern "C" void kernel_launch(void* const* d_in, const int* in_sizes, int n_in,
                              void* d_out, int out_size)
{
    const float* x      = (const float*)d_in[0];
    const float* wq     = (const float*)d_in[1];
    const float* wkv_a  = (const float*)d_in[2];
    const float* wkv_b  = (const float*)d_in[3];
    const float* wo     = (const float*)d_in[4];
    const float* kvw    = (const float*)d_in[5];
    float* out = (float*)d_out;

    float *qp, *kvcp, *latp, *kvfp, *krp, *yp;
    cudaGetSymbolAddress((void**)&qp,   g_q);
    cudaGetSymbolAddress((void**)&kvcp, g_kvc);
    cudaGetSymbolAddress((void**)&latp, g_lat);
    cudaGetSymbolAddress((void**)&kvfp, g_kvfull);
    cudaGetSymbolAddress((void**)&krp,  g_krope);
    cudaGetSymbolAddress((void**)&yp,   g_y);

    __half *xh, *lath, *yh;
    __half *wqth, *wath, *wbth, *woth;
    cudaGetSymbolAddress((void**)&xh,   g_xh);
    cudaGetSymbolAddress((void**)&lath, g_lath);
    cudaGetSymbolAddress((void**)&yh,   g_yh);
    cudaGetSymbolAddress((void**)&wqth, g_wqt_h);
    cudaGetSymbolAddress((void**)&wath, g_wat_h);
    cudaGetSymbolAddress((void**)&wbth, g_wbt_h);
    cudaGetSymbolAddress((void**)&woth, g_wot_h);

    cudaFuncSetAttribute(gemm_mma, cudaFuncAttributeMaxDynamicSharedMemorySize, GM_SMEM);
    cudaFuncSetAttribute(attn_mma_kernel, cudaFuncAttributeMaxDynamicSharedMemorySize, ATTN_SMEM);

    // ---- prep ----
    convert_kernel<<<(BT_*D_/4 + 255)/256, 256>>>(x, xh, BT_*D_/4);
    transpose_split_kernel<<<dim3((H_*QKD_)/32, D_/32), 256>>>(wq, wqth, D_, H_*QKD_);
    transpose_split_kernel<<<dim3((KVR_+ROPE_)/32, D_/32), 256>>>(wkv_a, wath, D_, KVR_+ROPE_);
    transpose_split_kernel<<<dim3((H_*(NOPE_+VD_))/32, KVR_/32), 256>>>(wkv_b, wbth, KVR_, H_*(NOPE_+VD_));
    transpose_split_kernel<<<dim3(D_/32, (H_*VD_)/32), 256>>>(wo, woth, H_*VD_, D_);

    // ---- GEMMs + elementwise ----
    gemm_mma<<<dim3(3072/128, BT_/128), 256, GM_SMEM>>>(xh, wqth, qp, BT_, H_*QKD_, D_);
    gemm_mma<<<dim3((KVR_+ROPE_+127)/128, BT_/128), 256, GM_SMEM>>>(xh, wath, kvcp, BT_, KVR_+ROPE_, D_);
    rmsnorm_kernel<<<BT_, 256>>>(kvcp, kvw, latp);
    rope_q_kernel<<<(BT_*H_*32)/256, 256>>>(qp);
    rope_k_kernel<<<(BT_*32)/256, 256>>>(kvcp, krp);
    convert_kernel<<<(BT_*KVR_/4 + 255)/256, 256>>>(latp, lath, BT_*KVR_/4);
    gemm_mma<<<dim3(4096/128, BT_/128), 256, GM_SMEM>>>(lath, wbth, kvfp, BT_, H_*(NOPE_+VD_), KVR_);
    attn_mma_kernel<<<dim3(T_/ABQ, H_, B_), 256, ATTN_SMEM>>>(qp, kvfp, krp, yp);
    convert_kernel<<<(BT_*H_*VD_/4 + 255)/256, 256>>>(yp, yh, BT_*H_*VD_/4);
    gemm_mma<<<dim3(D_/128, BT_/128), 256, GM_SMEM>>>(yh, woth, out, BT_, D_, H_*VD_);
}

// round 12
// speedup vs baseline: 6.6535x; 1.2822x over previous
#include <cuda_runtime.h>
#include <cuda_bf16.h>
#include <cuda_fp16.h>
#include <math.h>
#include <math_constants.h>
#include <cstdint>

// ---------------- problem constants ----------------
#define H_     16
#define NOPE_  128
#define ROPE_  64
#define VD_    128
#define KVR_   512
#define QKD_   192        // NOPE+ROPE
#define B_     2
#define T_     2048
#define D_     2048
#define BT_    (B_*T_)    // 4096

// ---------------- scratch (device globals; no cudaMalloc allowed) ----------------
__device__ float g_q[(size_t)BT_ * H_ * QKD_];
__device__ float g_kvc[(size_t)BT_ * (KVR_ + ROPE_)];
__device__ float g_lat[(size_t)BT_ * KVR_];
__device__ float g_kvfull[(size_t)BT_ * H_ * (NOPE_+VD_)];
__device__ float g_krope[(size_t)BT_ * ROPE_];
__device__ float g_y[(size_t)BT_ * H_ * VD_];

// fp16 operands
__device__ __half g_xh[(size_t)BT_ * D_];
__device__ __half g_lath[(size_t)BT_ * KVR_];
__device__ __half g_yh[(size_t)BT_ * H_ * VD_];
__device__ __half g_wqt_h[(size_t)(H_*QKD_) * D_];
__device__ __half g_wat_h[(size_t)(KVR_+ROPE_) * D_];
__device__ __half g_wbt_h[(size_t)(H_*(NOPE_+VD_)) * KVR_];
__device__ __half g_wot_h[(size_t)D_ * (H_*VD_)];

// ---------------- helpers ----------------
__device__ __forceinline__ uint32_t smem_u32(const void* p) {
    uint32_t a;
    asm("{ .reg .u64 t; cvta.to.shared.u64 t, %1; cvt.u32.u64 %0, t; }" : "=r"(a) : "l"(p));
    return a;
}

__device__ __forceinline__ void ldsm_x4(uint32_t* r, uint32_t addr) {
    asm volatile("ldmatrix.sync.aligned.m8n8.x4.shared.b16 {%0,%1,%2,%3}, [%4];"
                 : "=r"(r[0]), "=r"(r[1]), "=r"(r[2]), "=r"(r[3]) : "r"(addr));
}
__device__ __forceinline__ void ldsm_x4_trans(uint32_t* r, uint32_t addr) {
    asm volatile("ldmatrix.sync.aligned.m8n8.x4.trans.shared.b16 {%0,%1,%2,%3}, [%4];"
                 : "=r"(r[0]), "=r"(r[1]), "=r"(r[2]), "=r"(r[3]) : "r"(addr));
}

// fp16 mma
__device__ __forceinline__ void mma16816h(float* c, const uint32_t* a, const uint32_t* b) {
    asm volatile(
        "mma.sync.aligned.m16n8k16.row.col.f32.f16.f16.f32 "
        "{%0,%1,%2,%3}, {%4,%5,%6,%7}, {%8,%9}, {%0,%1,%2,%3};"
        : "+f"(c[0]), "+f"(c[1]), "+f"(c[2]), "+f"(c[3])
        : "r"(a[0]), "r"(a[1]), "r"(a[2]), "r"(a[3]), "r"(b[0]), "r"(b[1]));
}

__device__ __forceinline__ uint32_t pack_f16x2(float lo, float hi) {
    uint32_t d;
    asm("cvt.rn.f16x2.f32 %0, %1, %2;" : "=r"(d) : "f"(hi), "f"(lo));
    return d;
}

// fp32 float4 -> fp16x4 smem store (8B)
__device__ __forceinline__ void cvt_store8(uint32_t addr, float4 v) {
    uint32_t p0 = pack_f16x2(v.x, v.y);
    uint32_t p1 = pack_f16x2(v.z, v.w);
    asm volatile("st.shared.v2.b32 [%0], {%1,%2};" :: "r"(addr), "r"(p0), "r"(p1) : "memory");
}

// cp.async 16B with predicated src-size (0 => zero-fill)
__device__ __forceinline__ void cp16(uint32_t dst, const void* src, bool pred) {
    int sz = pred ? 16 : 0;
    asm volatile("cp.async.cg.shared.global [%0], [%1], 16, %2;"
                 :: "r"(dst), "l"(src), "r"(sz) : "memory");
}
#define CP_COMMIT() asm volatile("cp.async.commit_group;" ::: "memory")
#define CP_WAIT0()  asm volatile("cp.async.wait_group 0;" ::: "memory")

// ---------------- fp16 HMMA GEMM (single product): C = A[M,K] @ B[Nn,K]^T ----------------
#define GT_PITCHB 80
#define GT_TILE   10240
#define GT_BUF    20480
#define GM_SMEM   (2 * GT_BUF)   // 40 KB

__device__ __forceinline__ void gemm_cp_chunk(
    uint32_t sbase, const __half* A, const __half* Bm,
    int bm0, int bn0, int K, int Nn, int k0, int tid)
{
#pragma unroll
    for (int l = 0; l < 4; l++) {
        const int u = l * 256 + tid;      // 0..1023
        const int tile = u >> 9;          // 0..1
        const int r = (u >> 2) & 127;
        const int c4 = u & 3;
        const uint32_t dst = sbase + tile * GT_TILE + r * GT_PITCHB + c4 * 16;
        const __half* src;
        int row;
        bool ok = true;
        if (tile == 0) { src = A; row = bm0 + r; }
        else {
            src = Bm;
            row = bn0 + r;
            ok = (row < Nn);
            if (!ok) row = Nn - 1;
        }
        cp16(dst, src + (size_t)row * K + k0 + c4 * 8, ok);
    }
}

__device__ __forceinline__ void gemm_compute(
    uint32_t sbase, int wm, int wn, int lane, float c[4][4][4])
{
#pragma unroll
    for (int ks = 0; ks < 32; ks += 16) {
        uint32_t Bhf[4][2];
#pragma unroll
        for (int nj = 0; nj < 2; nj++) {
            const int nrow = wn * 32 + nj * 16 + ((lane >> 4) & 1) * 8 + (lane & 7);
            const uint32_t b = sbase + GT_TILE + nrow * GT_PITCHB
                             + (ks + ((lane >> 3) & 1) * 8) * 2;
            ldsm_x4(&Bhf[nj * 2][0], b);
        }
#pragma unroll
        for (int mi = 0; mi < 4; mi++) {
            uint32_t ah[4];
            const int row = wm * 64 + mi * 16 + (lane & 15);
            const uint32_t a = sbase + row * GT_PITCHB + (ks + (lane >> 4) * 8) * 2;
            ldsm_x4(ah, a);
#pragma unroll
            for (int ni = 0; ni < 4; ni++)
                mma16816h(c[mi][ni], ah, Bhf[ni]);
        }
    }
}

__global__ void __launch_bounds__(256, 2) gemm_mma(
    const __half* __restrict__ A, const __half* __restrict__ Bm,
    float* __restrict__ C, int M, int Nn, int K)
{
    extern __shared__ char smem[];
    const uint32_t sb = smem_u32(smem);
    const int tid = threadIdx.x;
    const int lane = tid & 31;
    const int wid = tid >> 5;
    const int wm = wid & 1;
    const int wn = wid >> 1;
    const int bm0 = blockIdx.y * 128;
    const int bn0 = blockIdx.x * 128;

    float c[4][4][4];
#pragma unroll
    for (int mi = 0; mi < 4; mi++)
#pragma unroll
        for (int ni = 0; ni < 4; ni++)
#pragma unroll
            for (int k = 0; k < 4; k++) c[mi][ni][k] = 0.f;

    const int nc = K >> 5;

    gemm_cp_chunk(sb, A, Bm, bm0, bn0, K, Nn, 0, tid);
    CP_COMMIT();

    for (int i = 0; i < nc; i++) {
        CP_WAIT0();
        __syncthreads();
        if (i + 1 < nc) {
            gemm_cp_chunk(sb + ((i + 1) & 1) * GT_BUF, A, Bm,
                          bm0, bn0, K, Nn, (i + 1) * 32, tid);
            CP_COMMIT();
        }
        gemm_compute(sb + (i & 1) * GT_BUF, wm, wn, lane, c);
    }

    const int g = lane >> 2;
    const int t = lane & 3;
#pragma unroll
    for (int mi = 0; mi < 4; mi++) {
        const int row = bm0 + wm * 64 + mi * 16 + g;
#pragma unroll
        for (int ni = 0; ni < 4; ni++) {
            const int col = bn0 + wn * 32 + ni * 8 + 2 * t;
            if (col < Nn) {
                float2 v0 = make_float2(c[mi][ni][0], c[mi][ni][1]);
                float2 v1 = make_float2(c[mi][ni][2], c[mi][ni][3]);
                *(float2*)&C[(size_t)row * Nn + col] = v0;
                *(float2*)&C[(size_t)(row + 8) * Nn + col] = v1;
            }
        }
    }
}

// ---------------- fp32 -> fp16 convert (element-wise, float4) ----------------
__global__ __launch_bounds__(256) void convert_kernel(
    const float* __restrict__ x, __half* __restrict__ h, int n4)
{
    int i = blockIdx.x * 256 + threadIdx.x;
    if (i >= n4) return;
    float4 v = ((const float4*)x)[i];
    ((__half2*)h)[i*2]   = __halves2half2(__float2half_rn(v.x), __float2half_rn(v.y));
    ((__half2*)h)[i*2+1] = __halves2half2(__float2half_rn(v.z), __float2half_rn(v.w));
}

// ---------------- transpose + fp16 convert: W[K,N] fp32 -> Wt [N,K] fp16 ----------------
__global__ __launch_bounds__(256) void transpose_split_kernel(
    const float* __restrict__ W, __half* __restrict__ th, int K, int N)
{
    __shared__ float tile[32][33];
    const int bx = blockIdx.x * 32;
    const int by = blockIdx.y * 32;
    const int txi = threadIdx.x & 31;
    const int tyi = threadIdx.x >> 5;
#pragma unroll
    for (int j = 0; j < 32; j += 8) {
        int kk = by + tyi + j, nn = bx + txi;
        if (kk < K && nn < N) tile[tyi + j][txi] = W[(size_t)kk * N + nn];
    }
    __syncthreads();
#pragma unroll
    for (int j = 0; j < 32; j += 8) {
        int nn = bx + tyi + j, kk = by + txi;
        if (nn < N && kk < K)
            th[(size_t)nn * K + kk] = __float2half_rn(tile[txi][tyi + j]);
    }
}

// ---------------- RMSNorm ----------------
__global__ __launch_bounds__(256) void rmsnorm_kernel(
    const float* __restrict__ kvc, const float* __restrict__ w,
    float* __restrict__ lat)
{
    const int row = blockIdx.x;
    const float* x = kvc + (size_t)row * (KVR_ + ROPE_);
    const int tid = threadIdx.x;

    float v0 = x[tid];
    float v1 = x[tid + 256];
    float ss = v0 * v0 + v1 * v1;
#pragma unroll
    for (int off = 16; off; off >>= 1)
        ss += __shfl_xor_sync(0xffffffffu, ss, off);

    __shared__ float red[8];
    if ((tid & 31) == 0) red[tid >> 5] = ss;
    __syncthreads();
    float tot = 0.f;
#pragma unroll
    for (int i = 0; i < 8; i++) tot += red[i];

    float nrm = rsqrtf(tot * (1.f / 512.f) + 1e-6f);
    float* o = lat + (size_t)row * KVR_;
    o[tid]       = v0 * nrm * w[tid];
    o[tid + 256] = v1 * nrm * w[tid + 256];
}

// ---------------- RoPE ----------------
__global__ __launch_bounds__(256) void rope_q_kernel(float* __restrict__ q)
{
    int idx = blockIdx.x * 256 + threadIdx.x;
    if (idx >= BT_ * H_ * 32) return;
    int i  = idx & 31;
    int h  = (idx >> 5) & (H_ - 1);
    int bt = idx >> 9;
    int t  = bt & (T_ - 1);

    float inv = powf(10000.f, -(float)(2 * i) / 64.f);
    float f = (float)t * inv;
    float c = cosf(f), s = sinf(f);

    float* p = q + ((size_t)bt * H_ + h) * QKD_ + NOPE_;
    float x1 = p[i], x2 = p[i + 32];
    p[i]      = x1 * c - x2 * s;
    p[i + 32] = x2 * c + x1 * s;
}

__global__ __launch_bounds__(256) void rope_k_kernel(
    const float* __restrict__ kvc, float* __restrict__ krope)
{
    int idx = blockIdx.x * 256 + threadIdx.x;
    if (idx >= BT_ * 32) return;
    int i  = idx & 31;
    int bt = idx >> 5;
    int t  = bt & (T_ - 1);

    float inv = powf(10000.f, -(float)(2 * i) / 64.f);
    float f = (float)t * inv;
    float c = cosf(f), s = sinf(f);

    const float* p = kvc + (size_t)bt * (KVR_ + ROPE_) + KVR_;
    float x1 = p[i], x2 = p[i + 32];
    float* o = krope + (size_t)bt * ROPE_;
    o[i]      = x1 * c - x2 * s;
    o[i + 32] = x2 * c + x1 * s;
}

// ---------------- fp16 HMMA causal flash attention (single product) ----------------
// BQ=128, BK=64, 8 warps (one per 16 q-rows).
#define ABQ 128
#define ABK 64
#define AQ_PITCH 400   // 192 fp16 = 384B + 16 pad
#define AK_PITCH 400
#define AV_PITCH 272   // 128 fp16 = 256B + 16 pad
#define OFF_Q 0
#define OFF_K 51200
#define OFF_V 76800
#define ATTN_SMEM 94208

__device__ __forceinline__ float quadmax(float v) {
    v = fmaxf(v, __shfl_xor_sync(0xffffffffu, v, 1));
    v = fmaxf(v, __shfl_xor_sync(0xffffffffu, v, 2));
    return v;
}
__device__ __forceinline__ float quadsum(float v) {
    v += __shfl_xor_sync(0xffffffffu, v, 1);
    v += __shfl_xor_sync(0xffffffffu, v, 2);
    return v;
}

__global__ __launch_bounds__(256) void attn_mma_kernel(
    const float* __restrict__ q, const float* __restrict__ kvfull,
    const float* __restrict__ krope, float* __restrict__ y)
{
    extern __shared__ char smem[];
    const uint32_t sb = smem_u32(smem);
    const int b  = blockIdx.z;
    const int h  = blockIdx.y;
    const int qt = blockIdx.x;
    const int q0 = qt * ABQ;
    const int tid = threadIdx.x;
    const int lane = tid & 31;
    const int w = tid >> 5;
    const int g = lane >> 2;
    const int t = lane & 3;
    const float scale = 0.07216878364870322f;

    // load Q tile [128][192] fp32 -> fp16 smem
#pragma unroll
    for (int l = 0; l < 24; l++) {
        int u = l * 256 + tid;
        int row = u / 48, c4 = u % 48, d = c4 * 4;
        float4 v = *(const float4*)&q[(((size_t)(b * T_ + q0 + row)) * H_ + h) * QKD_ + d];
        cvt_store8(sb + OFF_Q + row * AQ_PITCH + d * 2, v);
    }

    float oc[16][4];
#pragma unroll
    for (int d = 0; d < 16; d++) { oc[d][0]=0.f; oc[d][1]=0.f; oc[d][2]=0.f; oc[d][3]=0.f; }
    float m0 = -CUDART_INF_F, m1 = -CUDART_INF_F, l0s = 0.f, l1s = 0.f;

    const int row0 = q0 + w * 16 + g;
    const int wrow_max = q0 + w * 16 + 15;

    const int nkt = 2 * qt + 2;
    for (int kt = 0; kt < nkt; kt++) {
        const int k0 = kt * ABK;
        __syncthreads();

        // load K tile [64][192]
#pragma unroll
        for (int l = 0; l < 12; l++) {
            int u = l * 256 + tid;
            int row = u / 48, c4 = u % 48, d = c4 * 4;
            size_t tok = (size_t)(b * T_ + k0 + row);
            float4 v;
            if (d < NOPE_) v = *(const float4*)&kvfull[(tok * H_ + h) * (NOPE_+VD_) + d];
            else           v = *(const float4*)&krope[tok * ROPE_ + (d - NOPE_)];
            cvt_store8(sb + OFF_K + row * AK_PITCH + d * 2, v);
        }
        // load V tile [64][128]
#pragma unroll
        for (int l = 0; l < 8; l++) {
            int u = l * 256 + tid;
            int row = u >> 5, c4 = u & 31, d = c4 * 4;
            size_t tok = (size_t)(b * T_ + k0 + row);
            float4 v = *(const float4*)&kvfull[(tok * H_ + h) * (NOPE_+VD_) + NOPE_ + d];
            cvt_store8(sb + OFF_V + row * AV_PITCH + d * 2, v);
        }
        __syncthreads();

        if (k0 > wrow_max) continue;

        // ---- S = Q @ K^T (fp16 single product) ----
        float sc[8][4];
#pragma unroll
        for (int j = 0; j < 8; j++) { sc[j][0]=0.f; sc[j][1]=0.f; sc[j][2]=0.f; sc[j][3]=0.f; }

#pragma unroll
        for (int kb = 0; kb < 12; kb++) {
            uint32_t qa = sb + OFF_Q + (w * 16 + (lane & 15)) * AQ_PITCH
                        + (kb * 16 + (lane >> 4) * 8) * 2;
            uint32_t aq[4];
            ldsm_x4(aq, qa);
            uint32_t kh[8][2];
#pragma unroll
            for (int nj = 0; nj < 4; nj++) {
                uint32_t ka = sb + OFF_K
                            + (nj * 16 + ((lane >> 4) & 1) * 8 + (lane & 7)) * AK_PITCH
                            + (kb * 16 + ((lane >> 3) & 1) * 8) * 2;
                ldsm_x4(&kh[nj * 2][0], ka);
            }
#pragma unroll
            for (int j = 0; j < 8; j++)
                mma16816h(sc[j], aq, kh[j]);
        }

        // ---- scale + causal mask ----
        const bool need_mask = (k0 + ABK - 1 > q0 + w * 16);
#pragma unroll
        for (int j = 0; j < 8; j++) {
            int cbase = k0 + 8 * j + 2 * t;
#pragma unroll
            for (int e = 0; e < 4; e++) {
                int col = cbase + (e & 1);
                int row = (e < 2) ? row0 : row0 + 8;
                float v = sc[j][e] * scale;
                sc[j][e] = (need_mask && col > row) ? -CUDART_INF_F : v;
            }
        }

        // ---- online softmax ----
        float tm0 = -CUDART_INF_F, tm1 = -CUDART_INF_F;
#pragma unroll
        for (int j = 0; j < 8; j++) {
            tm0 = fmaxf(tm0, fmaxf(sc[j][0], sc[j][1]));
            tm1 = fmaxf(tm1, fmaxf(sc[j][2], sc[j][3]));
        }
        tm0 = quadmax(tm0); tm1 = quadmax(tm1);
        float mn0 = fmaxf(m0, tm0), mn1 = fmaxf(m1, tm1);
        float corr0 = __expf(m0 - mn0), corr1 = __expf(m1 - mn1);
        float rs0 = 0.f, rs1 = 0.f;
#pragma unroll
        for (int j = 0; j < 8; j++) {
            sc[j][0] = __expf(sc[j][0] - mn0);
            sc[j][1] = __expf(sc[j][1] - mn0);
            sc[j][2] = __expf(sc[j][2] - mn1);
            sc[j][3] = __expf(sc[j][3] - mn1);
            rs0 += sc[j][0] + sc[j][1];
            rs1 += sc[j][2] + sc[j][3];
        }
        rs0 = quadsum(rs0); rs1 = quadsum(rs1);
        l0s = l0s * corr0 + rs0;
        l1s = l1s * corr1 + rs1;
        m0 = mn0; m1 = mn1;
#pragma unroll
        for (int d = 0; d < 16; d++) {
            oc[d][0] *= corr0; oc[d][1] *= corr0;
            oc[d][2] *= corr1; oc[d][3] *= corr1;
        }

        // ---- O += P @ V (fp16 single product; P frags from S accumulators) ----
#pragma unroll
        for (int kb2 = 0; kb2 < 4; kb2++) {
            uint32_t pa[4];
#pragma unroll
            for (int half = 0; half < 2; half++) {
                int j = 2 * kb2 + half;
                pa[half * 2 + 0] = pack_f16x2(sc[j][0], sc[j][1]);
                pa[half * 2 + 1] = pack_f16x2(sc[j][2], sc[j][3]);
            }
#pragma unroll
            for (int dp = 0; dp < 8; dp++) {
                uint32_t vh[4];
                uint32_t va = sb + OFF_V
                            + (kb2 * 16 + (lane & 7) + ((lane >> 3) & 1) * 8) * AV_PITCH
                            + (dp * 16 + (lane >> 4) * 8) * 2;
                ldsm_x4_trans(vh, va);
                mma16816h(oc[dp * 2],     pa, &vh[0]);
                mma16816h(oc[dp * 2 + 1], pa, &vh[2]);
            }
        }
    }

    // ---- epilogue ----
    float inv0 = 1.f / l0s, inv1 = 1.f / l1s;
#pragma unroll
    for (int d = 0; d < 16; d++) {
        int col = d * 8 + 2 * t;
        size_t base0 = (((size_t)(b * T_ + row0)) * H_ + h) * VD_ + col;
        size_t base1 = (((size_t)(b * T_ + row0 + 8)) * H_ + h) * VD_ + col;
        *(float2*)&y[base0] = make_float2(oc[d][0] * inv0, oc[d][1] * inv0);
        *(float2*)&y[base1] = make_float2(oc[d][2] * inv1, oc[d][3] * inv1);
    }
}

// ---------------- launch ----------------
extern "C" void kernel_launch(void* const* d_in, const int* in_sizes, int n_in,
                              void* d_out, int out_size)
{
    const float* x      = (const float*)d_in[0];
    const float* wq     = (const float*)d_in[1];
    const float* wkv_a  = (const float*)d_in[2];
    const float* wkv_b  = (const float*)d_in[3];
    const float* wo     = (const float*)d_in[4];
    const float* kvw    = (const float*)d_in[5];
    float* out = (float*)d_out;

    float *qp, *kvcp, *latp, *kvfp, *krp, *yp;
    cudaGetSymbolAddress((void**)&qp,   g_q);
    cudaGetSymbolAddress((void**)&kvcp, g_kvc);
    cudaGetSymbolAddress((void**)&latp, g_lat);
    cudaGetSymbolAddress((void**)&kvfp, g_kvfull);
    cudaGetSymbolAddress((void**)&krp,  g_krope);
    cudaGetSymbolAddress((void**)&yp,   g_y);

    __half *xh, *lath, *yh;
    __half *wqth, *wath, *wbth, *woth;
    cudaGetSymbolAddress((void**)&xh,   g_xh);
    cudaGetSymbolAddress((void**)&lath, g_lath);
    cudaGetSymbolAddress((void**)&yh,   g_yh);
    cudaGetSymbolAddress((void**)&wqth, g_wqt_h);
    cudaGetSymbolAddress((void**)&wath, g_wat_h);
    cudaGetSymbolAddress((void**)&wbth, g_wbt_h);
    cudaGetSymbolAddress((void**)&woth, g_wot_h);

    cudaFuncSetAttribute(gemm_mma, cudaFuncAttributeMaxDynamicSharedMemorySize, GM_SMEM);
    cudaFuncSetAttribute(attn_mma_kernel, cudaFuncAttributeMaxDynamicSharedMemorySize, ATTN_SMEM);

    // ---- prep ----
    convert_kernel<<<(BT_*D_/4 + 255)/256, 256>>>(x, xh, BT_*D_/4);
    transpose_split_kernel<<<dim3((H_*QKD_)/32, D_/32), 256>>>(wq, wqth, D_, H_*QKD_);
    transpose_split_kernel<<<dim3((KVR_+ROPE_)/32, D_/32), 256>>>(wkv_a, wath, D_, KVR_+ROPE_);
    transpose_split_kernel<<<dim3((H_*(NOPE_+VD_))/32, KVR_/32), 256>>>(wkv_b, wbth, KVR_, H_*(NOPE_+VD_));
    transpose_split_kernel<<<dim3(D_/32, (H_*VD_)/32), 256>>>(wo, woth, H_*VD_, D_);

    // ---- GEMMs + elementwise ----
    gemm_mma<<<dim3(3072/128, BT_/128), 256, GM_SMEM>>>(xh, wqth, qp, BT_, H_*QKD_, D_);
    gemm_mma<<<dim3((KVR_+ROPE_+127)/128, BT_/128), 256, GM_SMEM>>>(xh, wath, kvcp, BT_, KVR_+ROPE_, D_);
    rmsnorm_kernel<<<BT_, 256>>>(kvcp, kvw, latp);
    rope_q_kernel<<<(BT_*H_*32)/256, 256>>>(qp);
    rope_k_kernel<<<(BT_*32)/256, 256>>>(kvcp, krp);
    convert_kernel<<<(BT_*KVR_/4 + 255)/256, 256>>>(latp, lath, BT_*KVR_/4);
    gemm_mma<<<dim3(4096/128, BT_/128), 256, GM_SMEM>>>(lath, wbth, kvfp, BT_, H_*(NOPE_+VD_), KVR_);
    attn_mma_kernel<<<dim3(T_/ABQ, H_, B_), 256, ATTN_SMEM>>>(qp, kvfp, krp, yp);
    convert_kernel<<<(BT_*H_*VD_/4 + 255)/256, 256>>>(yp, yh, BT_*H_*VD_/4);
    gemm_mma<<<dim3(D_/128, BT_/128), 256, GM_SMEM>>>(yh, woth, out, BT_, D_, H_*VD_);
}

// round 15
// speedup vs baseline: 7.3743x; 1.1083x over previous
#include <cuda_runtime.h>
#include <cuda_fp16.h>
#include <math.h>
#include <math_constants.h>
#include <cstdint>

// ---------------- problem constants ----------------
#define H_     16
#define NOPE_  128
#define ROPE_  64
#define VD_    128
#define KVR_   512
#define QKD_   192        // NOPE+ROPE
#define B_     2
#define T_     2048
#define D_     2048
#define BT_    (B_*T_)    // 4096
#define NQA_   (H_*QKD_ + KVR_ + ROPE_)   // 3648 combined q|kvc width

// ---------------- scratch (device globals; no cudaMalloc allowed) ----------------
__device__ float g_qkv[(size_t)BT_ * NQA_];               // [BT, 3648]: q(3072) | kvc(576)
__device__ float g_kvfull[(size_t)BT_ * H_ * (NOPE_+VD_)];
__device__ float g_krope[(size_t)BT_ * ROPE_];

// fp16 operands
__device__ __half g_xh[(size_t)BT_ * D_];
__device__ __half g_lath[(size_t)BT_ * KVR_];
__device__ __half g_yh[(size_t)BT_ * H_ * VD_];
__device__ __half g_wqa_h[(size_t)NQA_ * D_];             // [3648, 2048] = wq^T | wkv_a^T
__device__ __half g_wbt_h[(size_t)(H_*(NOPE_+VD_)) * KVR_];
__device__ __half g_wot_h[(size_t)D_ * (H_*VD_)];

// ---------------- helpers ----------------
__device__ __forceinline__ uint32_t smem_u32(const void* p) {
    uint32_t a;
    asm("{ .reg .u64 t; cvta.to.shared.u64 t, %1; cvt.u32.u64 %0, t; }" : "=r"(a) : "l"(p));
    return a;
}

__device__ __forceinline__ void ldsm_x4(uint32_t* r, uint32_t addr) {
    asm volatile("ldmatrix.sync.aligned.m8n8.x4.shared.b16 {%0,%1,%2,%3}, [%4];"
                 : "=r"(r[0]), "=r"(r[1]), "=r"(r[2]), "=r"(r[3]) : "r"(addr));
}
__device__ __forceinline__ void ldsm_x4_trans(uint32_t* r, uint32_t addr) {
    asm volatile("ldmatrix.sync.aligned.m8n8.x4.trans.shared.b16 {%0,%1,%2,%3}, [%4];"
                 : "=r"(r[0]), "=r"(r[1]), "=r"(r[2]), "=r"(r[3]) : "r"(addr));
}

__device__ __forceinline__ void mma16816h(float* c, const uint32_t* a, const uint32_t* b) {
    asm volatile(
        "mma.sync.aligned.m16n8k16.row.col.f32.f16.f16.f32 "
        "{%0,%1,%2,%3}, {%4,%5,%6,%7}, {%8,%9}, {%0,%1,%2,%3};"
        : "+f"(c[0]), "+f"(c[1]), "+f"(c[2]), "+f"(c[3])
        : "r"(a[0]), "r"(a[1]), "r"(a[2]), "r"(a[3]), "r"(b[0]), "r"(b[1]));
}

__device__ __forceinline__ uint32_t pack_f16x2(float lo, float hi) {
    uint32_t d;
    asm("cvt.rn.f16x2.f32 %0, %1, %2;" : "=r"(d) : "f"(hi), "f"(lo));
    return d;
}

__device__ __forceinline__ void cvt_store8(uint32_t addr, float4 v) {
    uint32_t p0 = pack_f16x2(v.x, v.y);
    uint32_t p1 = pack_f16x2(v.z, v.w);
    asm volatile("st.shared.v2.b32 [%0], {%1,%2};" :: "r"(addr), "r"(p0), "r"(p1) : "memory");
}

__device__ __forceinline__ void cp16(uint32_t dst, const void* src, bool pred) {
    int sz = pred ? 16 : 0;
    asm volatile("cp.async.cg.shared.global [%0], [%1], 16, %2;"
                 :: "r"(dst), "l"(src), "r"(sz) : "memory");
}
#define CP_COMMIT() asm volatile("cp.async.commit_group;" ::: "memory")
#define CP_WAIT0()  asm volatile("cp.async.wait_group 0;" ::: "memory")

// ---------------- fp16 HMMA GEMM, K-chunk 64, 2-stage, 2 CTAs/SM ----------------
// Tiles: A,B of 128 rows x 64 fp16, pitch 144B. buffer = 2*18432 = 36864 B.
#define GT_PITCHB 144
#define GT_TILE   18432
#define GT_BUF    36864
#define GM_SMEM   (2 * GT_BUF)   // 72 KB

__device__ __forceinline__ void gemm_cp_chunk(
    uint32_t sbase, const __half* A, const __half* Bm,
    int bm0, int bn0, int K, int Nn, int k0, int tid)
{
#pragma unroll
    for (int l = 0; l < 8; l++) {
        const int u = l * 256 + tid;      // 0..2047
        const int tile = u >> 10;         // 0..1
        const int r = (u >> 3) & 127;
        const int c4 = u & 7;             // 8 x 16B = 128B row
        const uint32_t dst = sbase + tile * GT_TILE + r * GT_PITCHB + c4 * 16;
        const __half* src;
        int row;
        bool ok = true;
        if (tile == 0) { src = A; row = bm0 + r; }
        else {
            src = Bm;
            row = bn0 + r;
            ok = (row < Nn);
            if (!ok) row = Nn - 1;
        }
        cp16(dst, src + (size_t)row * K + k0 + c4 * 8, ok);
    }
}

__device__ __forceinline__ void gemm_compute(
    uint32_t sbase, int wm, int wn, int lane, float c[4][4][4])
{
#pragma unroll
    for (int ks = 0; ks < 64; ks += 16) {
        uint32_t Bhf[4][2];
#pragma unroll
        for (int nj = 0; nj < 2; nj++) {
            const int nrow = wn * 32 + nj * 16 + ((lane >> 4) & 1) * 8 + (lane & 7);
            const uint32_t b = sbase + GT_TILE + nrow * GT_PITCHB
                             + (ks + ((lane >> 3) & 1) * 8) * 2;
            ldsm_x4(&Bhf[nj * 2][0], b);
        }
#pragma unroll
        for (int mi = 0; mi < 4; mi++) {
            uint32_t ah[4];
            const int row = wm * 64 + mi * 16 + (lane & 15);
            const uint32_t a = sbase + row * GT_PITCHB + (ks + (lane >> 4) * 8) * 2;
            ldsm_x4(ah, a);
#pragma unroll
            for (int ni = 0; ni < 4; ni++)
                mma16816h(c[mi][ni], ah, Bhf[ni]);
        }
    }
}

__global__ void __launch_bounds__(256, 2) gemm_mma(
    const __half* __restrict__ A, const __half* __restrict__ Bm,
    float* __restrict__ C, int M, int Nn, int K)
{
    extern __shared__ char smem[];
    const uint32_t sb = smem_u32(smem);
    const int tid = threadIdx.x;
    const int lane = tid & 31;
    const int wid = tid >> 5;
    const int wm = wid & 1;
    const int wn = wid >> 1;
    const int bm0 = blockIdx.y * 128;
    const int bn0 = blockIdx.x * 128;

    float c[4][4][4];
#pragma unroll
    for (int mi = 0; mi < 4; mi++)
#pragma unroll
        for (int ni = 0; ni < 4; ni++)
#pragma unroll
            for (int k = 0; k < 4; k++) c[mi][ni][k] = 0.f;

    const int nc = K >> 6;   // chunks of 64 (K=512 -> 8, K=2048 -> 32)

    gemm_cp_chunk(sb, A, Bm, bm0, bn0, K, Nn, 0, tid);
    CP_COMMIT();

    for (int i = 0; i < nc; i++) {
        CP_WAIT0();
        __syncthreads();
        if (i + 1 < nc) {
            gemm_cp_chunk(sb + ((i + 1) & 1) * GT_BUF, A, Bm,
                          bm0, bn0, K, Nn, (i + 1) * 64, tid);
            CP_COMMIT();
        }
        gemm_compute(sb + (i & 1) * GT_BUF, wm, wn, lane, c);
    }

    const int g = lane >> 2;
    const int t = lane & 3;
#pragma unroll
    for (int mi = 0; mi < 4; mi++) {
        const int row = bm0 + wm * 64 + mi * 16 + g;
#pragma unroll
        for (int ni = 0; ni < 4; ni++) {
            const int col = bn0 + wn * 32 + ni * 8 + 2 * t;
            if (col < Nn) {
                float2 v0 = make_float2(c[mi][ni][0], c[mi][ni][1]);
                float2 v1 = make_float2(c[mi][ni][2], c[mi][ni][3]);
                *(float2*)&C[(size_t)row * Nn + col] = v0;
                *(float2*)&C[(size_t)(row + 8) * Nn + col] = v1;
            }
        }
    }
}

// ---------------- fp32 -> fp16 convert ----------------
__global__ __launch_bounds__(256) void convert_kernel(
    const float* __restrict__ x, __half* __restrict__ h, int n4)
{
    int i = blockIdx.x * 256 + threadIdx.x;
    if (i >= n4) return;
    float4 v = ((const float4*)x)[i];
    ((__half2*)h)[i*2]   = __halves2half2(__float2half_rn(v.x), __float2half_rn(v.y));
    ((__half2*)h)[i*2+1] = __halves2half2(__float2half_rn(v.z), __float2half_rn(v.w));
}

// ---------------- transpose + fp16 convert: W[K,N] fp32 -> Wt [N,K] fp16 ----------------
__global__ __launch_bounds__(256) void transpose_split_kernel(
    const float* __restrict__ W, __half* __restrict__ th, int K, int N)
{
    __shared__ float tile[32][33];
    const int bx = blockIdx.x * 32;
    const int by = blockIdx.y * 32;
    const int txi = threadIdx.x & 31;
    const int tyi = threadIdx.x >> 5;
#pragma unroll
    for (int j = 0; j < 32; j += 8) {
        int kk = by + tyi + j, nn = bx + txi;
        if (kk < K && nn < N) tile[tyi + j][txi] = W[(size_t)kk * N + nn];
    }
    __syncthreads();
#pragma unroll
    for (int j = 0; j < 32; j += 8) {
        int nn = bx + tyi + j, kk = by + txi;
        if (nn < N && kk < K)
            th[(size_t)nn * K + kk] = __float2half_rn(tile[txi][tyi + j]);
    }
}

// ---------------- RMSNorm: qkv[:, 3072:3584] -> lath fp16 ----------------
__global__ __launch_bounds__(256) void rmsnorm_kernel(
    const float* __restrict__ qkv, const float* __restrict__ w,
    __half* __restrict__ lath)
{
    const int row = blockIdx.x;
    const float* x = qkv + (size_t)row * NQA_ + H_ * QKD_;
    const int tid = threadIdx.x;

    float v0 = x[tid];
    float v1 = x[tid + 256];
    float ss = v0 * v0 + v1 * v1;
#pragma unroll
    for (int off = 16; off; off >>= 1)
        ss += __shfl_xor_sync(0xffffffffu, ss, off);

    __shared__ float red[8];
    if ((tid & 31) == 0) red[tid >> 5] = ss;
    __syncthreads();
    float tot = 0.f;
#pragma unroll
    for (int i = 0; i < 8; i++) tot += red[i];

    float nrm = rsqrtf(tot * (1.f / 512.f) + 1e-6f);
    __half* o = lath + (size_t)row * KVR_;
    o[tid]       = __float2half_rn(v0 * nrm * w[tid]);
    o[tid + 256] = __float2half_rn(v1 * nrm * w[tid + 256]);
}

// ---------------- RoPE on qkv ----------------
__global__ __launch_bounds__(256) void rope_q_kernel(float* __restrict__ qkv)
{
    int idx = blockIdx.x * 256 + threadIdx.x;
    if (idx >= BT_ * H_ * 32) return;
    int i  = idx & 31;
    int h  = (idx >> 5) & (H_ - 1);
    int bt = idx >> 9;
    int t  = bt & (T_ - 1);

    float inv = powf(10000.f, -(float)(2 * i) / 64.f);
    float f = (float)t * inv;
    float c = cosf(f), s = sinf(f);

    float* p = qkv + (size_t)bt * NQA_ + h * QKD_ + NOPE_;
    float x1 = p[i], x2 = p[i + 32];
    p[i]      = x1 * c - x2 * s;
    p[i + 32] = x2 * c + x1 * s;
}

__global__ __launch_bounds__(256) void rope_k_kernel(
    const float* __restrict__ qkv, float* __restrict__ krope)
{
    int idx = blockIdx.x * 256 + threadIdx.x;
    if (idx >= BT_ * 32) return;
    int i  = idx & 31;
    int bt = idx >> 5;
    int t  = bt & (T_ - 1);

    float inv = powf(10000.f, -(float)(2 * i) / 64.f);
    float f = (float)t * inv;
    float c = cosf(f), s = sinf(f);

    const float* p = qkv + (size_t)bt * NQA_ + H_ * QKD_ + KVR_;
    float x1 = p[i], x2 = p[i + 32];
    float* o = krope + (size_t)bt * ROPE_;
    o[i]      = x1 * c - x2 * s;
    o[i + 32] = x2 * c + x1 * s;
}

// ---------------- fp16 HMMA causal flash attention (single product) ----------------
#define ABQ 128
#define ABK 64
#define AQ_PITCH 400
#define AK_PITCH 400
#define AV_PITCH 272
#define OFF_Q 0
#define OFF_K 51200
#define OFF_V 76800
#define ATTN_SMEM 94208

__device__ __forceinline__ float quadmax(float v) {
    v = fmaxf(v, __shfl_xor_sync(0xffffffffu, v, 1));
    v = fmaxf(v, __shfl_xor_sync(0xffffffffu, v, 2));
    return v;
}
__device__ __forceinline__ float quadsum(float v) {
    v += __shfl_xor_sync(0xffffffffu, v, 1);
    v += __shfl_xor_sync(0xffffffffu, v, 2);
    return v;
}

__global__ __launch_bounds__(256) void attn_mma_kernel(
    const float* __restrict__ qkv, const float* __restrict__ kvfull,
    const float* __restrict__ krope, __half* __restrict__ yh)
{
    extern __shared__ char smem[];
    const uint32_t sb = smem_u32(smem);
    const int b  = blockIdx.z;
    const int h  = blockIdx.y;
    const int qt = blockIdx.x;
    const int q0 = qt * ABQ;
    const int tid = threadIdx.x;
    const int lane = tid & 31;
    const int w = tid >> 5;
    const int g = lane >> 2;
    const int t = lane & 3;
    const float scale = 0.07216878364870322f;

    // load Q tile [128][192] fp32 (from combined qkv, stride NQA_) -> fp16 smem
#pragma unroll
    for (int l = 0; l < 24; l++) {
        int u = l * 256 + tid;
        int row = u / 48, c4 = u % 48, d = c4 * 4;
        float4 v = *(const float4*)&qkv[(size_t)(b * T_ + q0 + row) * NQA_ + h * QKD_ + d];
        cvt_store8(sb + OFF_Q + row * AQ_PITCH + d * 2, v);
    }

    float oc[16][4];
#pragma unroll
    for (int d = 0; d < 16; d++) { oc[d][0]=0.f; oc[d][1]=0.f; oc[d][2]=0.f; oc[d][3]=0.f; }
    float m0 = -CUDART_INF_F, m1 = -CUDART_INF_F, l0s = 0.f, l1s = 0.f;

    const int row0 = q0 + w * 16 + g;
    const int wrow_max = q0 + w * 16 + 15;

    const int nkt = 2 * qt + 2;
    for (int kt = 0; kt < nkt; kt++) {
        const int k0 = kt * ABK;
        __syncthreads();

#pragma unroll
        for (int l = 0; l < 12; l++) {
            int u = l * 256 + tid;
            int row = u / 48, c4 = u % 48, d = c4 * 4;
            size_t tok = (size_t)(b * T_ + k0 + row);
            float4 v;
            if (d < NOPE_) v = *(const float4*)&kvfull[(tok * H_ + h) * (NOPE_+VD_) + d];
            else           v = *(const float4*)&krope[tok * ROPE_ + (d - NOPE_)];
            cvt_store8(sb + OFF_K + row * AK_PITCH + d * 2, v);
        }
#pragma unroll
        for (int l = 0; l < 8; l++) {
            int u = l * 256 + tid;
            int row = u >> 5, c4 = u & 31, d = c4 * 4;
            size_t tok = (size_t)(b * T_ + k0 + row);
            float4 v = *(const float4*)&kvfull[(tok * H_ + h) * (NOPE_+VD_) + NOPE_ + d];
            cvt_store8(sb + OFF_V + row * AV_PITCH + d * 2, v);
        }
        __syncthreads();

        if (k0 > wrow_max) continue;

        float sc[8][4];
#pragma unroll
        for (int j = 0; j < 8; j++) { sc[j][0]=0.f; sc[j][1]=0.f; sc[j][2]=0.f; sc[j][3]=0.f; }

#pragma unroll
        for (int kb = 0; kb < 12; kb++) {
            uint32_t qa = sb + OFF_Q + (w * 16 + (lane & 15)) * AQ_PITCH
                        + (kb * 16 + (lane >> 4) * 8) * 2;
            uint32_t aq[4];
            ldsm_x4(aq, qa);
            uint32_t kh[8][2];
#pragma unroll
            for (int nj = 0; nj < 4; nj++) {
                uint32_t ka = sb + OFF_K
                            + (nj * 16 + ((lane >> 4) & 1) * 8 + (lane & 7)) * AK_PITCH
                            + (kb * 16 + ((lane >> 3) & 1) * 8) * 2;
                ldsm_x4(&kh[nj * 2][0], ka);
            }
#pragma unroll
            for (int j = 0; j < 8; j++)
                mma16816h(sc[j], aq, kh[j]);
        }

        const bool need_mask = (k0 + ABK - 1 > q0 + w * 16);
#pragma unroll
        for (int j = 0; j < 8; j++) {
            int cbase = k0 + 8 * j + 2 * t;
#pragma unroll
            for (int e = 0; e < 4; e++) {
                int col = cbase + (e & 1);
                int row = (e < 2) ? row0 : row0 + 8;
                float v = sc[j][e] * scale;
                sc[j][e] = (need_mask && col > row) ? -CUDART_INF_F : v;
            }
        }

        float tm0 = -CUDART_INF_F, tm1 = -CUDART_INF_F;
#pragma unroll
        for (int j = 0; j < 8; j++) {
            tm0 = fmaxf(tm0, fmaxf(sc[j][0], sc[j][1]));
            tm1 = fmaxf(tm1, fmaxf(sc[j][2], sc[j][3]));
        }
        tm0 = quadmax(tm0); tm1 = quadmax(tm1);
        float mn0 = fmaxf(m0, tm0), mn1 = fmaxf(m1, tm1);
        float corr0 = __expf(m0 - mn0), corr1 = __expf(m1 - mn1);
        float rs0 = 0.f, rs1 = 0.f;
#pragma unroll
        for (int j = 0; j < 8; j++) {
            sc[j][0] = __expf(sc[j][0] - mn0);
            sc[j][1] = __expf(sc[j][1] - mn0);
            sc[j][2] = __expf(sc[j][2] - mn1);
            sc[j][3] = __expf(sc[j][3] - mn1);
            rs0 += sc[j][0] + sc[j][1];
            rs1 += sc[j][2] + sc[j][3];
        }
        rs0 = quadsum(rs0); rs1 = quadsum(rs1);
        l0s = l0s * corr0 + rs0;
        l1s = l1s * corr1 + rs1;
        m0 = mn0; m1 = mn1;
#pragma unroll
        for (int d = 0; d < 16; d++) {
            oc[d][0] *= corr0; oc[d][1] *= corr0;
            oc[d][2] *= corr1; oc[d][3] *= corr1;
        }

#pragma unroll
        for (int kb2 = 0; kb2 < 4; kb2++) {
            uint32_t pa[4];
#pragma unroll
            for (int half = 0; half < 2; half++) {
                int j = 2 * kb2 + half;
                pa[half * 2 + 0] = pack_f16x2(sc[j][0], sc[j][1]);
                pa[half * 2 + 1] = pack_f16x2(sc[j][2], sc[j][3]);
            }
#pragma unroll
            for (int dp = 0; dp < 8; dp++) {
                uint32_t vh[4];
                uint32_t va = sb + OFF_V
                            + (kb2 * 16 + (lane & 7) + ((lane >> 3) & 1) * 8) * AV_PITCH
                            + (dp * 16 + (lane >> 4) * 8) * 2;
                ldsm_x4_trans(vh, va);
                mma16816h(oc[dp * 2],     pa, &vh[0]);
                mma16816h(oc[dp * 2 + 1], pa, &vh[2]);
            }
        }
    }

    // ---- epilogue: write fp16 yh directly ----
    float inv0 = 1.f / l0s, inv1 = 1.f / l1s;
#pragma unroll
    for (int d = 0; d < 16; d++) {
        int col = d * 8 + 2 * t;
        size_t base0 = (((size_t)(b * T_ + row0)) * H_ + h) * VD_ + col;
        size_t base1 = (((size_t)(b * T_ + row0 + 8)) * H_ + h) * VD_ + col;
        *(uint32_t*)&yh[base0] = pack_f16x2(oc[d][0] * inv0, oc[d][1] * inv0);
        *(uint32_t*)&yh[base1] = pack_f16x2(oc[d][2] * inv1, oc[d][3] * inv1);
    }
}

// ---------------- launch ----------------
extern "C" void kernel_launch(void* const* d_in, const int* in_sizes, int n_in,
                              void* d_out, int out_size)
{
    const float* x      = (const float*)d_in[0];
    const float* wq     = (const float*)d_in[1];
    const float* wkv_a  = (const float*)d_in[2];
    const float* wkv_b  = (const float*)d_in[3];
    const float* wo     = (const float*)d_in[4];
    const float* kvw    = (const float*)d_in[5];
    float* out = (float*)d_out;

    float *qkvp, *kvfp, *krp;
    cudaGetSymbolAddress((void**)&qkvp, g_qkv);
    cudaGetSymbolAddress((void**)&kvfp, g_kvfull);
    cudaGetSymbolAddress((void**)&krp,  g_krope);

    __half *xh, *lath, *yh, *wqah, *wbth, *woth;
    cudaGetSymbolAddress((void**)&xh,   g_xh);
    cudaGetSymbolAddress((void**)&lath, g_lath);
    cudaGetSymbolAddress((void**)&yh,   g_yh);
    cudaGetSymbolAddress((void**)&wqah, g_wqa_h);
    cudaGetSymbolAddress((void**)&wbth, g_wbt_h);
    cudaGetSymbolAddress((void**)&woth, g_wot_h);

    cudaFuncSetAttribute(gemm_mma, cudaFuncAttributeMaxDynamicSharedMemorySize, GM_SMEM);
    cudaFuncSetAttribute(attn_mma_kernel, cudaFuncAttributeMaxDynamicSharedMemorySize, ATTN_SMEM);

    // ---- prep ----
    convert_kernel<<<(BT_*D_/4 + 255)/256, 256>>>(x, xh, BT_*D_/4);
    // wq^T into rows [0, 3072)
    transpose_split_kernel<<<dim3((H_*QKD_)/32, D_/32), 256>>>(wq, wqah, D_, H_*QKD_);
    // wkv_a^T into rows [3072, 3648)
    transpose_split_kernel<<<dim3((KVR_+ROPE_)/32, D_/32), 256>>>(
        wkv_a, wqah + (size_t)(H_*QKD_) * D_, D_, KVR_+ROPE_);
    transpose_split_kernel<<<dim3((H_*(NOPE_+VD_))/32, KVR_/32), 256>>>(wkv_b, wbth, KVR_, H_*(NOPE_+VD_));
    transpose_split_kernel<<<dim3(D_/32, (H_*VD_)/32), 256>>>(wo, woth, H_*VD_, D_);

    // ---- merged q|kvc = x @ [wq | wkv_a] : [4096, 3648] ----
    gemm_mma<<<dim3((NQA_ + 127)/128, BT_/128), 256, GM_SMEM>>>(xh, wqah, qkvp, BT_, NQA_, D_);
    // ---- rmsnorm (-> fp16 lath) + rope ----
    rmsnorm_kernel<<<BT_, 256>>>(qkvp, kvw, lath);
    rope_q_kernel<<<(BT_*H_*32)/256, 256>>>(qkvp);
    rope_k_kernel<<<(BT_*32)/256, 256>>>(qkvp, krp);
    // ---- kv_full = lat @ wkv_b ----
    gemm_mma<<<dim3(4096/128, BT_/128), 256, GM_SMEM>>>(lath, wbth, kvfp, BT_, H_*(NOPE_+VD_), KVR_);
    // ---- attention (writes fp16 yh directly) ----
    attn_mma_kernel<<<dim3(T_/ABQ, H_, B_), 256, ATTN_SMEM>>>(qkvp, kvfp, krp, yh);
    // ---- out = y @ wo ----
    gemm_mma<<<dim3(D_/128, BT_/128), 256, GM_SMEM>>>(yh, woth, out, BT_, D_, H_*VD_);
}